// round 1
// baseline (speedup 1.0000x reference)
#include <cuda_runtime.h>
#include <cuda_bf16.h>
#include <math.h>
#include <stdint.h>

// Problem constants
#define BB 2
#define NN 2048
#define DD 1024
#define HH 16
#define HCC 8
#define HID 4096
#define BN (BB*NN)          // 4096 rows

// ------------------------- scratch (device globals; no allocs allowed) ---------
__device__ float g_emb[BB*HID];
__device__ float g_part[16*2*HID];
__device__ float g_h1[BB*HID];
__device__ float g_h2[BB*HID];
__device__ float g_av[BB*HID];
__device__ float g_cv[BB*HID];
__device__ __nv_bfloat16 g_wbf[6u*1048576u];        // 6 converted 1024x1024 weights
__device__ __nv_bfloat16 g_x1[BN*DD];
__device__ __nv_bfloat16 g_qk[BN*DD];
__device__ __nv_bfloat16 g_v[BN*DD];
__device__ float g_q2[BB*HH*NN];
__device__ float g_phi[BB*NN];
__device__ float g_S[(long)BB*HH*NN*NN];            // 536 MB logits
__device__ __nv_bfloat16 g_P[(long)BB*HH*NN*NN];    // 268 MB probs
__device__ __nv_bfloat16 g_attn[BN*DD];
__device__ float g_xmid[BN*DD];
__device__ __nv_bfloat16 g_x2[BN*DD];
__device__ __nv_bfloat16 g_qkc[BN*DD];
__device__ __nv_bfloat16 g_vc[BN*DD];
__device__ float g_q2c[BB*HCC*128];
__device__ float g_Sc[BB*HCC*128*128];
__device__ __nv_bfloat16 g_Pc[BB*HCC*128*128];
__device__ __nv_bfloat16 g_ch[BN*DD];

// ------------------------- helpers ---------------------------------------------
__device__ inline float blockRed(float v, int op) {  // op: 0=sum, 1=max ; result broadcast
    __shared__ float sm[32];
    int lane = threadIdx.x & 31, w = threadIdx.x >> 5;
    #pragma unroll
    for (int o = 16; o; o >>= 1) {
        float t = __shfl_xor_sync(0xffffffffu, v, o);
        v = op ? fmaxf(v, t) : v + t;
    }
    if (lane == 0) sm[w] = v;
    __syncthreads();
    int nw = blockDim.x >> 5;
    if (w == 0) {
        v = (lane < nw) ? sm[lane] : (op ? -INFINITY : 0.f);
        #pragma unroll
        for (int o = 16; o; o >>= 1) {
            float t = __shfl_xor_sync(0xffffffffu, v, o);
            v = op ? fmaxf(v, t) : v + t;
        }
        if (lane == 0) sm[0] = v;
    }
    __syncthreads();
    float r = sm[0];
    __syncthreads();
    return r;
}

// ------------------------- small kernels ----------------------------------------
__global__ void k_emb(const float* __restrict__ t, float* __restrict__ emb) {
    int i = blockIdx.x * 256 + threadIdx.x;
    if (i >= BB * HID) return;
    int b = i / HID, j = i % HID;
    int jj = j & 2047;
    float f = expf(-9.210340371976184f * (float)jj / 2048.0f);
    float a = t[b] * f;
    emb[i] = (j < 2048) ? cosf(a) : sinf(a);
}

__global__ void k_gemv_part(const float* __restrict__ in, const float* __restrict__ W,
                            float* __restrict__ part, int K, int Nout) {
    int col = blockIdx.x * 256 + threadIdx.x;
    int ks = K / 16;
    int k0 = blockIdx.y * ks;
    float a0 = 0.f, a1 = 0.f;
    for (int k = k0; k < k0 + ks; k++) {
        float w = W[(long)k * Nout + col];
        a0 += in[k] * w;
        a1 += in[K + k] * w;
    }
    part[((long)blockIdx.y * 2 + 0) * Nout + col] = a0;
    part[((long)blockIdx.y * 2 + 1) * Nout + col] = a1;
}

__global__ void k_gemv_red(const float* __restrict__ part, const float* __restrict__ bias,
                           float* __restrict__ out, int Nout, int act) {
    int i = blockIdx.x * 256 + threadIdx.x;
    if (i >= 2 * Nout) return;
    int b = i / Nout, col = i % Nout;
    float s = bias[col];
    for (int p = 0; p < 16; p++) s += part[((long)p * 2 + b) * Nout + col];
    if (act) s = s / (1.f + expf(-s));   // silu
    out[(long)b * Nout + col] = s;
}

__global__ void k_convert(const float* __restrict__ w0, const float* __restrict__ w1,
                          const float* __restrict__ w2, const float* __restrict__ w3,
                          const float* __restrict__ w4, const float* __restrict__ w5,
                          __nv_bfloat16* __restrict__ out) {
    long i = (long)blockIdx.x * 256 + threadIdx.x;
    if (i >= 6L * 1048576L) return;
    int w = (int)(i >> 20);
    long off = i & 1048575;
    const float* s = w0;
    if (w == 1) s = w1; else if (w == 2) s = w2; else if (w == 3) s = w3;
    else if (w == 4) s = w4; else if (w == 5) s = w5;
    out[i] = __float2bfloat16(s[off]);
}

// LayerNorm + modulate -> bf16
__global__ void k_ln_mod(const float* __restrict__ xin, __nv_bfloat16* __restrict__ xout,
                         const float* __restrict__ sc, const float* __restrict__ bi,
                         const float* __restrict__ mod /*(B,4096): [shift|scale|gate|lg]*/) {
    int r = blockIdx.x;
    int b = r >> 11;
    const float* xr = xin + (long)r * DD;
    int tid = threadIdx.x;
    float v[4];
    float s = 0.f;
    #pragma unroll
    for (int i = 0; i < 4; i++) { v[i] = xr[tid + i * 256]; s += v[i]; }
    s = blockRed(s, 0);
    float mu = s * (1.0f / DD);
    float vs = 0.f;
    #pragma unroll
    for (int i = 0; i < 4; i++) { float d = v[i] - mu; vs += d * d; }
    vs = blockRed(vs, 0);
    float rstd = rsqrtf(vs * (1.0f / DD) + 1e-6f);
    #pragma unroll
    for (int i = 0; i < 4; i++) {
        int j = tid + i * 256;
        float y = (v[i] - mu) * rstd * sc[j] + bi[j];
        float sh = mod[(long)b * HID + j];
        float sl = mod[(long)b * HID + 1024 + j];
        xout[(long)r * DD + j] = __float2bfloat16(y * (1.f + sl) + sh);
    }
}

__global__ void k_phi(const __nv_bfloat16* __restrict__ x1, const float* __restrict__ dw,
                      const float* __restrict__ db, float* __restrict__ phi) {
    int r = blockIdx.x;
    int tid = threadIdx.x;
    float s = 0.f;
    #pragma unroll
    for (int i = 0; i < 4; i++) {
        int j = tid + i * 256;
        s += __bfloat162float(x1[(long)r * DD + j]) * dw[j];
    }
    s = blockRed(s, 0);
    if (tid == 0) phi[r] = s + db[0];
}

__global__ void k_q2(const __nv_bfloat16* __restrict__ qk, float* __restrict__ q2) {
    int gid = blockIdx.x * 8 + (threadIdx.x >> 5);   // (b*16+h)*2048+n
    int lane = threadIdx.x & 31;
    int n = gid & 2047;
    int h = (gid >> 11) & 15;
    int b = gid >> 15;
    const __nv_bfloat16* p = qk + ((long)b * NN + n) * DD + h * 64;
    float f0 = __bfloat162float(p[lane]);
    float f1 = __bfloat162float(p[lane + 32]);
    float s = f0 * f0 + f1 * f1;
    #pragma unroll
    for (int o = 16; o; o >>= 1) s += __shfl_xor_sync(0xffffffffu, s, o);
    if (lane == 0) q2[gid] = s;
}

__global__ void k_q2c(const __nv_bfloat16* __restrict__ qkc, float* __restrict__ q2c) {
    int idx = blockIdx.x * 256 + threadIdx.x;   // (b*8+hc)*128+d
    if (idx >= BB * HCC * 128) return;
    int d = idx & 127;
    int hc = (idx >> 7) & 7;
    int b = idx >> 10;
    float s = 0.f;
    for (int n = 0; n < NN; n++) {
        float q = __bfloat162float(qkc[((long)b * NN + n) * DD + hc * 128 + d]);
        s += q * q;
    }
    q2c[idx] = s;
}

__global__ void k_softmax_tok(const float* __restrict__ S, __nv_bfloat16* __restrict__ P) {
    long row = blockIdx.x;
    const float* s = S + row * NN;
    int tid = threadIdx.x;
    float v[8];
    float mx = -INFINITY;
    #pragma unroll
    for (int i = 0; i < 8; i++) { v[i] = s[tid + i * 256]; mx = fmaxf(mx, v[i]); }
    mx = blockRed(mx, 1);
    float sum = 0.f;
    #pragma unroll
    for (int i = 0; i < 8; i++) { v[i] = expf(v[i] - mx); sum += v[i]; }
    sum = blockRed(sum, 0);
    float inv = 1.f / sum;
    #pragma unroll
    for (int i = 0; i < 8; i++)
        P[row * NN + tid + i * 256] = __float2bfloat16(v[i] * inv);
}

__global__ void k_softmax_ch(const float* __restrict__ S, __nv_bfloat16* __restrict__ P) {
    int row = blockIdx.x;     // 2048 rows of 128
    int tid = threadIdx.x;    // 128
    float v = S[(long)row * 128 + tid];
    float mx = blockRed(v, 1);
    float e = expf(v - mx);
    float sum = blockRed(e, 0);
    P[(long)row * 128 + tid] = __float2bfloat16(e / sum);
}

// ------------------------- generic bf16 mma GEMM --------------------------------
struct GemmP {
    const __nv_bfloat16 *A, *B;
    long sAm, sAk, sBk, sBn;
    long bAb, bAh, bBb, bBh, bCb, bCh;
    int nh, nb, M, N, K;
    void* C; long sCm, sCn;
    int epi, eStride;
    const float *e0, *e1, *e2;
    float f0;
};

__device__ inline void mma16816(float* c, const uint32_t* a, const uint32_t* b) {
    asm volatile(
        "mma.sync.aligned.m16n8k16.row.col.f32.bf16.bf16.f32 "
        "{%0,%1,%2,%3}, {%4,%5,%6,%7}, {%8,%9}, {%0,%1,%2,%3};\n"
        : "+f"(c[0]), "+f"(c[1]), "+f"(c[2]), "+f"(c[3])
        : "r"(a[0]), "r"(a[1]), "r"(a[2]), "r"(a[3]), "r"(b[0]), "r"(b[1]));
}

__device__ inline void epi_write(const GemmP& p, long cOff, int z, int b, int h,
                                 int m, int n, float acc) {
    long ci = cOff + (long)m * p.sCm + (long)n * p.sCn;
    switch (p.epi) {
    case 0: {  // out = bf16( acc * exp(lg[b, n]) ), b from row
        float s = expf(p.e0[(long)(m >> 11) * p.eStride + n]);
        ((__nv_bfloat16*)p.C)[ci] = __float2bfloat16(acc * s);
        break; }
    case 1:    // plain bf16 store
        ((__nv_bfloat16*)p.C)[ci] = __float2bfloat16(acc);
        break;
    case 2: {  // token logits: 2*acc - q2[m] - q2[n] + phi[n]
        float v = 2.f * acc - p.e0[(long)z * NN + m] - p.e0[(long)z * NN + n]
                  + p.e1[(long)b * NN + n];
        ((float*)p.C)[ci] = v;
        break; }
    case 3: {  // residual: x + acc*gate[b,n]*gamma[n]  (fp32 out)
        int bb = m >> 11;
        float v = p.e2[(long)m * DD + n]
                  + acc * p.e0[(long)bb * p.eStride + n] * p.e1[n];
        ((float*)p.C)[ci] = v;
        break; }
    case 4: {  // channel logits: (2*acc - q2c[m] - q2c[n]) * rsqrtN * tau[h]
        float v = (2.f * acc - p.e0[z * 128 + m] - p.e0[z * 128 + n]) * p.f0 * p.e1[h];
        ((float*)p.C)[ci] = v;
        break; }
    }
}

__global__ void __launch_bounds__(128) k_gemm(GemmP p) {
    int z = blockIdx.z;
    int b = z / p.nh, h = z - b * p.nh;
    const __nv_bfloat16* A = p.A + (long)b * p.bAb + (long)h * p.bAh;
    const __nv_bfloat16* Bm = p.B + (long)b * p.bBb + (long)h * p.bBh;
    long cOff = (long)b * p.bCb + (long)h * p.bCh;
    int bm = blockIdx.y * 64, bn = blockIdx.x * 64;
    __shared__ __nv_bfloat16 sA[64][40];
    __shared__ __nv_bfloat16 sB[64][40];
    int tid = threadIdx.x;
    int wid = tid >> 5, lane = tid & 31, g = lane >> 2, tg = lane & 3;
    int wm = (wid >> 1) * 32, wn = (wid & 1) * 32;
    float acc[2][4][4];
    #pragma unroll
    for (int i = 0; i < 2; i++)
        #pragma unroll
        for (int j = 0; j < 4; j++)
            #pragma unroll
            for (int q = 0; q < 4; q++) acc[i][j][q] = 0.f;

    for (int k0 = 0; k0 < p.K; k0 += 32) {
        #pragma unroll
        for (int i = 0; i < 16; i++) {
            int idx = i * 128 + tid;
            int ma = idx >> 5, ka = idx & 31;
            sA[ma][ka] = A[(long)(bm + ma) * p.sAm + (long)(k0 + ka) * p.sAk];
            int kb = idx >> 6, nb2 = idx & 63;
            sB[nb2][kb] = Bm[(long)(k0 + kb) * p.sBk + (long)(bn + nb2) * p.sBn];
        }
        __syncthreads();
        #pragma unroll
        for (int kk = 0; kk < 32; kk += 16) {
            uint32_t ar[2][4], br[4][2];
            #pragma unroll
            for (int mi = 0; mi < 2; mi++) {
                int r = wm + mi * 16;
                ar[mi][0] = *(const uint32_t*)&sA[r + g][kk + 2 * tg];
                ar[mi][1] = *(const uint32_t*)&sA[r + g + 8][kk + 2 * tg];
                ar[mi][2] = *(const uint32_t*)&sA[r + g][kk + 2 * tg + 8];
                ar[mi][3] = *(const uint32_t*)&sA[r + g + 8][kk + 2 * tg + 8];
            }
            #pragma unroll
            for (int ni = 0; ni < 4; ni++) {
                int c = wn + ni * 8 + g;
                br[ni][0] = *(const uint32_t*)&sB[c][kk + 2 * tg];
                br[ni][1] = *(const uint32_t*)&sB[c][kk + 2 * tg + 8];
            }
            #pragma unroll
            for (int mi = 0; mi < 2; mi++)
                #pragma unroll
                for (int ni = 0; ni < 4; ni++)
                    mma16816(acc[mi][ni], ar[mi], br[ni]);
        }
        __syncthreads();
    }

    #pragma unroll
    for (int mi = 0; mi < 2; mi++)
        #pragma unroll
        for (int ni = 0; ni < 4; ni++) {
            int r = bm + wm + mi * 16 + g;
            int c = bn + wn + ni * 8 + 2 * tg;
            epi_write(p, cOff, z, b, h, r, c, acc[mi][ni][0]);
            epi_write(p, cOff, z, b, h, r, c + 1, acc[mi][ni][1]);
            epi_write(p, cOff, z, b, h, r + 8, c, acc[mi][ni][2]);
            epi_write(p, cOff, z, b, h, r + 8, c + 1, acc[mi][ni][3]);
        }
}

static inline void rungemm(const GemmP& p) {
    dim3 grid(p.N / 64, p.M / 64, p.nb);
    k_gemm<<<grid, 128>>>(p);
}

#define SYMADDR(v, s) do { void* _p = nullptr; cudaGetSymbolAddress(&_p, s); v = (decltype(v))_p; } while (0)

// ------------------------- launch ----------------------------------------------
extern "C" void kernel_launch(void* const* d_in, const int* in_sizes, int n_in,
                              void* d_out, int out_size) {
    const float* x        = (const float*)d_in[0];
    const float* t        = (const float*)d_in[1];
    const float* n1s      = (const float*)d_in[2];
    const float* n1b      = (const float*)d_in[3];
    const float* n2s      = (const float*)d_in[4];
    const float* n2b      = (const float*)d_in[5];
    const float* tc_w1    = (const float*)d_in[6];
    const float* tc_b1    = (const float*)d_in[7];
    const float* tc_w2    = (const float*)d_in[8];
    const float* tc_b2    = (const float*)d_in[9];
    const float* tc_wa    = (const float*)d_in[10];
    const float* tc_ba    = (const float*)d_in[11];
    const float* tc_wc    = (const float*)d_in[12];
    const float* tc_bc    = (const float*)d_in[13];
    const float* attn_qk_w = (const float*)d_in[14];
    const float* attn_v_w  = (const float*)d_in[15];
    const float* attn_out_w= (const float*)d_in[16];
    const float* doob_w   = (const float*)d_in[17];
    const float* doob_b   = (const float*)d_in[18];
    const float* ch_qk_w  = (const float*)d_in[19];
    const float* ch_v_w   = (const float*)d_in[20];
    const float* ch_out_w = (const float*)d_in[21];
    const float* tau      = (const float*)d_in[22];
    const float* gamma1   = (const float*)d_in[23];
    const float* gamma2   = (const float*)d_in[24];

    float *emb, *part, *h1, *h2, *av, *cv, *q2, *phi, *Sp, *xmid, *q2c, *Scp;
    __nv_bfloat16 *wbf, *x1, *qkb, *vb, *Pp, *attnb, *x2, *qkcb, *vcb, *Pcp, *chb;
    SYMADDR(emb, g_emb);   SYMADDR(part, g_part); SYMADDR(h1, g_h1);  SYMADDR(h2, g_h2);
    SYMADDR(av, g_av);     SYMADDR(cv, g_cv);     SYMADDR(wbf, g_wbf);
    SYMADDR(x1, g_x1);     SYMADDR(qkb, g_qk);    SYMADDR(vb, g_v);
    SYMADDR(q2, g_q2);     SYMADDR(phi, g_phi);   SYMADDR(Sp, g_S);   SYMADDR(Pp, g_P);
    SYMADDR(attnb, g_attn);SYMADDR(xmid, g_xmid); SYMADDR(x2, g_x2);
    SYMADDR(qkcb, g_qkc);  SYMADDR(vcb, g_vc);    SYMADDR(q2c, g_q2c);
    SYMADDR(Scp, g_Sc);    SYMADDR(Pcp, g_Pc);    SYMADDR(chb, g_ch);

    // weight conversion (independent; launch first)
    k_convert<<<(6 * 1048576 + 255) / 256, 256>>>(attn_qk_w, attn_v_w, attn_out_w,
                                                  ch_qk_w, ch_v_w, ch_out_w, wbf);
    __nv_bfloat16* wqk = wbf;
    __nv_bfloat16* wv  = wbf + 1 * 1048576;
    __nv_bfloat16* wo  = wbf + 2 * 1048576;
    __nv_bfloat16* wcq = wbf + 3 * 1048576;
    __nv_bfloat16* wcv = wbf + 4 * 1048576;
    __nv_bfloat16* wco = wbf + 5 * 1048576;

    // ---- conditioning ----
    k_emb<<<(BB * HID + 255) / 256, 256>>>(t, emb);
    k_gemv_part<<<dim3(HID / 256, 16), 256>>>(emb, tc_w1, part, HID, HID);
    k_gemv_red<<<(2 * HID + 255) / 256, 256>>>(part, tc_b1, h1, HID, 1);
    k_gemv_part<<<dim3(HID / 256, 16), 256>>>(h1, tc_w2, part, HID, HID);
    k_gemv_red<<<(2 * HID + 255) / 256, 256>>>(part, tc_b2, h2, HID, 1);
    k_gemv_part<<<dim3(HID / 256, 16), 256>>>(h2, tc_wa, part, HID, HID);
    k_gemv_red<<<(2 * HID + 255) / 256, 256>>>(part, tc_ba, av, HID, 0);
    k_gemv_part<<<dim3(HID / 256, 16), 256>>>(h2, tc_wc, part, HID, HID);
    k_gemv_red<<<(2 * HID + 255) / 256, 256>>>(part, tc_bc, cv, HID, 0);

    // ---- token attention ----
    k_ln_mod<<<BN, 256>>>(x, x1, n1s, n1b, av);
    k_phi<<<BN, 256>>>(x1, doob_w, doob_b, phi);

    {   // qk = (x1 @ Wqk) * exp(a_lg)
        GemmP p = {};
        p.A = x1; p.sAm = DD; p.sAk = 1;
        p.B = wqk; p.sBk = DD; p.sBn = 1;
        p.M = BN; p.N = DD; p.K = DD; p.nh = 1; p.nb = 1;
        p.C = qkb; p.sCm = DD; p.sCn = 1;
        p.epi = 0; p.e0 = av + 3072; p.eStride = HID;
        rungemm(p);
    }
    {   // v = x1 @ Wv
        GemmP p = {};
        p.A = x1; p.sAm = DD; p.sAk = 1;
        p.B = wv; p.sBk = DD; p.sBn = 1;
        p.M = BN; p.N = DD; p.K = DD; p.nh = 1; p.nb = 1;
        p.C = vb; p.sCm = DD; p.sCn = 1;
        p.epi = 1;
        rungemm(p);
    }
    k_q2<<<BB * HH * NN / 8, 256>>>(qkb, q2);
    {   // S[z] = 2 Q Q^T - q2m - q2n + phi_n   (batched over 32)
        GemmP p = {};
        p.A = qkb; p.sAm = DD; p.sAk = 1; p.bAb = (long)NN * DD; p.bAh = 64;
        p.B = qkb; p.sBk = 1; p.sBn = DD; p.bBb = (long)NN * DD; p.bBh = 64;
        p.M = NN; p.N = NN; p.K = 64; p.nh = HH; p.nb = BB * HH;
        p.C = Sp; p.sCm = NN; p.sCn = 1;
        p.bCb = (long)HH * NN * NN; p.bCh = (long)NN * NN;
        p.epi = 2; p.e0 = q2; p.e1 = phi;
        rungemm(p);
    }
    k_softmax_tok<<<BB * HH * NN, 256>>>(Sp, Pp);
    {   // attn_in[b,m,h*64+d] = P @ V
        GemmP p = {};
        p.A = Pp; p.sAm = NN; p.sAk = 1;
        p.bAb = (long)HH * NN * NN; p.bAh = (long)NN * NN;
        p.B = vb; p.sBk = DD; p.sBn = 1; p.bBb = (long)NN * DD; p.bBh = 64;
        p.M = NN; p.N = 64; p.K = NN; p.nh = HH; p.nb = BB * HH;
        p.C = attnb; p.sCm = DD; p.sCn = 1;
        p.bCb = (long)NN * DD; p.bCh = 64;
        p.epi = 1;
        rungemm(p);
    }
    {   // x_mid = x + (attn_in @ Wo) * a_gate * gamma1
        GemmP p = {};
        p.A = attnb; p.sAm = DD; p.sAk = 1;
        p.B = wo; p.sBk = DD; p.sBn = 1;
        p.M = BN; p.N = DD; p.K = DD; p.nh = 1; p.nb = 1;
        p.C = xmid; p.sCm = DD; p.sCn = 1;
        p.epi = 3; p.e0 = av + 2048; p.eStride = HID; p.e1 = gamma1; p.e2 = x;
        rungemm(p);
    }

    // ---- channel attention ----
    k_ln_mod<<<BN, 256>>>(xmid, x2, n2s, n2b, cv);
    {   // qkc = (x2 @ Wcq) * exp(c_lg)
        GemmP p = {};
        p.A = x2; p.sAm = DD; p.sAk = 1;
        p.B = wcq; p.sBk = DD; p.sBn = 1;
        p.M = BN; p.N = DD; p.K = DD; p.nh = 1; p.nb = 1;
        p.C = qkcb; p.sCm = DD; p.sCn = 1;
        p.epi = 0; p.e0 = cv + 3072; p.eStride = HID;
        rungemm(p);
    }
    {   // vc = x2 @ Wcv
        GemmP p = {};
        p.A = x2; p.sAm = DD; p.sAk = 1;
        p.B = wcv; p.sBk = DD; p.sBn = 1;
        p.M = BN; p.N = DD; p.K = DD; p.nh = 1; p.nb = 1;
        p.C = vcb; p.sCm = DD; p.sCn = 1;
        p.epi = 1;
        rungemm(p);
    }
    k_q2c<<<(BB * HCC * 128 + 255) / 256, 256>>>(qkcb, q2c);
    {   // Sc[z] = (2 Qc Qc^T - q2c_m - q2c_n)/sqrt(N) * tau[hc]  (batched 16)
        GemmP p = {};
        p.A = qkcb; p.sAm = 1; p.sAk = DD; p.bAb = (long)NN * DD; p.bAh = 128;
        p.B = qkcb; p.sBk = DD; p.sBn = 1; p.bBb = (long)NN * DD; p.bBh = 128;
        p.M = 128; p.N = 128; p.K = NN; p.nh = HCC; p.nb = BB * HCC;
        p.C = Scp; p.sCm = 128; p.sCn = 1;
        p.bCb = (long)HCC * 128 * 128; p.bCh = 128 * 128;
        p.epi = 4; p.e0 = q2c; p.e1 = tau;
        p.f0 = 0.022097086912079608f;  // 1/sqrt(2048)
        rungemm(p);
    }
    k_softmax_ch<<<BB * HCC * 128, 128>>>(Scp, Pcp);
    {   // ch_in[b,n,hc*128+c] = Pc @ Vc
        GemmP p = {};
        p.A = Pcp; p.sAm = 128; p.sAk = 1;
        p.bAb = (long)HCC * 128 * 128; p.bAh = 128 * 128;
        p.B = vcb; p.sBk = 1; p.sBn = DD; p.bBb = (long)NN * DD; p.bBh = 128;
        p.M = 128; p.N = NN; p.K = 128; p.nh = HCC; p.nb = BB * HCC;
        p.C = chb; p.sCm = 1; p.sCn = DD;
        p.bCb = (long)NN * DD; p.bCh = 128;
        p.epi = 1;
        rungemm(p);
    }
    {   // out = x_mid + (ch_in @ Wco) * c_gate * gamma2
        GemmP p = {};
        p.A = chb; p.sAm = DD; p.sAk = 1;
        p.B = wco; p.sBk = DD; p.sBn = 1;
        p.M = BN; p.N = DD; p.K = DD; p.nh = 1; p.nb = 1;
        p.C = d_out; p.sCm = DD; p.sCn = 1;
        p.epi = 3; p.e0 = cv + 2048; p.eStride = HID; p.e1 = gamma2; p.e2 = xmid;
        rungemm(p);
    }
}

// round 2
// speedup vs baseline: 2.3266x; 2.3266x over previous
#include <cuda_runtime.h>
#include <cuda_bf16.h>
#include <math.h>
#include <stdint.h>

// Problem constants
#define BB 2
#define NN 2048
#define DD 1024
#define HH 16
#define HCC 8
#define HID 4096
#define BN (BB*NN)          // 4096 rows

// ------------------------- scratch (device globals; no allocs allowed) ---------
__device__ float g_emb[BB*HID];
__device__ float g_part[16*2*HID];
__device__ float g_h1[BB*HID];
__device__ float g_h2[BB*HID];
__device__ float g_av[BB*HID];
__device__ float g_cv[BB*HID];
__device__ __nv_bfloat16 g_wbf[6u*1048576u];        // 6 converted 1024x1024 weights
__device__ __nv_bfloat16 g_x1[BN*DD];
__device__ __nv_bfloat16 g_qk[BN*DD];
__device__ __nv_bfloat16 g_v[BN*DD];
__device__ float g_bias[BB*HH*NN];                  // phi - q2 per key
__device__ float g_phi[BB*NN];
__device__ __nv_bfloat16 g_attn[BN*DD];
__device__ float g_xmid[BN*DD];
__device__ __nv_bfloat16 g_x2[BN*DD];
__device__ __nv_bfloat16 g_qkc[BN*DD];
__device__ __nv_bfloat16 g_vc[BN*DD];
__device__ float g_q2c[BB*HCC*128];
__device__ float g_Sc[BB*HCC*128*128];
__device__ __nv_bfloat16 g_Pc[BB*HCC*128*128];
__device__ __nv_bfloat16 g_ch[BN*DD];

// ------------------------- helpers ---------------------------------------------
__device__ inline float blockRed(float v, int op) {  // op: 0=sum, 1=max ; broadcast
    __shared__ float sm[32];
    int lane = threadIdx.x & 31, w = threadIdx.x >> 5;
    #pragma unroll
    for (int o = 16; o; o >>= 1) {
        float t = __shfl_xor_sync(0xffffffffu, v, o);
        v = op ? fmaxf(v, t) : v + t;
    }
    if (lane == 0) sm[w] = v;
    __syncthreads();
    int nw = blockDim.x >> 5;
    if (w == 0) {
        v = (lane < nw) ? sm[lane] : (op ? -INFINITY : 0.f);
        #pragma unroll
        for (int o = 16; o; o >>= 1) {
            float t = __shfl_xor_sync(0xffffffffu, v, o);
            v = op ? fmaxf(v, t) : v + t;
        }
        if (lane == 0) sm[0] = v;
    }
    __syncthreads();
    float r = sm[0];
    __syncthreads();
    return r;
}

__device__ inline void mma16816(float* c, const uint32_t* a, const uint32_t* b) {
    asm volatile(
        "mma.sync.aligned.m16n8k16.row.col.f32.bf16.bf16.f32 "
        "{%0,%1,%2,%3}, {%4,%5,%6,%7}, {%8,%9}, {%0,%1,%2,%3};\n"
        : "+f"(c[0]), "+f"(c[1]), "+f"(c[2]), "+f"(c[3])
        : "r"(a[0]), "r"(a[1]), "r"(a[2]), "r"(a[3]), "r"(b[0]), "r"(b[1]));
}

__device__ inline uint32_t packbf(float a, float b) {
    __nv_bfloat162 t = __floats2bfloat162_rn(a, b);
    return *(uint32_t*)&t;
}

// ------------------------- small kernels ----------------------------------------
__global__ void k_emb(const float* __restrict__ t, float* __restrict__ emb) {
    int i = blockIdx.x * 256 + threadIdx.x;
    if (i >= BB * HID) return;
    int b = i / HID, j = i % HID;
    int jj = j & 2047;
    float f = expf(-9.210340371976184f * (float)jj / 2048.0f);
    float a = t[b] * f;
    emb[i] = (j < 2048) ? cosf(a) : sinf(a);
}

__global__ void k_gemv_part(const float* __restrict__ in, const float* __restrict__ W,
                            float* __restrict__ part, int K, int Nout) {
    int col = blockIdx.x * 256 + threadIdx.x;
    int ks = K / 16;
    int k0 = blockIdx.y * ks;
    float a0 = 0.f, a1 = 0.f;
    for (int k = k0; k < k0 + ks; k++) {
        float w = W[(long)k * Nout + col];
        a0 += in[k] * w;
        a1 += in[K + k] * w;
    }
    part[((long)blockIdx.y * 2 + 0) * Nout + col] = a0;
    part[((long)blockIdx.y * 2 + 1) * Nout + col] = a1;
}

__global__ void k_gemv_red(const float* __restrict__ part, const float* __restrict__ bias,
                           float* __restrict__ out, int Nout, int act) {
    int i = blockIdx.x * 256 + threadIdx.x;
    if (i >= 2 * Nout) return;
    int b = i / Nout, col = i % Nout;
    float s = bias[col];
    for (int p = 0; p < 16; p++) s += part[((long)p * 2 + b) * Nout + col];
    if (act) s = s / (1.f + expf(-s));   // silu
    out[(long)b * Nout + col] = s;
}

__global__ void k_convert(const float* __restrict__ w0, const float* __restrict__ w1,
                          const float* __restrict__ w2, const float* __restrict__ w3,
                          const float* __restrict__ w4, const float* __restrict__ w5,
                          __nv_bfloat16* __restrict__ out) {
    long i = (long)blockIdx.x * 256 + threadIdx.x;
    if (i >= 6L * 1048576L) return;
    int w = (int)(i >> 20);
    long off = i & 1048575;
    const float* s = w0;
    if (w == 1) s = w1; else if (w == 2) s = w2; else if (w == 3) s = w3;
    else if (w == 4) s = w4; else if (w == 5) s = w5;
    out[i] = __float2bfloat16(s[off]);
}

// LayerNorm + modulate -> bf16
__global__ void k_ln_mod(const float* __restrict__ xin, __nv_bfloat16* __restrict__ xout,
                         const float* __restrict__ sc, const float* __restrict__ bi,
                         const float* __restrict__ mod) {
    int r = blockIdx.x;
    int b = r >> 11;
    const float* xr = xin + (long)r * DD;
    int tid = threadIdx.x;
    float v[4];
    float s = 0.f;
    #pragma unroll
    for (int i = 0; i < 4; i++) { v[i] = xr[tid + i * 256]; s += v[i]; }
    s = blockRed(s, 0);
    float mu = s * (1.0f / DD);
    float vs = 0.f;
    #pragma unroll
    for (int i = 0; i < 4; i++) { float d = v[i] - mu; vs += d * d; }
    vs = blockRed(vs, 0);
    float rstd = rsqrtf(vs * (1.0f / DD) + 1e-6f);
    #pragma unroll
    for (int i = 0; i < 4; i++) {
        int j = tid + i * 256;
        float y = (v[i] - mu) * rstd * sc[j] + bi[j];
        float sh = mod[(long)b * HID + j];
        float sl = mod[(long)b * HID + 1024 + j];
        xout[(long)r * DD + j] = __float2bfloat16(y * (1.f + sl) + sh);
    }
}

__global__ void k_phi(const __nv_bfloat16* __restrict__ x1, const float* __restrict__ dw,
                      const float* __restrict__ db, float* __restrict__ phi) {
    int r = blockIdx.x;
    int tid = threadIdx.x;
    float s = 0.f;
    #pragma unroll
    for (int i = 0; i < 4; i++) {
        int j = tid + i * 256;
        s += __bfloat162float(x1[(long)r * DD + j]) * dw[j];
    }
    s = blockRed(s, 0);
    if (tid == 0) phi[r] = s + db[0];
}

// bias[z*NN+n] = phi[b,n] - |q[b,h,n,:]|^2
__global__ void k_bias(const __nv_bfloat16* __restrict__ qk, const float* __restrict__ phi,
                       float* __restrict__ bias) {
    int gid = blockIdx.x * 8 + (threadIdx.x >> 5);   // (b*16+h)*2048+n
    int lane = threadIdx.x & 31;
    int n = gid & 2047;
    int h = (gid >> 11) & 15;
    int b = gid >> 15;
    const __nv_bfloat16* p = qk + ((long)b * NN + n) * DD + h * 64;
    float f0 = __bfloat162float(p[lane]);
    float f1 = __bfloat162float(p[lane + 32]);
    float s = f0 * f0 + f1 * f1;
    #pragma unroll
    for (int o = 16; o; o >>= 1) s += __shfl_xor_sync(0xffffffffu, s, o);
    if (lane == 0) bias[gid] = phi[b * NN + n] - s;
}

__global__ void k_q2c(const __nv_bfloat16* __restrict__ qkc, float* __restrict__ q2c) {
    int idx = blockIdx.x * 256 + threadIdx.x;   // (b*8+hc)*128+d
    if (idx >= BB * HCC * 128) return;
    int d = idx & 127;
    int hc = (idx >> 7) & 7;
    int b = idx >> 10;
    float s = 0.f;
    for (int n = 0; n < NN; n++) {
        float q = __bfloat162float(qkc[((long)b * NN + n) * DD + hc * 128 + d]);
        s += q * q;
    }
    q2c[idx] = s;
}

__global__ void k_softmax_ch(const float* __restrict__ S, __nv_bfloat16* __restrict__ P) {
    int row = blockIdx.x;
    int tid = threadIdx.x;
    float v = S[(long)row * 128 + tid];
    float mx = blockRed(v, 1);
    float e = expf(v - mx);
    float sum = blockRed(e, 0);
    P[(long)row * 128 + tid] = __float2bfloat16(e / sum);
}

// ------------------------- flash token attention --------------------------------
// logits_eff[m,n] = 2*q_m.q_n + bias_n   (row-constant -q2_m dropped from softmax)
__global__ void __launch_bounds__(256) k_flash(
    const __nv_bfloat16* __restrict__ qk,
    const __nv_bfloat16* __restrict__ v,
    const float* __restrict__ bias,
    __nv_bfloat16* __restrict__ out)
{
    int z = blockIdx.z;
    int b = z >> 4, h = z & 15;
    const __nv_bfloat16* Qb = qk + ((long)b * NN) * DD + h * 64;
    const __nv_bfloat16* Vb = v  + ((long)b * NN) * DD + h * 64;
    const float* biasb = bias + (long)z * NN;
    int m0 = blockIdx.y * 128;

    __shared__ __nv_bfloat16 sK[128][72];    // [token][d]
    __shared__ __nv_bfloat16 sV[64][130];    // [d][token]
    __shared__ float sBias[128];

    int tid = threadIdx.x, wid = tid >> 5, lane = tid & 31;
    int g = lane >> 2, tg = lane & 3;
    int mrow = m0 + wid * 16;

    // Q fragments (4 k16-chunks)
    uint32_t qf[4][4];
    #pragma unroll
    for (int kp = 0; kp < 4; kp++) {
        const __nv_bfloat16* q0 = Qb + (long)(mrow + g) * DD + kp * 16 + 2 * tg;
        const __nv_bfloat16* q1 = Qb + (long)(mrow + g + 8) * DD + kp * 16 + 2 * tg;
        qf[kp][0] = *(const uint32_t*)q0;
        qf[kp][1] = *(const uint32_t*)q1;
        qf[kp][2] = *(const uint32_t*)(q0 + 8);
        qf[kp][3] = *(const uint32_t*)(q1 + 8);
    }

    float m_run[2] = {-1e30f, -1e30f};
    float l_run[2] = {0.f, 0.f};
    float o[8][4];
    #pragma unroll
    for (int i = 0; i < 8; i++)
        #pragma unroll
        for (int j = 0; j < 4; j++) o[i][j] = 0.f;

    for (int n0 = 0; n0 < NN; n0 += 128) {
        // K tile (vectorized), V tile (transpose on store)
        #pragma unroll
        for (int t = 0; t < 4; t++) {
            int i = tid + t * 256;
            int tok = i >> 3, dv = (i & 7) * 8;
            *(uint4*)&sK[tok][dv] = *(const uint4*)(Qb + (long)(n0 + tok) * DD + dv);
            union { uint4 u; __nv_bfloat16 hh[8]; } tv;
            tv.u = *(const uint4*)(Vb + (long)(n0 + tok) * DD + dv);
            #pragma unroll
            for (int j = 0; j < 8; j++) sV[dv + j][tok] = tv.hh[j];
        }
        if (tid < 128) sBias[tid] = biasb[n0 + tid];
        __syncthreads();

        // S = Q @ K^T  (16 n-tiles of 8)
        float s[16][4];
        #pragma unroll
        for (int ni = 0; ni < 16; ni++) {
            s[ni][0] = s[ni][1] = s[ni][2] = s[ni][3] = 0.f;
            #pragma unroll
            for (int kp = 0; kp < 4; kp++) {
                uint32_t bv[2];
                int c = ni * 8 + g;
                bv[0] = *(const uint32_t*)&sK[c][kp * 16 + 2 * tg];
                bv[1] = *(const uint32_t*)&sK[c][kp * 16 + 2 * tg + 8];
                mma16816(s[ni], qf[kp], bv);
            }
        }

        // logits + row stats
        float mx[2] = {-1e30f, -1e30f};
        #pragma unroll
        for (int ni = 0; ni < 16; ni++) {
            #pragma unroll
            for (int j = 0; j < 4; j++) {
                float bval = sBias[ni * 8 + 2 * tg + (j & 1)];
                s[ni][j] = 2.f * s[ni][j] + bval;
                mx[j >> 1] = fmaxf(mx[j >> 1], s[ni][j]);
            }
        }
        #pragma unroll
        for (int r = 0; r < 2; r++) {
            mx[r] = fmaxf(mx[r], __shfl_xor_sync(0xffffffffu, mx[r], 1));
            mx[r] = fmaxf(mx[r], __shfl_xor_sync(0xffffffffu, mx[r], 2));
        }
        float m_new[2], alpha[2], rs[2] = {0.f, 0.f};
        #pragma unroll
        for (int r = 0; r < 2; r++) {
            m_new[r] = fmaxf(m_run[r], mx[r]);
            alpha[r] = __expf(m_run[r] - m_new[r]);
            m_run[r] = m_new[r];
        }
        #pragma unroll
        for (int ni = 0; ni < 16; ni++) {
            #pragma unroll
            for (int j = 0; j < 4; j++) {
                float p = __expf(s[ni][j] - m_new[j >> 1]);
                s[ni][j] = p;
                rs[j >> 1] += p;
            }
        }
        #pragma unroll
        for (int r = 0; r < 2; r++) {
            rs[r] += __shfl_xor_sync(0xffffffffu, rs[r], 1);
            rs[r] += __shfl_xor_sync(0xffffffffu, rs[r], 2);
            l_run[r] = l_run[r] * alpha[r] + rs[r];
        }
        // rescale O
        #pragma unroll
        for (int di = 0; di < 8; di++) {
            o[di][0] *= alpha[0]; o[di][1] *= alpha[0];
            o[di][2] *= alpha[1]; o[di][3] *= alpha[1];
        }
        // P fragments
        uint32_t pf[8][4];
        #pragma unroll
        for (int kp = 0; kp < 8; kp++) {
            pf[kp][0] = packbf(s[2 * kp][0], s[2 * kp][1]);
            pf[kp][1] = packbf(s[2 * kp][2], s[2 * kp][3]);
            pf[kp][2] = packbf(s[2 * kp + 1][0], s[2 * kp + 1][1]);
            pf[kp][3] = packbf(s[2 * kp + 1][2], s[2 * kp + 1][3]);
        }
        // O += P @ V
        #pragma unroll
        for (int kp = 0; kp < 8; kp++) {
            #pragma unroll
            for (int di = 0; di < 8; di++) {
                uint32_t bv[2];
                int c = di * 8 + g;
                bv[0] = *(const uint32_t*)&sV[c][kp * 16 + 2 * tg];
                bv[1] = *(const uint32_t*)&sV[c][kp * 16 + 2 * tg + 8];
                mma16816(o[di], pf[kp], bv);
            }
        }
        __syncthreads();
    }

    float inv0 = 1.f / l_run[0], inv1 = 1.f / l_run[1];
    long r0 = (long)(b * NN + mrow + g) * DD + h * 64;
    long r1 = (long)(b * NN + mrow + g + 8) * DD + h * 64;
    #pragma unroll
    for (int di = 0; di < 8; di++) {
        int col = di * 8 + 2 * tg;
        __nv_bfloat162 v0 = __floats2bfloat162_rn(o[di][0] * inv0, o[di][1] * inv0);
        __nv_bfloat162 v1 = __floats2bfloat162_rn(o[di][2] * inv1, o[di][3] * inv1);
        *(__nv_bfloat162*)&out[r0 + col] = v0;
        *(__nv_bfloat162*)&out[r1 + col] = v1;
    }
}

// ------------------------- GEMM params + epilogue --------------------------------
struct GemmP {
    const __nv_bfloat16 *A, *B;
    long sAm, sAk, sBk, sBn;
    long bAb, bAh, bBb, bBh, bCb, bCh;
    int nh, nb, M, N, K;
    void* C; long sCm, sCn;
    int epi, eStride;
    const float *e0, *e1, *e2;
    float f0;
};

__device__ inline void epi_write(const GemmP& p, long cOff, int z, int b, int h,
                                 int m, int n, float acc) {
    long ci = cOff + (long)m * p.sCm + (long)n * p.sCn;
    switch (p.epi) {
    case 0: {  // bf16( acc * exp(lg[b, n]) )
        float s = expf(p.e0[(long)(m >> 11) * p.eStride + n]);
        ((__nv_bfloat16*)p.C)[ci] = __float2bfloat16(acc * s);
        break; }
    case 1:
        ((__nv_bfloat16*)p.C)[ci] = __float2bfloat16(acc);
        break;
    case 3: {  // residual fp32
        int bb = m >> 11;
        float v = p.e2[(long)m * DD + n]
                  + acc * p.e0[(long)bb * p.eStride + n] * p.e1[n];
        ((float*)p.C)[ci] = v;
        break; }
    case 4: {  // channel logits
        float v = (2.f * acc - p.e0[z * 128 + m] - p.e0[z * 128 + n]) * p.f0 * p.e1[h];
        ((float*)p.C)[ci] = v;
        break; }
    }
}

// ------------------------- generic 64x64 GEMM (odd layouts, small) ---------------
__global__ void __launch_bounds__(128) k_gemm(GemmP p) {
    int z = blockIdx.z;
    int b = z / p.nh, h = z - b * p.nh;
    const __nv_bfloat16* A = p.A + (long)b * p.bAb + (long)h * p.bAh;
    const __nv_bfloat16* Bm = p.B + (long)b * p.bBb + (long)h * p.bBh;
    long cOff = (long)b * p.bCb + (long)h * p.bCh;
    int bm = blockIdx.y * 64, bn = blockIdx.x * 64;
    __shared__ __nv_bfloat16 sA[64][40];
    __shared__ __nv_bfloat16 sB[64][40];
    int tid = threadIdx.x;
    int wid = tid >> 5, lane = tid & 31, g = lane >> 2, tg = lane & 3;
    int wm = (wid >> 1) * 32, wn = (wid & 1) * 32;
    float acc[2][4][4];
    #pragma unroll
    for (int i = 0; i < 2; i++)
        #pragma unroll
        for (int j = 0; j < 4; j++)
            #pragma unroll
            for (int q = 0; q < 4; q++) acc[i][j][q] = 0.f;

    for (int k0 = 0; k0 < p.K; k0 += 32) {
        #pragma unroll
        for (int i = 0; i < 16; i++) {
            int idx = i * 128 + tid;
            int ma = idx >> 5, ka = idx & 31;
            sA[ma][ka] = A[(long)(bm + ma) * p.sAm + (long)(k0 + ka) * p.sAk];
            int kb = idx >> 6, nb2 = idx & 63;
            sB[nb2][kb] = Bm[(long)(k0 + kb) * p.sBk + (long)(bn + nb2) * p.sBn];
        }
        __syncthreads();
        #pragma unroll
        for (int kk = 0; kk < 32; kk += 16) {
            uint32_t ar[2][4], br[4][2];
            #pragma unroll
            for (int mi = 0; mi < 2; mi++) {
                int r = wm + mi * 16;
                ar[mi][0] = *(const uint32_t*)&sA[r + g][kk + 2 * tg];
                ar[mi][1] = *(const uint32_t*)&sA[r + g + 8][kk + 2 * tg];
                ar[mi][2] = *(const uint32_t*)&sA[r + g][kk + 2 * tg + 8];
                ar[mi][3] = *(const uint32_t*)&sA[r + g + 8][kk + 2 * tg + 8];
            }
            #pragma unroll
            for (int ni = 0; ni < 4; ni++) {
                int c = wn + ni * 8 + g;
                br[ni][0] = *(const uint32_t*)&sB[c][kk + 2 * tg];
                br[ni][1] = *(const uint32_t*)&sB[c][kk + 2 * tg + 8];
            }
            #pragma unroll
            for (int mi = 0; mi < 2; mi++)
                #pragma unroll
                for (int ni = 0; ni < 4; ni++)
                    mma16816(acc[mi][ni], ar[mi], br[ni]);
        }
        __syncthreads();
    }

    #pragma unroll
    for (int mi = 0; mi < 2; mi++)
        #pragma unroll
        for (int ni = 0; ni < 4; ni++) {
            int r = bm + wm + mi * 16 + g;
            int c = bn + wn + ni * 8 + 2 * tg;
            epi_write(p, cOff, z, b, h, r, c, acc[mi][ni][0]);
            epi_write(p, cOff, z, b, h, r, c + 1, acc[mi][ni][1]);
            epi_write(p, cOff, z, b, h, r + 8, c, acc[mi][ni][2]);
            epi_write(p, cOff, z, b, h, r + 8, c + 1, acc[mi][ni][3]);
        }
}

// ------------------------- fast 128x128 GEMM (row-major A k-contig, B n-contig) --
__global__ void __launch_bounds__(256) k_gemm_f(GemmP p) {
    __shared__ __nv_bfloat16 sA[128][40];
    __shared__ __nv_bfloat16 sB[128][34];   // [n][k]
    int bm = blockIdx.y * 128, bn = blockIdx.x * 128;
    int tid = threadIdx.x, wid = tid >> 5, lane = tid & 31;
    int g = lane >> 2, tg = lane & 3;
    int wm = (wid & 1) * 64, wn = (wid >> 1) * 32;
    float acc[4][4][4];
    #pragma unroll
    for (int i = 0; i < 4; i++)
        #pragma unroll
        for (int j = 0; j < 4; j++)
            #pragma unroll
            for (int q = 0; q < 4; q++) acc[i][j][q] = 0.f;

    const __nv_bfloat16* A = p.A;
    const __nv_bfloat16* Bm = p.B;

    uint4 ra[2], rb[2];
    int ia_r[2], ia_k[2], ib_k[2], ib_n[2];
    #pragma unroll
    for (int t = 0; t < 2; t++) {
        int i = tid + t * 256;
        ia_r[t] = i >> 2;        ia_k[t] = (i & 3) * 8;
        ib_k[t] = i >> 4;        ib_n[t] = (i & 15) * 8;
    }
    // prefetch k0=0
    #pragma unroll
    for (int t = 0; t < 2; t++) {
        ra[t] = *(const uint4*)(A + (long)(bm + ia_r[t]) * p.sAm + ia_k[t]);
        rb[t] = *(const uint4*)(Bm + (long)ib_k[t] * p.sBk + bn + ib_n[t]);
    }

    for (int k0 = 0; k0 < p.K; k0 += 32) {
        #pragma unroll
        for (int t = 0; t < 2; t++) {
            *(uint4*)&sA[ia_r[t]][ia_k[t]] = ra[t];
            union { uint4 u; __nv_bfloat16 hh[8]; } tv;
            tv.u = rb[t];
            #pragma unroll
            for (int j = 0; j < 8; j++) sB[ib_n[t] + j][ib_k[t]] = tv.hh[j];
        }
        __syncthreads();
        if (k0 + 32 < p.K) {
            #pragma unroll
            for (int t = 0; t < 2; t++) {
                ra[t] = *(const uint4*)(A + (long)(bm + ia_r[t]) * p.sAm + k0 + 32 + ia_k[t]);
                rb[t] = *(const uint4*)(Bm + (long)(k0 + 32 + ib_k[t]) * p.sBk + bn + ib_n[t]);
            }
        }
        #pragma unroll
        for (int kk = 0; kk < 32; kk += 16) {
            uint32_t ar[4][4], br[4][2];
            #pragma unroll
            for (int mi = 0; mi < 4; mi++) {
                int r = wm + mi * 16;
                ar[mi][0] = *(const uint32_t*)&sA[r + g][kk + 2 * tg];
                ar[mi][1] = *(const uint32_t*)&sA[r + g + 8][kk + 2 * tg];
                ar[mi][2] = *(const uint32_t*)&sA[r + g][kk + 2 * tg + 8];
                ar[mi][3] = *(const uint32_t*)&sA[r + g + 8][kk + 2 * tg + 8];
            }
            #pragma unroll
            for (int ni = 0; ni < 4; ni++) {
                int c = wn + ni * 8 + g;
                br[ni][0] = *(const uint32_t*)&sB[c][kk + 2 * tg];
                br[ni][1] = *(const uint32_t*)&sB[c][kk + 2 * tg + 8];
            }
            #pragma unroll
            for (int mi = 0; mi < 4; mi++)
                #pragma unroll
                for (int ni = 0; ni < 4; ni++)
                    mma16816(acc[mi][ni], ar[mi], br[ni]);
        }
        __syncthreads();
    }

    #pragma unroll
    for (int mi = 0; mi < 4; mi++)
        #pragma unroll
        for (int ni = 0; ni < 4; ni++) {
            int r = bm + wm + mi * 16 + g;
            int c = bn + wn + ni * 8 + 2 * tg;
            epi_write(p, 0, 0, 0, 0, r, c, acc[mi][ni][0]);
            epi_write(p, 0, 0, 0, 0, r, c + 1, acc[mi][ni][1]);
            epi_write(p, 0, 0, 0, 0, r + 8, c, acc[mi][ni][2]);
            epi_write(p, 0, 0, 0, 0, r + 8, c + 1, acc[mi][ni][3]);
        }
}

static inline void rungemm(const GemmP& p) {
    dim3 grid(p.N / 64, p.M / 64, p.nb);
    k_gemm<<<grid, 128>>>(p);
}
static inline void rungemm_f(const GemmP& p) {
    dim3 grid(p.N / 128, p.M / 128, 1);
    k_gemm_f<<<grid, 256>>>(p);
}

#define SYMADDR(v, s) do { void* _p = nullptr; cudaGetSymbolAddress(&_p, s); v = (decltype(v))_p; } while (0)

// ------------------------- launch ----------------------------------------------
extern "C" void kernel_launch(void* const* d_in, const int* in_sizes, int n_in,
                              void* d_out, int out_size) {
    const float* x        = (const float*)d_in[0];
    const float* t        = (const float*)d_in[1];
    const float* n1s      = (const float*)d_in[2];
    const float* n1b      = (const float*)d_in[3];
    const float* n2s      = (const float*)d_in[4];
    const float* n2b      = (const float*)d_in[5];
    const float* tc_w1    = (const float*)d_in[6];
    const float* tc_b1    = (const float*)d_in[7];
    const float* tc_w2    = (const float*)d_in[8];
    const float* tc_b2    = (const float*)d_in[9];
    const float* tc_wa    = (const float*)d_in[10];
    const float* tc_ba    = (const float*)d_in[11];
    const float* tc_wc    = (const float*)d_in[12];
    const float* tc_bc    = (const float*)d_in[13];
    const float* attn_qk_w = (const float*)d_in[14];
    const float* attn_v_w  = (const float*)d_in[15];
    const float* attn_out_w= (const float*)d_in[16];
    const float* doob_w   = (const float*)d_in[17];
    const float* doob_b   = (const float*)d_in[18];
    const float* ch_qk_w  = (const float*)d_in[19];
    const float* ch_v_w   = (const float*)d_in[20];
    const float* ch_out_w = (const float*)d_in[21];
    const float* tau      = (const float*)d_in[22];
    const float* gamma1   = (const float*)d_in[23];
    const float* gamma2   = (const float*)d_in[24];

    float *emb, *part, *h1, *h2, *av, *cv, *bias, *phi, *xmid, *q2c, *Scp;
    __nv_bfloat16 *wbf, *x1, *qkb, *vb, *attnb, *x2, *qkcb, *vcb, *Pcp, *chb;
    SYMADDR(emb, g_emb);   SYMADDR(part, g_part); SYMADDR(h1, g_h1);  SYMADDR(h2, g_h2);
    SYMADDR(av, g_av);     SYMADDR(cv, g_cv);     SYMADDR(wbf, g_wbf);
    SYMADDR(x1, g_x1);     SYMADDR(qkb, g_qk);    SYMADDR(vb, g_v);
    SYMADDR(bias, g_bias); SYMADDR(phi, g_phi);
    SYMADDR(attnb, g_attn);SYMADDR(xmid, g_xmid); SYMADDR(x2, g_x2);
    SYMADDR(qkcb, g_qkc);  SYMADDR(vcb, g_vc);    SYMADDR(q2c, g_q2c);
    SYMADDR(Scp, g_Sc);    SYMADDR(Pcp, g_Pc);    SYMADDR(chb, g_ch);

    k_convert<<<(6 * 1048576 + 255) / 256, 256>>>(attn_qk_w, attn_v_w, attn_out_w,
                                                  ch_qk_w, ch_v_w, ch_out_w, wbf);
    __nv_bfloat16* wqk = wbf;
    __nv_bfloat16* wv  = wbf + 1 * 1048576;
    __nv_bfloat16* wo  = wbf + 2 * 1048576;
    __nv_bfloat16* wcq = wbf + 3 * 1048576;
    __nv_bfloat16* wcv = wbf + 4 * 1048576;
    __nv_bfloat16* wco = wbf + 5 * 1048576;

    // ---- conditioning ----
    k_emb<<<(BB * HID + 255) / 256, 256>>>(t, emb);
    k_gemv_part<<<dim3(HID / 256, 16), 256>>>(emb, tc_w1, part, HID, HID);
    k_gemv_red<<<(2 * HID + 255) / 256, 256>>>(part, tc_b1, h1, HID, 1);
    k_gemv_part<<<dim3(HID / 256, 16), 256>>>(h1, tc_w2, part, HID, HID);
    k_gemv_red<<<(2 * HID + 255) / 256, 256>>>(part, tc_b2, h2, HID, 1);
    k_gemv_part<<<dim3(HID / 256, 16), 256>>>(h2, tc_wa, part, HID, HID);
    k_gemv_red<<<(2 * HID + 255) / 256, 256>>>(part, tc_ba, av, HID, 0);
    k_gemv_part<<<dim3(HID / 256, 16), 256>>>(h2, tc_wc, part, HID, HID);
    k_gemv_red<<<(2 * HID + 255) / 256, 256>>>(part, tc_bc, cv, HID, 0);

    // ---- token attention ----
    k_ln_mod<<<BN, 256>>>(x, x1, n1s, n1b, av);
    k_phi<<<BN, 256>>>(x1, doob_w, doob_b, phi);

    {   // qk = (x1 @ Wqk) * exp(a_lg)
        GemmP p = {};
        p.A = x1; p.sAm = DD; p.sAk = 1;
        p.B = wqk; p.sBk = DD; p.sBn = 1;
        p.M = BN; p.N = DD; p.K = DD;
        p.C = qkb; p.sCm = DD; p.sCn = 1;
        p.epi = 0; p.e0 = av + 3072; p.eStride = HID;
        rungemm_f(p);
    }
    {   // v = x1 @ Wv
        GemmP p = {};
        p.A = x1; p.sAm = DD; p.sAk = 1;
        p.B = wv; p.sBk = DD; p.sBn = 1;
        p.M = BN; p.N = DD; p.K = DD;
        p.C = vb; p.sCm = DD; p.sCn = 1;
        p.epi = 1;
        rungemm_f(p);
    }
    k_bias<<<BB * HH * NN / 8, 256>>>(qkb, phi, bias);
    k_flash<<<dim3(1, 16, BB * HH), 256>>>(qkb, vb, bias, attnb);
    {   // x_mid = x + (attn @ Wo) * a_gate * gamma1
        GemmP p = {};
        p.A = attnb; p.sAm = DD; p.sAk = 1;
        p.B = wo; p.sBk = DD; p.sBn = 1;
        p.M = BN; p.N = DD; p.K = DD;
        p.C = xmid; p.sCm = DD; p.sCn = 1;
        p.epi = 3; p.e0 = av + 2048; p.eStride = HID; p.e1 = gamma1; p.e2 = x;
        rungemm_f(p);
    }

    // ---- channel attention ----
    k_ln_mod<<<BN, 256>>>(xmid, x2, n2s, n2b, cv);
    {   // qkc = (x2 @ Wcq) * exp(c_lg)
        GemmP p = {};
        p.A = x2; p.sAm = DD; p.sAk = 1;
        p.B = wcq; p.sBk = DD; p.sBn = 1;
        p.M = BN; p.N = DD; p.K = DD;
        p.C = qkcb; p.sCm = DD; p.sCn = 1;
        p.epi = 0; p.e0 = cv + 3072; p.eStride = HID;
        rungemm_f(p);
    }
    {   // vc = x2 @ Wcv
        GemmP p = {};
        p.A = x2; p.sAm = DD; p.sAk = 1;
        p.B = wcv; p.sBk = DD; p.sBn = 1;
        p.M = BN; p.N = DD; p.K = DD;
        p.C = vcb; p.sCm = DD; p.sCn = 1;
        p.epi = 1;
        rungemm_f(p);
    }
    k_q2c<<<(BB * HCC * 128 + 255) / 256, 256>>>(qkcb, q2c);
    {   // Sc[z] = (2 Qc Qc^T - q2c_m - q2c_n)/sqrt(N) * tau[hc]
        GemmP p = {};
        p.A = qkcb; p.sAm = 1; p.sAk = DD; p.bAb = (long)NN * DD; p.bAh = 128;
        p.B = qkcb; p.sBk = DD; p.sBn = 1; p.bBb = (long)NN * DD; p.bBh = 128;
        p.M = 128; p.N = 128; p.K = NN; p.nh = HCC; p.nb = BB * HCC;
        p.C = Scp; p.sCm = 128; p.sCn = 1;
        p.bCb = (long)HCC * 128 * 128; p.bCh = 128 * 128;
        p.epi = 4; p.e0 = q2c; p.e1 = tau;
        p.f0 = 0.022097086912079608f;  // 1/sqrt(2048)
        rungemm(p);
    }
    k_softmax_ch<<<BB * HCC * 128, 128>>>(Scp, Pcp);
    {   // ch[b,n,hc*128+c] = sum_d Vc^T[n][d] * Pc^T[d][c]  (Vc coalesced)
        GemmP p = {};
        p.A = vcb; p.sAm = DD; p.sAk = 1; p.bAb = (long)NN * DD; p.bAh = 128;
        p.B = Pcp; p.sBk = 1; p.sBn = 128;
        p.bBb = (long)HCC * 128 * 128; p.bBh = 128 * 128;
        p.M = NN; p.N = 128; p.K = 128; p.nh = HCC; p.nb = BB * HCC;
        p.C = chb; p.sCm = DD; p.sCn = 1;
        p.bCb = (long)NN * DD; p.bCh = 128;
        p.epi = 1;
        rungemm(p);
    }
    {   // out = x_mid + (ch @ Wco) * c_gate * gamma2
        GemmP p = {};
        p.A = chb; p.sAm = DD; p.sAk = 1;
        p.B = wco; p.sBk = DD; p.sBn = 1;
        p.M = BN; p.N = DD; p.K = DD;
        p.C = d_out; p.sCm = DD; p.sCn = 1;
        p.epi = 3; p.e0 = cv + 2048; p.eStride = HID; p.e1 = gamma2; p.e2 = xmid;
        rungemm_f(p);
    }
}

// round 4
// speedup vs baseline: 3.0698x; 1.3194x over previous
#include <cuda_runtime.h>
#include <cuda_bf16.h>
#include <math.h>
#include <stdint.h>

// Problem constants
#define BB 2
#define NN 2048
#define DD 1024
#define HH 16
#define HCC 8
#define HID 4096
#define BN (BB*NN)          // 4096 rows

// ------------------------- scratch (device globals; no allocs allowed) ---------
__device__ float g_emb[BB*HID];
__device__ float g_part[32*2*HID];
__device__ float g_h1[BB*HID];
__device__ float g_h2[BB*HID];
__device__ float g_av[BB*HID];
__device__ float g_cv[BB*HID];
__device__ __nv_bfloat16 g_wbf[6u*1048576u];        // 6 transposed bf16 weights [n][k]
__device__ __nv_bfloat16 g_x1[BN*DD];
__device__ __nv_bfloat16 g_qk[BN*DD];
__device__ __nv_bfloat16 g_v[BN*DD];
__device__ float g_bias[BB*HH*NN];                  // phi - q2 per key
__device__ float g_phi[BB*NN];
__device__ __nv_bfloat16 g_attn[BN*DD];
__device__ float g_xmid[BN*DD];
__device__ __nv_bfloat16 g_x2[BN*DD];
__device__ __nv_bfloat16 g_qkc[BN*DD];
__device__ __nv_bfloat16 g_vc[BN*DD];
__device__ float g_q2c[BB*HCC*128];
__device__ float g_Sc[BB*HCC*128*128];
__device__ __nv_bfloat16 g_Pc[BB*HCC*128*128];
__device__ __nv_bfloat16 g_ch[BN*DD];

// ------------------------- helpers ---------------------------------------------
__device__ inline float blockRed(float v, int op) {  // op: 0=sum, 1=max ; broadcast
    __shared__ float sm[32];
    int lane = threadIdx.x & 31, w = threadIdx.x >> 5;
    #pragma unroll
    for (int o = 16; o; o >>= 1) {
        float t = __shfl_xor_sync(0xffffffffu, v, o);
        v = op ? fmaxf(v, t) : v + t;
    }
    if (lane == 0) sm[w] = v;
    __syncthreads();
    int nw = blockDim.x >> 5;
    if (w == 0) {
        v = (lane < nw) ? sm[lane] : (op ? -INFINITY : 0.f);
        #pragma unroll
        for (int o = 16; o; o >>= 1) {
            float t = __shfl_xor_sync(0xffffffffu, v, o);
            v = op ? fmaxf(v, t) : v + t;
        }
        if (lane == 0) sm[0] = v;
    }
    __syncthreads();
    float r = sm[0];
    __syncthreads();
    return r;
}

__device__ inline void mma16816(float* c, const uint32_t* a, const uint32_t* b) {
    asm volatile(
        "mma.sync.aligned.m16n8k16.row.col.f32.bf16.bf16.f32 "
        "{%0,%1,%2,%3}, {%4,%5,%6,%7}, {%8,%9}, {%0,%1,%2,%3};\n"
        : "+f"(c[0]), "+f"(c[1]), "+f"(c[2]), "+f"(c[3])
        : "r"(a[0]), "r"(a[1]), "r"(a[2]), "r"(a[3]), "r"(b[0]), "r"(b[1]));
}

__device__ inline uint32_t packbf(float a, float b) {
    __nv_bfloat162 t = __floats2bfloat162_rn(a, b);
    return *(uint32_t*)&t;
}

__device__ inline uint32_t smem_u32(const void* p) {
    uint32_t a;
    asm("{ .reg .u64 t; cvta.to.shared.u64 t, %1; cvt.u32.u64 %0, t; }" : "=r"(a) : "l"(p));
    return a;
}

__device__ inline void cp_async16(uint32_t saddr, const void* gaddr) {
    asm volatile("cp.async.cg.shared.global [%0], [%1], 16;" :: "r"(saddr), "l"(gaddr));
}

// ------------------------- small kernels ----------------------------------------
__global__ void k_emb(const float* __restrict__ t, float* __restrict__ emb) {
    int i = blockIdx.x * 256 + threadIdx.x;
    if (i >= BB * HID) return;
    int b = i / HID, j = i % HID;
    int jj = j & 2047;
    float f = expf(-9.210340371976184f * (float)jj / 2048.0f);
    float a = t[b] * f;
    emb[i] = (j < 2048) ? cosf(a) : sinf(a);
}

__global__ void k_gemv_part(const float* __restrict__ in, const float* __restrict__ W,
                            float* __restrict__ part, int K, int Nout) {
    int col = blockIdx.x * 256 + threadIdx.x;
    int ks = K / 32;
    int k0 = blockIdx.y * ks;
    float a0 = 0.f, a1 = 0.f;
    #pragma unroll 8
    for (int k = k0; k < k0 + ks; k++) {
        float w = W[(long)k * Nout + col];
        a0 += in[k] * w;
        a1 += in[K + k] * w;
    }
    part[((long)blockIdx.y * 2 + 0) * Nout + col] = a0;
    part[((long)blockIdx.y * 2 + 1) * Nout + col] = a1;
}

__global__ void k_gemv_red(const float* __restrict__ part, const float* __restrict__ bias,
                           float* __restrict__ out, int Nout, int act) {
    int i = blockIdx.x * 256 + threadIdx.x;
    if (i >= 2 * Nout) return;
    int b = i / Nout, col = i % Nout;
    float s = bias[col];
    #pragma unroll 8
    for (int p = 0; p < 32; p++) s += part[((long)p * 2 + b) * Nout + col];
    if (act) s = s / (1.f + expf(-s));   // silu
    out[(long)b * Nout + col] = s;
}

// tiled transpose + fp32->bf16: out[z][n][k] = w_z[k][n]
__global__ void k_convt(const float* __restrict__ w0, const float* __restrict__ w1,
                        const float* __restrict__ w2, const float* __restrict__ w3,
                        const float* __restrict__ w4, const float* __restrict__ w5,
                        __nv_bfloat16* __restrict__ out) {
    __shared__ float t[32][33];
    const float* s = w0;
    int z = blockIdx.z;
    if (z == 1) s = w1; else if (z == 2) s = w2; else if (z == 3) s = w3;
    else if (z == 4) s = w4; else if (z == 5) s = w5;
    int x = blockIdx.x * 32 + threadIdx.x;   // n
    int y0 = blockIdx.y * 32;                // k
    #pragma unroll
    for (int j = 0; j < 32; j += 8)
        t[threadIdx.y + j][threadIdx.x] = s[(long)(y0 + threadIdx.y + j) * DD + x];
    __syncthreads();
    __nv_bfloat16* d = out + (long)z * 1048576;
    int n = blockIdx.x * 32 + threadIdx.y;
    int k = y0 + threadIdx.x;
    #pragma unroll
    for (int j = 0; j < 32; j += 8)
        d[(long)(n + j) * DD + k] = __float2bfloat16(t[threadIdx.x][threadIdx.y + j]);
}

// LayerNorm + modulate -> bf16
__global__ void k_ln_mod(const float* __restrict__ xin, __nv_bfloat16* __restrict__ xout,
                         const float* __restrict__ sc, const float* __restrict__ bi,
                         const float* __restrict__ mod) {
    int r = blockIdx.x;
    int b = r >> 11;
    const float* xr = xin + (long)r * DD;
    int tid = threadIdx.x;
    float v[4];
    float s = 0.f;
    #pragma unroll
    for (int i = 0; i < 4; i++) { v[i] = xr[tid + i * 256]; s += v[i]; }
    s = blockRed(s, 0);
    float mu = s * (1.0f / DD);
    float vs = 0.f;
    #pragma unroll
    for (int i = 0; i < 4; i++) { float d = v[i] - mu; vs += d * d; }
    vs = blockRed(vs, 0);
    float rstd = rsqrtf(vs * (1.0f / DD) + 1e-6f);
    #pragma unroll
    for (int i = 0; i < 4; i++) {
        int j = tid + i * 256;
        float y = (v[i] - mu) * rstd * sc[j] + bi[j];
        float sh = mod[(long)b * HID + j];
        float sl = mod[(long)b * HID + 1024 + j];
        xout[(long)r * DD + j] = __float2bfloat16(y * (1.f + sl) + sh);
    }
}

__global__ void k_phi(const __nv_bfloat16* __restrict__ x1, const float* __restrict__ dw,
                      const float* __restrict__ db, float* __restrict__ phi) {
    int r = blockIdx.x;
    int tid = threadIdx.x;
    float s = 0.f;
    #pragma unroll
    for (int i = 0; i < 4; i++) {
        int j = tid + i * 256;
        s += __bfloat162float(x1[(long)r * DD + j]) * dw[j];
    }
    s = blockRed(s, 0);
    if (tid == 0) phi[r] = s + db[0];
}

// bias[z*NN+n] = phi[b,n] - |q[b,h,n,:]|^2
__global__ void k_bias(const __nv_bfloat16* __restrict__ qk, const float* __restrict__ phi,
                       float* __restrict__ bias) {
    int gid = blockIdx.x * 8 + (threadIdx.x >> 5);   // (b*16+h)*2048+n
    int lane = threadIdx.x & 31;
    int n = gid & 2047;
    int h = (gid >> 11) & 15;
    int b = gid >> 15;
    const __nv_bfloat16* p = qk + ((long)b * NN + n) * DD + h * 64;
    float f0 = __bfloat162float(p[lane]);
    float f1 = __bfloat162float(p[lane + 32]);
    float s = f0 * f0 + f1 * f1;
    #pragma unroll
    for (int o = 16; o; o >>= 1) s += __shfl_xor_sync(0xffffffffu, s, o);
    if (lane == 0) bias[gid] = phi[b * NN + n] - s;
}

// q2c two-pass (coalesced)
__global__ void k_q2c_part(const __nv_bfloat16* __restrict__ qkc, float* __restrict__ part) {
    int z = blockIdx.x;          // (b*8+hc)
    int ns = blockIdx.y;         // 0..15
    int d = threadIdx.x;         // 128
    int b = z >> 3, hc = z & 7;
    const __nv_bfloat16* base = qkc + ((long)b * NN + ns * 128) * DD + hc * 128 + d;
    float s = 0.f;
    #pragma unroll 4
    for (int n = 0; n < 128; n++) {
        float q = __bfloat162float(base[(long)n * DD]);
        s += q * q;
    }
    part[(z * 16 + ns) * 128 + d] = s;
}

__global__ void k_q2c_red(const float* __restrict__ part, float* __restrict__ q2c) {
    int i = blockIdx.x * 256 + threadIdx.x;
    if (i >= BB * HCC * 128) return;
    int z = i >> 7, d = i & 127;
    float s = 0.f;
    #pragma unroll
    for (int j = 0; j < 16; j++) s += part[(z * 16 + j) * 128 + d];
    q2c[i] = s;
}

__global__ void k_softmax_ch(const float* __restrict__ S, __nv_bfloat16* __restrict__ P) {
    int row = blockIdx.x;
    int tid = threadIdx.x;
    float v = S[(long)row * 128 + tid];
    float mx = blockRed(v, 1);
    float e = expf(v - mx);
    float sum = blockRed(e, 0);
    P[(long)row * 128 + tid] = __float2bfloat16(e / sum);
}

// ------------------------- flash token attention --------------------------------
// logits_eff[m,n] = 2*q_m.q_n + bias_n ; register-prefetch of next K/V tile
__global__ void __launch_bounds__(256) k_flash(
    const __nv_bfloat16* __restrict__ qk,
    const __nv_bfloat16* __restrict__ v,
    const float* __restrict__ bias,
    __nv_bfloat16* __restrict__ out)
{
    int z = blockIdx.z;
    int b = z >> 4, h = z & 15;
    const __nv_bfloat16* Qb = qk + ((long)b * NN) * DD + h * 64;
    const __nv_bfloat16* Vb = v  + ((long)b * NN) * DD + h * 64;
    const float* biasb = bias + (long)z * NN;
    int m0 = blockIdx.y * 128;

    __shared__ __nv_bfloat16 sK[128][72];
    __shared__ __nv_bfloat16 sV[64][130];
    __shared__ float sBias[128];

    int tid = threadIdx.x, wid = tid >> 5, lane = tid & 31;
    int g = lane >> 2, tg = lane & 3;
    int mrow = m0 + wid * 16;
    int ptok = tid >> 1, pdv = (tid & 1) * 32;   // unused placeholder (kept simple below)
    (void)ptok; (void)pdv;

    uint32_t qf[4][4];
    #pragma unroll
    for (int kp = 0; kp < 4; kp++) {
        const __nv_bfloat16* q0 = Qb + (long)(mrow + g) * DD + kp * 16 + 2 * tg;
        const __nv_bfloat16* q1 = Qb + (long)(mrow + g + 8) * DD + kp * 16 + 2 * tg;
        qf[kp][0] = *(const uint32_t*)q0;
        qf[kp][1] = *(const uint32_t*)q1;
        qf[kp][2] = *(const uint32_t*)(q0 + 8);
        qf[kp][3] = *(const uint32_t*)(q1 + 8);
    }

    // prefetch tile 0 into registers
    uint4 rk[4], rv[4];
    #pragma unroll
    for (int t = 0; t < 4; t++) {
        int i = tid + t * 256;
        int tok = i >> 3, dv = (i & 7) * 8;
        rk[t] = *(const uint4*)(Qb + (long)tok * DD + dv);
        rv[t] = *(const uint4*)(Vb + (long)tok * DD + dv);
    }

    float m_run[2] = {-1e30f, -1e30f};
    float l_run[2] = {0.f, 0.f};
    float o[8][4];
    #pragma unroll
    for (int i = 0; i < 8; i++)
        #pragma unroll
        for (int j = 0; j < 4; j++) o[i][j] = 0.f;

    for (int n0 = 0; n0 < NN; n0 += 128) {
        // store prefetched tile into smem
        #pragma unroll
        for (int t = 0; t < 4; t++) {
            int i = tid + t * 256;
            int tok = i >> 3, dv = (i & 7) * 8;
            *(uint4*)&sK[tok][dv] = rk[t];
            union { uint4 u; __nv_bfloat16 hh[8]; } tv;
            tv.u = rv[t];
            #pragma unroll
            for (int j = 0; j < 8; j++) sV[dv + j][tok] = tv.hh[j];
        }
        if (tid < 128) sBias[tid] = biasb[n0 + tid];
        __syncthreads();

        // issue next tile's global loads (latency hidden behind compute)
        if (n0 + 128 < NN) {
            #pragma unroll
            for (int t = 0; t < 4; t++) {
                int i = tid + t * 256;
                int tok = i >> 3, dv = (i & 7) * 8;
                rk[t] = *(const uint4*)(Qb + (long)(n0 + 128 + tok) * DD + dv);
                rv[t] = *(const uint4*)(Vb + (long)(n0 + 128 + tok) * DD + dv);
            }
        }

        float s[16][4];
        #pragma unroll
        for (int ni = 0; ni < 16; ni++) {
            s[ni][0] = s[ni][1] = s[ni][2] = s[ni][3] = 0.f;
            #pragma unroll
            for (int kp = 0; kp < 4; kp++) {
                uint32_t bv[2];
                int c = ni * 8 + g;
                bv[0] = *(const uint32_t*)&sK[c][kp * 16 + 2 * tg];
                bv[1] = *(const uint32_t*)&sK[c][kp * 16 + 2 * tg + 8];
                mma16816(s[ni], qf[kp], bv);
            }
        }

        float mx[2] = {-1e30f, -1e30f};
        #pragma unroll
        for (int ni = 0; ni < 16; ni++) {
            #pragma unroll
            for (int j = 0; j < 4; j++) {
                float bval = sBias[ni * 8 + 2 * tg + (j & 1)];
                s[ni][j] = 2.f * s[ni][j] + bval;
                mx[j >> 1] = fmaxf(mx[j >> 1], s[ni][j]);
            }
        }
        #pragma unroll
        for (int r = 0; r < 2; r++) {
            mx[r] = fmaxf(mx[r], __shfl_xor_sync(0xffffffffu, mx[r], 1));
            mx[r] = fmaxf(mx[r], __shfl_xor_sync(0xffffffffu, mx[r], 2));
        }
        float m_new[2], alpha[2], rs[2] = {0.f, 0.f};
        #pragma unroll
        for (int r = 0; r < 2; r++) {
            m_new[r] = fmaxf(m_run[r], mx[r]);
            alpha[r] = __expf(m_run[r] - m_new[r]);
            m_run[r] = m_new[r];
        }
        #pragma unroll
        for (int ni = 0; ni < 16; ni++) {
            #pragma unroll
            for (int j = 0; j < 4; j++) {
                float p = __expf(s[ni][j] - m_new[j >> 1]);
                s[ni][j] = p;
                rs[j >> 1] += p;
            }
        }
        #pragma unroll
        for (int r = 0; r < 2; r++) {
            rs[r] += __shfl_xor_sync(0xffffffffu, rs[r], 1);
            rs[r] += __shfl_xor_sync(0xffffffffu, rs[r], 2);
            l_run[r] = l_run[r] * alpha[r] + rs[r];
        }
        #pragma unroll
        for (int di = 0; di < 8; di++) {
            o[di][0] *= alpha[0]; o[di][1] *= alpha[0];
            o[di][2] *= alpha[1]; o[di][3] *= alpha[1];
        }
        uint32_t pf[8][4];
        #pragma unroll
        for (int kp = 0; kp < 8; kp++) {
            pf[kp][0] = packbf(s[2 * kp][0], s[2 * kp][1]);
            pf[kp][1] = packbf(s[2 * kp][2], s[2 * kp][3]);
            pf[kp][2] = packbf(s[2 * kp + 1][0], s[2 * kp + 1][1]);
            pf[kp][3] = packbf(s[2 * kp + 1][2], s[2 * kp + 1][3]);
        }
        #pragma unroll
        for (int kp = 0; kp < 8; kp++) {
            #pragma unroll
            for (int di = 0; di < 8; di++) {
                uint32_t bv[2];
                int c = di * 8 + g;
                bv[0] = *(const uint32_t*)&sV[c][kp * 16 + 2 * tg];
                bv[1] = *(const uint32_t*)&sV[c][kp * 16 + 2 * tg + 8];
                mma16816(o[di], pf[kp], bv);
            }
        }
        __syncthreads();
    }

    float inv0 = 1.f / l_run[0], inv1 = 1.f / l_run[1];
    long r0 = (long)(b * NN + mrow + g) * DD + h * 64;
    long r1 = (long)(b * NN + mrow + g + 8) * DD + h * 64;
    #pragma unroll
    for (int di = 0; di < 8; di++) {
        int col = di * 8 + 2 * tg;
        __nv_bfloat162 v0 = __floats2bfloat162_rn(o[di][0] * inv0, o[di][1] * inv0);
        __nv_bfloat162 v1 = __floats2bfloat162_rn(o[di][2] * inv1, o[di][3] * inv1);
        *(__nv_bfloat162*)&out[r0 + col] = v0;
        *(__nv_bfloat162*)&out[r1 + col] = v1;
    }
}

// ------------------------- fast 128x128 GEMM, cp.async, both operands k-contig ---
// C[M,N] = A[M,K] @ B^T  with A row-major [m][k], B row-major [n][k] (transposed W)
struct GemmF {
    const __nv_bfloat16 *A, *B;
    void* C;
    int epi;                      // 0: bf16*exp(e0), 1: bf16, 3: fp32 residual
    const float *e0, *e1, *e2;
};

#define GF_SMEM (4*128*72*2)     // 73728 bytes

__global__ void __launch_bounds__(256) k_gemm_f2(GemmF p) {
    extern __shared__ __nv_bfloat16 smdyn[];
    __nv_bfloat16* sA[2] = { smdyn,              smdyn + 128 * 72 };
    __nv_bfloat16* sB[2] = { smdyn + 2 * 128 * 72, smdyn + 3 * 128 * 72 };
    int tid = threadIdx.x, wid = tid >> 5, lane = tid & 31;
    int g = lane >> 2, tg = lane & 3;
    int bm = blockIdx.y * 128, bn = blockIdx.x * 128;
    int wm = (wid & 1) * 64, wn = (wid >> 1) * 32;
    const __nv_bfloat16* Ag = p.A + (long)bm * DD;
    const __nv_bfloat16* Bg = p.B + (long)bn * DD;

    int lrow = tid >> 1, lv = (tid & 1) * 8;   // 256 threads: rows 0..127, 2 vec each... 
    // We need 8 uint4 per operand per stage with 256 threads -> 4 iterations of (row,v)
    float acc[4][4][4];
    #pragma unroll
    for (int i = 0; i < 4; i++)
        #pragma unroll
        for (int j = 0; j < 4; j++)
            #pragma unroll
            for (int q = 0; q < 4; q++) acc[i][j][q] = 0.f;
    (void)lrow; (void)lv;

    // prologue: stage 0
    {
        #pragma unroll
        for (int t = 0; t < 4; t++) {
            int idx = tid + t * 256;
            int row = idx >> 3, v = (idx & 7) * 8;
            cp_async16(smem_u32(&sA[0][row * 72 + v]), Ag + (long)row * DD + v);
            cp_async16(smem_u32(&sB[0][row * 72 + v]), Bg + (long)row * DD + v);
        }
        asm volatile("cp.async.commit_group;");
    }

    #pragma unroll 1
    for (int c = 0; c < 16; c++) {
        int s = c & 1;
        if (c < 15) {
            int s2 = s ^ 1, k0 = (c + 1) * 64;
            #pragma unroll
            for (int t = 0; t < 4; t++) {
                int idx = tid + t * 256;
                int row = idx >> 3, v = (idx & 7) * 8;
                cp_async16(smem_u32(&sA[s2][row * 72 + v]), Ag + (long)row * DD + k0 + v);
                cp_async16(smem_u32(&sB[s2][row * 72 + v]), Bg + (long)row * DD + k0 + v);
            }
            asm volatile("cp.async.commit_group;");
            asm volatile("cp.async.wait_group 1;");
        } else {
            asm volatile("cp.async.wait_group 0;");
        }
        __syncthreads();

        const __nv_bfloat16* cA = sA[s];
        const __nv_bfloat16* cB = sB[s];
        #pragma unroll
        for (int kk = 0; kk < 64; kk += 16) {
            uint32_t ar[4][4], br[4][2];
            #pragma unroll
            for (int mi = 0; mi < 4; mi++) {
                int r = wm + mi * 16;
                ar[mi][0] = *(const uint32_t*)&cA[(r + g) * 72 + kk + 2 * tg];
                ar[mi][1] = *(const uint32_t*)&cA[(r + g + 8) * 72 + kk + 2 * tg];
                ar[mi][2] = *(const uint32_t*)&cA[(r + g) * 72 + kk + 2 * tg + 8];
                ar[mi][3] = *(const uint32_t*)&cA[(r + g + 8) * 72 + kk + 2 * tg + 8];
            }
            #pragma unroll
            for (int ni = 0; ni < 4; ni++) {
                int cc = wn + ni * 8 + g;
                br[ni][0] = *(const uint32_t*)&cB[cc * 72 + kk + 2 * tg];
                br[ni][1] = *(const uint32_t*)&cB[cc * 72 + kk + 2 * tg + 8];
            }
            #pragma unroll
            for (int mi = 0; mi < 4; mi++)
                #pragma unroll
                for (int ni = 0; ni < 4; ni++)
                    mma16816(acc[mi][ni], ar[mi], br[ni]);
        }
        __syncthreads();
    }

    // epilogue
    #pragma unroll
    for (int mi = 0; mi < 4; mi++)
        #pragma unroll
        for (int ni = 0; ni < 4; ni++) {
            #pragma unroll
            for (int hh = 0; hh < 2; hh++) {
                int r = bm + wm + mi * 16 + g + hh * 8;
                int cc = bn + wn + ni * 8 + 2 * tg;
                float a0 = acc[mi][ni][2 * hh], a1 = acc[mi][ni][2 * hh + 1];
                int bb = r >> 11;
                if (p.epi == 0) {
                    float s0 = expf(p.e0[(long)bb * HID + cc]);
                    float s1 = expf(p.e0[(long)bb * HID + cc + 1]);
                    *(__nv_bfloat162*)&((__nv_bfloat16*)p.C)[(long)r * DD + cc] =
                        __floats2bfloat162_rn(a0 * s0, a1 * s1);
                } else if (p.epi == 1) {
                    *(__nv_bfloat162*)&((__nv_bfloat16*)p.C)[(long)r * DD + cc] =
                        __floats2bfloat162_rn(a0, a1);
                } else {
                    float* dst = (float*)p.C + (long)r * DD + cc;
                    const float* res = p.e2 + (long)r * DD + cc;
                    dst[0] = res[0] + a0 * p.e0[(long)bb * HID + cc] * p.e1[cc];
                    dst[1] = res[1] + a1 * p.e0[(long)bb * HID + cc + 1] * p.e1[cc + 1];
                }
            }
        }
}

// ------------------------- generic 64x64 GEMM (channel path) ---------------------
struct GemmP {
    const __nv_bfloat16 *A, *B;
    long sAm, sAk, sBk, sBn;
    long bAb, bAh, bBb, bBh, bCb, bCh;
    int nh, nb, M, N, K;
    void* C; long sCm, sCn;
    int epi, eStride;
    const float *e0, *e1, *e2;
    float f0;
};

__device__ inline void epi_write(const GemmP& p, long cOff, int z, int b, int h,
                                 int m, int n, float acc) {
    long ci = cOff + (long)m * p.sCm + (long)n * p.sCn;
    switch (p.epi) {
    case 1:
        ((__nv_bfloat16*)p.C)[ci] = __float2bfloat16(acc);
        break;
    case 4: {  // channel logits
        float v = (2.f * acc - p.e0[z * 128 + m] - p.e0[z * 128 + n]) * p.f0 * p.e1[h];
        ((float*)p.C)[ci] = v;
        break; }
    }
}

__global__ void __launch_bounds__(128) k_gemm(GemmP p) {
    int z = blockIdx.z;
    int b = z / p.nh, h = z - b * p.nh;
    const __nv_bfloat16* A = p.A + (long)b * p.bAb + (long)h * p.bAh;
    const __nv_bfloat16* Bm = p.B + (long)b * p.bBb + (long)h * p.bBh;
    long cOff = (long)b * p.bCb + (long)h * p.bCh;
    int bm = blockIdx.y * 64, bn = blockIdx.x * 64;
    __shared__ __nv_bfloat16 sA[64][40];
    __shared__ __nv_bfloat16 sB[64][40];
    int tid = threadIdx.x;
    int wid = tid >> 5, lane = tid & 31, g = lane >> 2, tg = lane & 3;
    int wm = (wid >> 1) * 32, wn = (wid & 1) * 32;
    float acc[2][4][4];
    #pragma unroll
    for (int i = 0; i < 2; i++)
        #pragma unroll
        for (int j = 0; j < 4; j++)
            #pragma unroll
            for (int q = 0; q < 4; q++) acc[i][j][q] = 0.f;

    for (int k0 = 0; k0 < p.K; k0 += 32) {
        #pragma unroll
        for (int i = 0; i < 16; i++) {
            int idx = i * 128 + tid;
            int ma = idx >> 5, ka = idx & 31;
            sA[ma][ka] = A[(long)(bm + ma) * p.sAm + (long)(k0 + ka) * p.sAk];
            int kb = idx >> 6, nb2 = idx & 63;
            sB[nb2][kb] = Bm[(long)(k0 + kb) * p.sBk + (long)(bn + nb2) * p.sBn];
        }
        __syncthreads();
        #pragma unroll
        for (int kk = 0; kk < 32; kk += 16) {
            uint32_t ar[2][4], br[4][2];
            #pragma unroll
            for (int mi = 0; mi < 2; mi++) {
                int r = wm + mi * 16;
                ar[mi][0] = *(const uint32_t*)&sA[r + g][kk + 2 * tg];
                ar[mi][1] = *(const uint32_t*)&sA[r + g + 8][kk + 2 * tg];
                ar[mi][2] = *(const uint32_t*)&sA[r + g][kk + 2 * tg + 8];
                ar[mi][3] = *(const uint32_t*)&sA[r + g + 8][kk + 2 * tg + 8];
            }
            #pragma unroll
            for (int ni = 0; ni < 4; ni++) {
                int c = wn + ni * 8 + g;
                br[ni][0] = *(const uint32_t*)&sB[c][kk + 2 * tg];
                br[ni][1] = *(const uint32_t*)&sB[c][kk + 2 * tg + 8];
            }
            #pragma unroll
            for (int mi = 0; mi < 2; mi++)
                #pragma unroll
                for (int ni = 0; ni < 4; ni++)
                    mma16816(acc[mi][ni], ar[mi], br[ni]);
        }
        __syncthreads();
    }

    #pragma unroll
    for (int mi = 0; mi < 2; mi++)
        #pragma unroll
        for (int ni = 0; ni < 4; ni++) {
            int r = bm + wm + mi * 16 + g;
            int c = bn + wn + ni * 8 + 2 * tg;
            epi_write(p, cOff, z, b, h, r, c, acc[mi][ni][0]);
            epi_write(p, cOff, z, b, h, r, c + 1, acc[mi][ni][1]);
            epi_write(p, cOff, z, b, h, r + 8, c, acc[mi][ni][2]);
            epi_write(p, cOff, z, b, h, r + 8, c + 1, acc[mi][ni][3]);
        }
}

static inline void rungemm(const GemmP& p) {
    dim3 grid(p.N / 64, p.M / 64, p.nb);
    k_gemm<<<grid, 128>>>(p);
}

static inline void rungemm_f2(const GemmF& p) {
    static int inited = 0;
    if (!inited) {
        cudaFuncSetAttribute(k_gemm_f2, cudaFuncAttributeMaxDynamicSharedMemorySize, GF_SMEM);
        inited = 1;
    }
    dim3 grid(DD / 128, BN / 128, 1);
    k_gemm_f2<<<grid, 256, GF_SMEM>>>(p);
}

#define SYMADDR(v, s) do { void* _p = nullptr; cudaGetSymbolAddress(&_p, s); v = (decltype(v))_p; } while (0)

// ------------------------- launch ----------------------------------------------
extern "C" void kernel_launch(void* const* d_in, const int* in_sizes, int n_in,
                              void* d_out, int out_size) {
    const float* x        = (const float*)d_in[0];
    const float* t        = (const float*)d_in[1];
    const float* n1s      = (const float*)d_in[2];
    const float* n1b      = (const float*)d_in[3];
    const float* n2s      = (const float*)d_in[4];
    const float* n2b      = (const float*)d_in[5];
    const float* tc_w1    = (const float*)d_in[6];
    const float* tc_b1    = (const float*)d_in[7];
    const float* tc_w2    = (const float*)d_in[8];
    const float* tc_b2    = (const float*)d_in[9];
    const float* tc_wa    = (const float*)d_in[10];
    const float* tc_ba    = (const float*)d_in[11];
    const float* tc_wc    = (const float*)d_in[12];
    const float* tc_bc    = (const float*)d_in[13];
    const float* attn_qk_w = (const float*)d_in[14];
    const float* attn_v_w  = (const float*)d_in[15];
    const float* attn_out_w= (const float*)d_in[16];
    const float* doob_w   = (const float*)d_in[17];
    const float* doob_b   = (const float*)d_in[18];
    const float* ch_qk_w  = (const float*)d_in[19];
    const float* ch_v_w   = (const float*)d_in[20];
    const float* ch_out_w = (const float*)d_in[21];
    const float* tau      = (const float*)d_in[22];
    const float* gamma1   = (const float*)d_in[23];
    const float* gamma2   = (const float*)d_in[24];

    float *emb, *part, *h1, *h2, *av, *cv, *bias, *phi, *xmid, *q2c, *Scp;
    __nv_bfloat16 *wbf, *x1, *qkb, *vb, *attnb, *x2, *qkcb, *vcb, *Pcp, *chb;
    SYMADDR(emb, g_emb);   SYMADDR(part, g_part); SYMADDR(h1, g_h1);  SYMADDR(h2, g_h2);
    SYMADDR(av, g_av);     SYMADDR(cv, g_cv);     SYMADDR(wbf, g_wbf);
    SYMADDR(x1, g_x1);     SYMADDR(qkb, g_qk);    SYMADDR(vb, g_v);
    SYMADDR(bias, g_bias); SYMADDR(phi, g_phi);
    SYMADDR(attnb, g_attn);SYMADDR(xmid, g_xmid); SYMADDR(x2, g_x2);
    SYMADDR(qkcb, g_qkc);  SYMADDR(vcb, g_vc);    SYMADDR(q2c, g_q2c);
    SYMADDR(Scp, g_Sc);    SYMADDR(Pcp, g_Pc);    SYMADDR(chb, g_ch);

    // transposed bf16 weights (wT[n][k])
    k_convt<<<dim3(32, 32, 6), dim3(32, 8)>>>(attn_qk_w, attn_v_w, attn_out_w,
                                              ch_qk_w, ch_v_w, ch_out_w, wbf);
    __nv_bfloat16* wqk = wbf;
    __nv_bfloat16* wv  = wbf + 1 * 1048576;
    __nv_bfloat16* wo  = wbf + 2 * 1048576;
    __nv_bfloat16* wcq = wbf + 3 * 1048576;
    __nv_bfloat16* wcv = wbf + 4 * 1048576;
    __nv_bfloat16* wco = wbf + 5 * 1048576;

    // ---- conditioning ----
    k_emb<<<(BB * HID + 255) / 256, 256>>>(t, emb);
    k_gemv_part<<<dim3(HID / 256, 32), 256>>>(emb, tc_w1, part, HID, HID);
    k_gemv_red<<<(2 * HID + 255) / 256, 256>>>(part, tc_b1, h1, HID, 1);
    k_gemv_part<<<dim3(HID / 256, 32), 256>>>(h1, tc_w2, part, HID, HID);
    k_gemv_red<<<(2 * HID + 255) / 256, 256>>>(part, tc_b2, h2, HID, 1);
    k_gemv_part<<<dim3(HID / 256, 32), 256>>>(h2, tc_wa, part, HID, HID);
    k_gemv_red<<<(2 * HID + 255) / 256, 256>>>(part, tc_ba, av, HID, 0);
    k_gemv_part<<<dim3(HID / 256, 32), 256>>>(h2, tc_wc, part, HID, HID);
    k_gemv_red<<<(2 * HID + 255) / 256, 256>>>(part, tc_bc, cv, HID, 0);

    // ---- token attention ----
    k_ln_mod<<<BN, 256>>>(x, x1, n1s, n1b, av);
    k_phi<<<BN, 256>>>(x1, doob_w, doob_b, phi);

    {   // qk = (x1 @ Wqk) * exp(a_lg)
        GemmF p = {};
        p.A = x1; p.B = wqk; p.C = qkb;
        p.epi = 0; p.e0 = av + 3072;
        rungemm_f2(p);
    }
    {   // v = x1 @ Wv
        GemmF p = {};
        p.A = x1; p.B = wv; p.C = vb;
        p.epi = 1;
        rungemm_f2(p);
    }
    k_bias<<<BB * HH * NN / 8, 256>>>(qkb, phi, bias);
    k_flash<<<dim3(1, 16, BB * HH), 256>>>(qkb, vb, bias, attnb);
    {   // x_mid = x + (attn @ Wo) * a_gate * gamma1
        GemmF p = {};
        p.A = attnb; p.B = wo; p.C = xmid;
        p.epi = 3; p.e0 = av + 2048; p.e1 = gamma1; p.e2 = x;
        rungemm_f2(p);
    }

    // ---- channel attention ----
    k_ln_mod<<<BN, 256>>>(xmid, x2, n2s, n2b, cv);
    {   // qkc = (x2 @ Wcq) * exp(c_lg)
        GemmF p = {};
        p.A = x2; p.B = wcq; p.C = qkcb;
        p.epi = 0; p.e0 = cv + 3072;
        rungemm_f2(p);
    }
    {   // vc = x2 @ Wcv
        GemmF p = {};
        p.A = x2; p.B = wcv; p.C = vcb;
        p.epi = 1;
        rungemm_f2(p);
    }
    k_q2c_part<<<dim3(BB * HCC, 16), 128>>>(qkcb, part);
    k_q2c_red<<<(BB * HCC * 128 + 255) / 256, 256>>>(part, q2c);
    {   // Sc[z] = (2 Qc Qc^T - q2c_m - q2c_n)/sqrt(N) * tau[hc]
        GemmP p = {};
        p.A = qkcb; p.sAm = 1; p.sAk = DD; p.bAb = (long)NN * DD; p.bAh = 128;
        p.B = qkcb; p.sBk = DD; p.sBn = 1; p.bBb = (long)NN * DD; p.bBh = 128;
        p.M = 128; p.N = 128; p.K = NN; p.nh = HCC; p.nb = BB * HCC;
        p.C = Scp; p.sCm = 128; p.sCn = 1;
        p.bCb = (long)HCC * 128 * 128; p.bCh = 128 * 128;
        p.epi = 4; p.e0 = q2c; p.e1 = tau;
        p.f0 = 0.022097086912079608f;  // 1/sqrt(2048)
        rungemm(p);
    }
    k_softmax_ch<<<BB * HCC * 128, 128>>>(Scp, Pcp);
    {   // ch[b,n,hc*128+c] = sum_d Vc[n][d] * Pc^T[d][c]
        GemmP p = {};
        p.A = vcb; p.sAm = DD; p.sAk = 1; p.bAb = (long)NN * DD; p.bAh = 128;
        p.B = Pcp; p.sBk = 1; p.sBn = 128;
        p.bBb = (long)HCC * 128 * 128; p.bBh = 128 * 128;
        p.M = NN; p.N = 128; p.K = 128; p.nh = HCC; p.nb = BB * HCC;
        p.C = chb; p.sCm = DD; p.sCn = 1;
        p.bCb = (long)NN * DD; p.bCh = 128;
        p.epi = 1;
        rungemm(p);
    }
    {   // out = x_mid + (ch @ Wco) * c_gate * gamma2
        GemmF p = {};
        p.A = chb; p.B = wco; p.C = d_out;
        p.epi = 3; p.e0 = cv + 2048; p.e1 = gamma2; p.e2 = xmid;
        rungemm_f2(p);
    }
}

// round 5
// speedup vs baseline: 3.4172x; 1.1132x over previous
#include <cuda_runtime.h>
#include <cuda_bf16.h>
#include <math.h>
#include <stdint.h>

#define BB 2
#define NN 2048
#define DD 1024
#define HH 16
#define HCC 8
#define HID 4096
#define BN (BB*NN)

// ------------------------- scratch ----------------------------------------------
__device__ float g_emb[BB*HID];
__device__ float g_part[2*32*2*HID];
__device__ float g_h1[BB*HID];
__device__ float g_h2[BB*HID];
__device__ float g_av[BB*HID];
__device__ float g_cv[BB*HID];
__device__ __nv_bfloat16 g_wbf[6u*1048576u];   // transposed bf16 weights [n][k]
__device__ __nv_bfloat16 g_x1[BN*DD];
__device__ __nv_bfloat16 g_qk[BN*DD];
__device__ __nv_bfloat16 g_v[BN*DD];
__device__ float g_bias[BB*HH*NN];
__device__ float g_phi[BB*NN];
__device__ __nv_bfloat16 g_attn[BN*DD];
__device__ float g_xmid[BN*DD];
__device__ __nv_bfloat16 g_x2[BN*DD];
__device__ __nv_bfloat16 g_qkc[BN*DD];
__device__ __nv_bfloat16 g_vc[BN*DD];
__device__ float g_q2c[BB*HCC*128];
__device__ __nv_bfloat16 g_Pc[BB*HCC*128*128];
__device__ __nv_bfloat16 g_ch[BN*DD];

// ------------------------- helpers ---------------------------------------------
__device__ inline float blockRed(float v, int op) {
    __shared__ float sm[32];
    int lane = threadIdx.x & 31, w = threadIdx.x >> 5;
    #pragma unroll
    for (int o = 16; o; o >>= 1) {
        float t = __shfl_xor_sync(0xffffffffu, v, o);
        v = op ? fmaxf(v, t) : v + t;
    }
    if (lane == 0) sm[w] = v;
    __syncthreads();
    int nw = blockDim.x >> 5;
    if (w == 0) {
        v = (lane < nw) ? sm[lane] : (op ? -INFINITY : 0.f);
        #pragma unroll
        for (int o = 16; o; o >>= 1) {
            float t = __shfl_xor_sync(0xffffffffu, v, o);
            v = op ? fmaxf(v, t) : v + t;
        }
        if (lane == 0) sm[0] = v;
    }
    __syncthreads();
    float r = sm[0];
    __syncthreads();
    return r;
}

__device__ inline void mma16816(float* c, const uint32_t* a, const uint32_t* b) {
    asm volatile(
        "mma.sync.aligned.m16n8k16.row.col.f32.bf16.bf16.f32 "
        "{%0,%1,%2,%3}, {%4,%5,%6,%7}, {%8,%9}, {%0,%1,%2,%3};\n"
        : "+f"(c[0]), "+f"(c[1]), "+f"(c[2]), "+f"(c[3])
        : "r"(a[0]), "r"(a[1]), "r"(a[2]), "r"(a[3]), "r"(b[0]), "r"(b[1]));
}

__device__ inline uint32_t packbf(float a, float b) {
    __nv_bfloat162 t = __floats2bfloat162_rn(a, b);
    return *(uint32_t*)&t;
}

__device__ inline uint32_t smem_u32(const void* p) {
    uint32_t a;
    asm("{ .reg .u64 t; cvta.to.shared.u64 t, %1; cvt.u32.u64 %0, t; }" : "=r"(a) : "l"(p));
    return a;
}

__device__ inline void cp_async16(uint32_t saddr, const void* gaddr) {
    asm volatile("cp.async.cg.shared.global [%0], [%1], 16;" :: "r"(saddr), "l"(gaddr));
}

// ------------------------- small kernels ----------------------------------------
__global__ void k_emb(const float* __restrict__ t, float* __restrict__ emb) {
    int i = blockIdx.x * 256 + threadIdx.x;
    if (i >= BB * HID) return;
    int b = i / HID, j = i % HID;
    int jj = j & 2047;
    float f = expf(-9.210340371976184f * (float)jj / 2048.0f);
    float a = t[b] * f;
    emb[i] = (j < 2048) ? cosf(a) : sinf(a);
}

__global__ void k_gemv_part(const float* __restrict__ in, const float* __restrict__ W,
                            float* __restrict__ part) {
    int col = blockIdx.x * 256 + threadIdx.x;
    int k0 = blockIdx.y * (HID / 32);
    float a0 = 0.f, a1 = 0.f;
    #pragma unroll 8
    for (int k = k0; k < k0 + HID / 32; k++) {
        float w = W[(long)k * HID + col];
        a0 += in[k] * w;
        a1 += in[HID + k] * w;
    }
    part[((long)blockIdx.y * 2 + 0) * HID + col] = a0;
    part[((long)blockIdx.y * 2 + 1) * HID + col] = a1;
}

__global__ void k_gemv_red(const float* __restrict__ part, const float* __restrict__ bias,
                           float* __restrict__ out, int act) {
    int i = blockIdx.x * 256 + threadIdx.x;
    if (i >= 2 * HID) return;
    int b = i / HID, col = i % HID;
    float s = bias[col];
    #pragma unroll 8
    for (int p = 0; p < 32; p++) s += part[((long)p * 2 + b) * HID + col];
    if (act) s = s / (1.f + expf(-s));
    out[(long)b * HID + col] = s;
}

// fused pair: z=0 -> W0, z=1 -> W1
__global__ void k_gemv_part2(const float* __restrict__ in, const float* __restrict__ W0,
                             const float* __restrict__ W1, float* __restrict__ part) {
    const float* W = blockIdx.z ? W1 : W0;
    float* pp = part + (long)blockIdx.z * 32 * 2 * HID;
    int col = blockIdx.x * 256 + threadIdx.x;
    int k0 = blockIdx.y * (HID / 32);
    float a0 = 0.f, a1 = 0.f;
    #pragma unroll 8
    for (int k = k0; k < k0 + HID / 32; k++) {
        float w = W[(long)k * HID + col];
        a0 += in[k] * w;
        a1 += in[HID + k] * w;
    }
    pp[((long)blockIdx.y * 2 + 0) * HID + col] = a0;
    pp[((long)blockIdx.y * 2 + 1) * HID + col] = a1;
}

__global__ void k_gemv_red2(const float* __restrict__ part, const float* __restrict__ b0,
                            const float* __restrict__ b1, float* __restrict__ o0,
                            float* __restrict__ o1) {
    int i = blockIdx.x * 256 + threadIdx.x;
    if (i >= 2 * HID) return;
    const float* pp = part + (long)blockIdx.z * 32 * 2 * HID;
    const float* bias = blockIdx.z ? b1 : b0;
    float* out = blockIdx.z ? o1 : o0;
    int b = i / HID, col = i % HID;
    float s = bias[col];
    #pragma unroll 8
    for (int p = 0; p < 32; p++) s += pp[((long)p * 2 + b) * HID + col];
    out[(long)b * HID + col] = s;
}

// tiled transpose + fp32->bf16
__global__ void k_convt(const float* __restrict__ w0, const float* __restrict__ w1,
                        const float* __restrict__ w2, const float* __restrict__ w3,
                        const float* __restrict__ w4, const float* __restrict__ w5,
                        __nv_bfloat16* __restrict__ out) {
    __shared__ float t[32][33];
    const float* s = w0;
    int z = blockIdx.z;
    if (z == 1) s = w1; else if (z == 2) s = w2; else if (z == 3) s = w3;
    else if (z == 4) s = w4; else if (z == 5) s = w5;
    int x = blockIdx.x * 32 + threadIdx.x;
    int y0 = blockIdx.y * 32;
    #pragma unroll
    for (int j = 0; j < 32; j += 8)
        t[threadIdx.y + j][threadIdx.x] = s[(long)(y0 + threadIdx.y + j) * DD + x];
    __syncthreads();
    __nv_bfloat16* d = out + (long)z * 1048576;
    int n = blockIdx.x * 32 + threadIdx.y;
    int k = y0 + threadIdx.x;
    #pragma unroll
    for (int j = 0; j < 32; j += 8)
        d[(long)(n + j) * DD + k] = __float2bfloat16(t[threadIdx.x][threadIdx.y + j]);
}

// LayerNorm + modulate -> bf16, optional fused phi (doob) reduction
__global__ void k_ln_mod(const float* __restrict__ xin, __nv_bfloat16* __restrict__ xout,
                         const float* __restrict__ sc, const float* __restrict__ bi,
                         const float* __restrict__ mod, const float* __restrict__ dw,
                         const float* __restrict__ db, float* __restrict__ phi) {
    int r = blockIdx.x;
    int b = r >> 11;
    const float* xr = xin + (long)r * DD;
    int tid = threadIdx.x;
    float v[4];
    float s = 0.f;
    #pragma unroll
    for (int i = 0; i < 4; i++) { v[i] = xr[tid + i * 256]; s += v[i]; }
    s = blockRed(s, 0);
    float mu = s * (1.0f / DD);
    float vs = 0.f;
    #pragma unroll
    for (int i = 0; i < 4; i++) { float d = v[i] - mu; vs += d * d; }
    vs = blockRed(vs, 0);
    float rstd = rsqrtf(vs * (1.0f / DD) + 1e-6f);
    float ps = 0.f;
    #pragma unroll
    for (int i = 0; i < 4; i++) {
        int j = tid + i * 256;
        float y = (v[i] - mu) * rstd * sc[j] + bi[j];
        float m = y * (1.f + mod[(long)b * HID + 1024 + j]) + mod[(long)b * HID + j];
        xout[(long)r * DD + j] = __float2bfloat16(m);
        if (dw) ps += m * dw[j];
    }
    if (dw) {
        ps = blockRed(ps, 0);
        if (tid == 0) phi[r] = ps + db[0];
    }
}

// bias[z*NN+n] = phi[b,n] - |q[b,h,n,:]|^2
__global__ void k_bias(const __nv_bfloat16* __restrict__ qk, const float* __restrict__ phi,
                       float* __restrict__ bias) {
    int gid = blockIdx.x * 8 + (threadIdx.x >> 5);
    int lane = threadIdx.x & 31;
    int n = gid & 2047;
    int h = (gid >> 11) & 15;
    int b = gid >> 15;
    const __nv_bfloat16* p = qk + ((long)b * NN + n) * DD + h * 64;
    float f0 = __bfloat162float(p[lane]);
    float f1 = __bfloat162float(p[lane + 32]);
    float s = f0 * f0 + f1 * f1;
    #pragma unroll
    for (int o = 16; o; o >>= 1) s += __shfl_xor_sync(0xffffffffu, s, o);
    if (lane == 0) bias[gid] = phi[b * NN + n] - s;
}

// q2c two-pass (coalesced); part reuses g_part
__global__ void k_q2c_part(const __nv_bfloat16* __restrict__ qkc, float* __restrict__ part) {
    int z = blockIdx.x, ns = blockIdx.y, d = threadIdx.x;
    int b = z >> 3, hc = z & 7;
    const __nv_bfloat16* base = qkc + ((long)b * NN + ns * 128) * DD + hc * 128 + d;
    float s = 0.f;
    #pragma unroll 4
    for (int n = 0; n < 128; n++) {
        float q = __bfloat162float(base[(long)n * DD]);
        s += q * q;
    }
    part[(z * 16 + ns) * 128 + d] = s;
}

__global__ void k_q2c_red(const float* __restrict__ part, float* __restrict__ q2c) {
    int i = blockIdx.x * 256 + threadIdx.x;
    if (i >= BB * HCC * 128) return;
    int z = i >> 7, d = i & 127;
    float s = 0.f;
    #pragma unroll
    for (int j = 0; j < 16; j++) s += part[(z * 16 + j) * 128 + d];
    q2c[i] = s;
}

// ------------------------- channel S + softmax (one CTA per (b,hc)) -------------
// P[c][d] = softmax_d( (2*sum_n q[n,c]q[n,d] - q2c_d) * tau[hc]/sqrt(N) )
#define CHS_SMEM (128*72*2 + 128*129*4 + 512)
__global__ void __launch_bounds__(256) k_chS(
    const __nv_bfloat16* __restrict__ qkc, const float* __restrict__ q2c,
    const float* __restrict__ tau, __nv_bfloat16* __restrict__ Pc)
{
    extern __shared__ __align__(16) char smraw[];
    __nv_bfloat16* sQt = (__nv_bfloat16*)smraw;                 // [128][72]
    float* sS = (float*)(smraw + 128 * 72 * 2);                 // [128][129]
    float* sq2 = (float*)(smraw + 128 * 72 * 2 + 128 * 129 * 4);// [128]
    int z = blockIdx.x;
    int b = z >> 3, hc = z & 7;
    int tid = threadIdx.x, wid = tid >> 5, lane = tid & 31;
    int g = lane >> 2, tg = lane & 3;
    int wm = (wid & 1) * 64, wn = (wid >> 1) * 32;
    const __nv_bfloat16* base = qkc + (long)b * NN * DD + hc * 128;
    float ft = 0.022097086912079608f * tau[hc];

    if (tid < 128) sq2[tid] = q2c[z * 128 + tid];

    float acc[4][4][4];
    #pragma unroll
    for (int i = 0; i < 4; i++)
        #pragma unroll
        for (int j = 0; j < 4; j++)
            #pragma unroll
            for (int q = 0; q < 4; q++) acc[i][j][q] = 0.f;

    uint4 rq[4];
    #pragma unroll
    for (int t = 0; t < 4; t++) {
        int idx = tid + t * 256;
        int tok = idx >> 4, dg = (idx & 15) * 8;
        rq[t] = *(const uint4*)(base + (long)tok * DD + dg);
    }

    for (int ch = 0; ch < 32; ch++) {
        #pragma unroll
        for (int t = 0; t < 4; t++) {
            int idx = tid + t * 256;
            int tok = idx >> 4, dg = (idx & 15) * 8;
            union { uint4 u; __nv_bfloat16 hh[8]; } tv;
            tv.u = rq[t];
            #pragma unroll
            for (int j = 0; j < 8; j++) sQt[(dg + j) * 72 + tok] = tv.hh[j];
        }
        __syncthreads();
        if (ch < 31) {
            #pragma unroll
            for (int t = 0; t < 4; t++) {
                int idx = tid + t * 256;
                int tok = idx >> 4, dg = (idx & 15) * 8;
                rq[t] = *(const uint4*)(base + (long)((ch + 1) * 64 + tok) * DD + dg);
            }
        }
        #pragma unroll
        for (int kk = 0; kk < 64; kk += 16) {
            uint32_t ar[4][4], br[4][2];
            #pragma unroll
            for (int mi = 0; mi < 4; mi++) {
                int r = wm + mi * 16;
                ar[mi][0] = *(const uint32_t*)&sQt[(r + g) * 72 + kk + 2 * tg];
                ar[mi][1] = *(const uint32_t*)&sQt[(r + g + 8) * 72 + kk + 2 * tg];
                ar[mi][2] = *(const uint32_t*)&sQt[(r + g) * 72 + kk + 2 * tg + 8];
                ar[mi][3] = *(const uint32_t*)&sQt[(r + g + 8) * 72 + kk + 2 * tg + 8];
            }
            #pragma unroll
            for (int ni = 0; ni < 4; ni++) {
                int c = wn + ni * 8 + g;
                br[ni][0] = *(const uint32_t*)&sQt[c * 72 + kk + 2 * tg];
                br[ni][1] = *(const uint32_t*)&sQt[c * 72 + kk + 2 * tg + 8];
            }
            #pragma unroll
            for (int mi = 0; mi < 4; mi++)
                #pragma unroll
                for (int ni = 0; ni < 4; ni++)
                    mma16816(acc[mi][ni], ar[mi], br[ni]);
        }
        __syncthreads();
    }

    // dump S to smem
    #pragma unroll
    for (int mi = 0; mi < 4; mi++)
        #pragma unroll
        for (int ni = 0; ni < 4; ni++) {
            int r0 = wm + mi * 16 + g, c0 = wn + ni * 8 + 2 * tg;
            sS[r0 * 129 + c0] = acc[mi][ni][0];
            sS[r0 * 129 + c0 + 1] = acc[mi][ni][1];
            sS[(r0 + 8) * 129 + c0] = acc[mi][ni][2];
            sS[(r0 + 8) * 129 + c0 + 1] = acc[mi][ni][3];
        }
    __syncthreads();

    // row softmax: warp per row
    for (int it = 0; it < 16; it++) {
        int r = it * 8 + wid;
        float v[4], mx = -1e30f;
        #pragma unroll
        for (int j = 0; j < 4; j++) {
            int c = lane + 32 * j;
            v[j] = (2.f * sS[r * 129 + c] - sq2[c]) * ft;
            mx = fmaxf(mx, v[j]);
        }
        #pragma unroll
        for (int o = 16; o; o >>= 1) mx = fmaxf(mx, __shfl_xor_sync(0xffffffffu, mx, o));
        float sum = 0.f;
        #pragma unroll
        for (int j = 0; j < 4; j++) { v[j] = __expf(v[j] - mx); sum += v[j]; }
        #pragma unroll
        for (int o = 16; o; o >>= 1) sum += __shfl_xor_sync(0xffffffffu, sum, o);
        float inv = 1.f / sum;
        #pragma unroll
        for (int j = 0; j < 4; j++)
            Pc[(long)z * 16384 + r * 128 + lane + 32 * j] = __float2bfloat16(v[j] * inv);
    }
}

// ------------------------- flash token attention --------------------------------
__global__ void __launch_bounds__(256) k_flash(
    const __nv_bfloat16* __restrict__ qk,
    const __nv_bfloat16* __restrict__ v,
    const float* __restrict__ bias,
    __nv_bfloat16* __restrict__ out)
{
    int z = blockIdx.z;
    int b = z >> 4, h = z & 15;
    const __nv_bfloat16* Qb = qk + ((long)b * NN) * DD + h * 64;
    const __nv_bfloat16* Vb = v  + ((long)b * NN) * DD + h * 64;
    const float* biasb = bias + (long)z * NN;
    int m0 = blockIdx.y * 128;

    __shared__ __nv_bfloat16 sK[128][72];
    __shared__ __nv_bfloat16 sV[64][130];
    __shared__ float sBias[128];

    int tid = threadIdx.x, wid = tid >> 5, lane = tid & 31;
    int g = lane >> 2, tg = lane & 3;
    int mrow = m0 + wid * 16;

    uint32_t qf[4][4];
    #pragma unroll
    for (int kp = 0; kp < 4; kp++) {
        const __nv_bfloat16* q0 = Qb + (long)(mrow + g) * DD + kp * 16 + 2 * tg;
        const __nv_bfloat16* q1 = Qb + (long)(mrow + g + 8) * DD + kp * 16 + 2 * tg;
        qf[kp][0] = *(const uint32_t*)q0;
        qf[kp][1] = *(const uint32_t*)q1;
        qf[kp][2] = *(const uint32_t*)(q0 + 8);
        qf[kp][3] = *(const uint32_t*)(q1 + 8);
    }

    uint4 rk[4], rv[4];
    #pragma unroll
    for (int t = 0; t < 4; t++) {
        int i = tid + t * 256;
        int tok = i >> 3, dv = (i & 7) * 8;
        rk[t] = *(const uint4*)(Qb + (long)tok * DD + dv);
        rv[t] = *(const uint4*)(Vb + (long)tok * DD + dv);
    }

    float m_run[2] = {-1e30f, -1e30f};
    float l_run[2] = {0.f, 0.f};
    float o[8][4];
    #pragma unroll
    for (int i = 0; i < 8; i++)
        #pragma unroll
        for (int j = 0; j < 4; j++) o[i][j] = 0.f;

    for (int n0 = 0; n0 < NN; n0 += 128) {
        #pragma unroll
        for (int t = 0; t < 4; t++) {
            int i = tid + t * 256;
            int tok = i >> 3, dv = (i & 7) * 8;
            *(uint4*)&sK[tok][dv] = rk[t];
            union { uint4 u; __nv_bfloat16 hh[8]; } tv;
            tv.u = rv[t];
            #pragma unroll
            for (int j = 0; j < 8; j++) sV[dv + j][tok] = tv.hh[j];
        }
        if (tid < 128) sBias[tid] = biasb[n0 + tid];
        __syncthreads();

        if (n0 + 128 < NN) {
            #pragma unroll
            for (int t = 0; t < 4; t++) {
                int i = tid + t * 256;
                int tok = i >> 3, dv = (i & 7) * 8;
                rk[t] = *(const uint4*)(Qb + (long)(n0 + 128 + tok) * DD + dv);
                rv[t] = *(const uint4*)(Vb + (long)(n0 + 128 + tok) * DD + dv);
            }
        }

        float s[16][4];
        #pragma unroll
        for (int ni = 0; ni < 16; ni++) {
            s[ni][0] = s[ni][1] = s[ni][2] = s[ni][3] = 0.f;
            #pragma unroll
            for (int kp = 0; kp < 4; kp++) {
                uint32_t bv[2];
                int c = ni * 8 + g;
                bv[0] = *(const uint32_t*)&sK[c][kp * 16 + 2 * tg];
                bv[1] = *(const uint32_t*)&sK[c][kp * 16 + 2 * tg + 8];
                mma16816(s[ni], qf[kp], bv);
            }
        }

        float mx[2] = {-1e30f, -1e30f};
        #pragma unroll
        for (int ni = 0; ni < 16; ni++) {
            #pragma unroll
            for (int j = 0; j < 4; j++) {
                float bval = sBias[ni * 8 + 2 * tg + (j & 1)];
                s[ni][j] = 2.f * s[ni][j] + bval;
                mx[j >> 1] = fmaxf(mx[j >> 1], s[ni][j]);
            }
        }
        #pragma unroll
        for (int r = 0; r < 2; r++) {
            mx[r] = fmaxf(mx[r], __shfl_xor_sync(0xffffffffu, mx[r], 1));
            mx[r] = fmaxf(mx[r], __shfl_xor_sync(0xffffffffu, mx[r], 2));
        }
        float m_new[2], alpha[2], rs[2] = {0.f, 0.f};
        #pragma unroll
        for (int r = 0; r < 2; r++) {
            m_new[r] = fmaxf(m_run[r], mx[r]);
            alpha[r] = __expf(m_run[r] - m_new[r]);
            m_run[r] = m_new[r];
        }
        #pragma unroll
        for (int ni = 0; ni < 16; ni++) {
            #pragma unroll
            for (int j = 0; j < 4; j++) {
                float p = __expf(s[ni][j] - m_new[j >> 1]);
                s[ni][j] = p;
                rs[j >> 1] += p;
            }
        }
        #pragma unroll
        for (int r = 0; r < 2; r++) {
            rs[r] += __shfl_xor_sync(0xffffffffu, rs[r], 1);
            rs[r] += __shfl_xor_sync(0xffffffffu, rs[r], 2);
            l_run[r] = l_run[r] * alpha[r] + rs[r];
        }
        #pragma unroll
        for (int di = 0; di < 8; di++) {
            o[di][0] *= alpha[0]; o[di][1] *= alpha[0];
            o[di][2] *= alpha[1]; o[di][3] *= alpha[1];
        }
        uint32_t pf[8][4];
        #pragma unroll
        for (int kp = 0; kp < 8; kp++) {
            pf[kp][0] = packbf(s[2 * kp][0], s[2 * kp][1]);
            pf[kp][1] = packbf(s[2 * kp][2], s[2 * kp][3]);
            pf[kp][2] = packbf(s[2 * kp + 1][0], s[2 * kp + 1][1]);
            pf[kp][3] = packbf(s[2 * kp + 1][2], s[2 * kp + 1][3]);
        }
        #pragma unroll
        for (int kp = 0; kp < 8; kp++) {
            #pragma unroll
            for (int di = 0; di < 8; di++) {
                uint32_t bv[2];
                int c = di * 8 + g;
                bv[0] = *(const uint32_t*)&sV[c][kp * 16 + 2 * tg];
                bv[1] = *(const uint32_t*)&sV[c][kp * 16 + 2 * tg + 8];
                mma16816(o[di], pf[kp], bv);
            }
        }
        __syncthreads();
    }

    float inv0 = 1.f / l_run[0], inv1 = 1.f / l_run[1];
    long r0 = (long)(b * NN + mrow + g) * DD + h * 64;
    long r1 = (long)(b * NN + mrow + g + 8) * DD + h * 64;
    #pragma unroll
    for (int di = 0; di < 8; di++) {
        int col = di * 8 + 2 * tg;
        __nv_bfloat162 v0 = __floats2bfloat162_rn(o[di][0] * inv0, o[di][1] * inv0);
        __nv_bfloat162 v1 = __floats2bfloat162_rn(o[di][2] * inv1, o[di][3] * inv1);
        *(__nv_bfloat162*)&out[r0 + col] = v0;
        *(__nv_bfloat162*)&out[r1 + col] = v1;
    }
}

// ------------------------- generalized fast GEMM (cp.async, k-contig both) ------
struct GemmF {
    const __nv_bfloat16 *A, *B;
    long sA, sB, sC;           // row strides
    long bBz;                  // per-z B offset (zmode 1)
    int K;                     // multiple of 64
    void *C, *C2;
    int epi;                   // 0 exp bf16, 1 bf16, 3 residual fp32, 5 pair
    int zmode;                 // 0: z unused; 1: channel decode (b,hc)
    const float *e0, *e1, *e2;
};

#define GF_SMEM (4*128*72*2)

__global__ void __launch_bounds__(256) k_gemmF(GemmF p) {
    extern __shared__ __nv_bfloat16 smdyn[];
    __nv_bfloat16* sA[2] = { smdyn, smdyn + 128 * 72 };
    __nv_bfloat16* sB[2] = { smdyn + 2 * 128 * 72, smdyn + 3 * 128 * 72 };
    int tid = threadIdx.x, wid = tid >> 5, lane = tid & 31;
    int g = lane >> 2, tg = lane & 3;
    int bm = blockIdx.y * 128, bn = blockIdx.x * 128;
    int wm = (wid & 1) * 64, wn = (wid >> 1) * 32;

    long offA = 0, offB = 0, offC = 0;
    if (p.zmode == 1) {
        int z = blockIdx.z, b = z >> 3, hc = z & 7;
        offA = (long)b * NN * DD + hc * 128;
        offB = (long)z * p.bBz;
        offC = offA;
    }
    const __nv_bfloat16* Ag = p.A + offA + (long)bm * p.sA;
    const __nv_bfloat16* Bg = p.B + offB + (long)bn * p.sB;

    float acc[4][4][4];
    #pragma unroll
    for (int i = 0; i < 4; i++)
        #pragma unroll
        for (int j = 0; j < 4; j++)
            #pragma unroll
            for (int q = 0; q < 4; q++) acc[i][j][q] = 0.f;

    #pragma unroll
    for (int t = 0; t < 4; t++) {
        int idx = tid + t * 256;
        int row = idx >> 3, v = (idx & 7) * 8;
        cp_async16(smem_u32(&sA[0][row * 72 + v]), Ag + (long)row * p.sA + v);
        cp_async16(smem_u32(&sB[0][row * 72 + v]), Bg + (long)row * p.sB + v);
    }
    asm volatile("cp.async.commit_group;");

    int nc = p.K >> 6;
    #pragma unroll 1
    for (int c = 0; c < nc; c++) {
        int s = c & 1;
        if (c < nc - 1) {
            int s2 = s ^ 1, k0 = (c + 1) * 64;
            #pragma unroll
            for (int t = 0; t < 4; t++) {
                int idx = tid + t * 256;
                int row = idx >> 3, v = (idx & 7) * 8;
                cp_async16(smem_u32(&sA[s2][row * 72 + v]), Ag + (long)row * p.sA + k0 + v);
                cp_async16(smem_u32(&sB[s2][row * 72 + v]), Bg + (long)row * p.sB + k0 + v);
            }
            asm volatile("cp.async.commit_group;");
            asm volatile("cp.async.wait_group 1;");
        } else {
            asm volatile("cp.async.wait_group 0;");
        }
        __syncthreads();

        const __nv_bfloat16* cA = sA[s];
        const __nv_bfloat16* cB = sB[s];
        #pragma unroll
        for (int kk = 0; kk < 64; kk += 16) {
            uint32_t ar[4][4], br[4][2];
            #pragma unroll
            for (int mi = 0; mi < 4; mi++) {
                int r = wm + mi * 16;
                ar[mi][0] = *(const uint32_t*)&cA[(r + g) * 72 + kk + 2 * tg];
                ar[mi][1] = *(const uint32_t*)&cA[(r + g + 8) * 72 + kk + 2 * tg];
                ar[mi][2] = *(const uint32_t*)&cA[(r + g) * 72 + kk + 2 * tg + 8];
                ar[mi][3] = *(const uint32_t*)&cA[(r + g + 8) * 72 + kk + 2 * tg + 8];
            }
            #pragma unroll
            for (int ni = 0; ni < 4; ni++) {
                int cc = wn + ni * 8 + g;
                br[ni][0] = *(const uint32_t*)&cB[cc * 72 + kk + 2 * tg];
                br[ni][1] = *(const uint32_t*)&cB[cc * 72 + kk + 2 * tg + 8];
            }
            #pragma unroll
            for (int mi = 0; mi < 4; mi++)
                #pragma unroll
                for (int ni = 0; ni < 4; ni++)
                    mma16816(acc[mi][ni], ar[mi], br[ni]);
        }
        __syncthreads();
    }

    #pragma unroll
    for (int mi = 0; mi < 4; mi++)
        #pragma unroll
        for (int ni = 0; ni < 4; ni++) {
            #pragma unroll
            for (int hh = 0; hh < 2; hh++) {
                int r = bm + wm + mi * 16 + g + hh * 8;
                int cc = bn + wn + ni * 8 + 2 * tg;
                float a0 = acc[mi][ni][2 * hh], a1 = acc[mi][ni][2 * hh + 1];
                int bb = r >> 11;
                if (p.epi == 0) {
                    float s0 = expf(p.e0[(long)bb * HID + cc]);
                    float s1 = expf(p.e0[(long)bb * HID + cc + 1]);
                    *(__nv_bfloat162*)&((__nv_bfloat16*)p.C)[offC + (long)r * p.sC + cc] =
                        __floats2bfloat162_rn(a0 * s0, a1 * s1);
                } else if (p.epi == 1) {
                    *(__nv_bfloat162*)&((__nv_bfloat16*)p.C)[offC + (long)r * p.sC + cc] =
                        __floats2bfloat162_rn(a0, a1);
                } else if (p.epi == 3) {
                    float* dst = (float*)p.C + (long)r * p.sC + cc;
                    const float* res = p.e2 + (long)r * DD + cc;
                    dst[0] = res[0] + a0 * p.e0[(long)bb * HID + cc] * p.e1[cc];
                    dst[1] = res[1] + a1 * p.e0[(long)bb * HID + cc + 1] * p.e1[cc + 1];
                } else {   // 5: pair — col<1024 -> C with exp scale, else C2 plain
                    if (cc < 1024) {
                        float s0 = expf(p.e0[(long)bb * HID + cc]);
                        float s1 = expf(p.e0[(long)bb * HID + cc + 1]);
                        *(__nv_bfloat162*)&((__nv_bfloat16*)p.C)[(long)r * DD + cc] =
                            __floats2bfloat162_rn(a0 * s0, a1 * s1);
                    } else {
                        *(__nv_bfloat162*)&((__nv_bfloat16*)p.C2)[(long)r * DD + cc - 1024] =
                            __floats2bfloat162_rn(a0, a1);
                    }
                }
            }
        }
}

static inline void rungemmF(const GemmF& p, int gx, int gy, int gz) {
    static int inited = 0;
    if (!inited) {
        cudaFuncSetAttribute(k_gemmF, cudaFuncAttributeMaxDynamicSharedMemorySize, GF_SMEM);
        cudaFuncSetAttribute(k_chS, cudaFuncAttributeMaxDynamicSharedMemorySize, CHS_SMEM);
        inited = 1;
    }
    k_gemmF<<<dim3(gx, gy, gz), 256, GF_SMEM>>>(p);
}

#define SYMADDR(v, s) do { void* _p = nullptr; cudaGetSymbolAddress(&_p, s); v = (decltype(v))_p; } while (0)

// ------------------------- launch ----------------------------------------------
extern "C" void kernel_launch(void* const* d_in, const int* in_sizes, int n_in,
                              void* d_out, int out_size) {
    const float* x        = (const float*)d_in[0];
    const float* t        = (const float*)d_in[1];
    const float* n1s      = (const float*)d_in[2];
    const float* n1b      = (const float*)d_in[3];
    const float* n2s      = (const float*)d_in[4];
    const float* n2b      = (const float*)d_in[5];
    const float* tc_w1    = (const float*)d_in[6];
    const float* tc_b1    = (const float*)d_in[7];
    const float* tc_w2    = (const float*)d_in[8];
    const float* tc_b2    = (const float*)d_in[9];
    const float* tc_wa    = (const float*)d_in[10];
    const float* tc_ba    = (const float*)d_in[11];
    const float* tc_wc    = (const float*)d_in[12];
    const float* tc_bc    = (const float*)d_in[13];
    const float* attn_qk_w = (const float*)d_in[14];
    const float* attn_v_w  = (const float*)d_in[15];
    const float* attn_out_w= (const float*)d_in[16];
    const float* doob_w   = (const float*)d_in[17];
    const float* doob_b   = (const float*)d_in[18];
    const float* ch_qk_w  = (const float*)d_in[19];
    const float* ch_v_w   = (const float*)d_in[20];
    const float* ch_out_w = (const float*)d_in[21];
    const float* tau      = (const float*)d_in[22];
    const float* gamma1   = (const float*)d_in[23];
    const float* gamma2   = (const float*)d_in[24];

    float *emb, *part, *h1, *h2, *av, *cv, *bias, *phi, *xmid, *q2c;
    __nv_bfloat16 *wbf, *x1, *qkb, *vb, *attnb, *x2, *qkcb, *vcb, *Pcp, *chb;
    SYMADDR(emb, g_emb);   SYMADDR(part, g_part); SYMADDR(h1, g_h1);  SYMADDR(h2, g_h2);
    SYMADDR(av, g_av);     SYMADDR(cv, g_cv);     SYMADDR(wbf, g_wbf);
    SYMADDR(x1, g_x1);     SYMADDR(qkb, g_qk);    SYMADDR(vb, g_v);
    SYMADDR(bias, g_bias); SYMADDR(phi, g_phi);
    SYMADDR(attnb, g_attn);SYMADDR(xmid, g_xmid); SYMADDR(x2, g_x2);
    SYMADDR(qkcb, g_qkc);  SYMADDR(vcb, g_vc);    SYMADDR(q2c, g_q2c);
    SYMADDR(Pcp, g_Pc);    SYMADDR(chb, g_ch);

    k_convt<<<dim3(32, 32, 6), dim3(32, 8)>>>(attn_qk_w, attn_v_w, attn_out_w,
                                              ch_qk_w, ch_v_w, ch_out_w, wbf);
    __nv_bfloat16* wqkv = wbf;                  // wqk|wv adjacent (N=2048)
    __nv_bfloat16* wo   = wbf + 2 * 1048576;
    __nv_bfloat16* wcqv = wbf + 3 * 1048576;    // wcq|wcv adjacent
    __nv_bfloat16* wco  = wbf + 5 * 1048576;

    // ---- conditioning ----
    k_emb<<<(BB * HID + 255) / 256, 256>>>(t, emb);
    k_gemv_part<<<dim3(HID / 256, 32), 256>>>(emb, tc_w1, part);
    k_gemv_red<<<(2 * HID + 255) / 256, 256>>>(part, tc_b1, h1, 1);
    k_gemv_part<<<dim3(HID / 256, 32), 256>>>(h1, tc_w2, part);
    k_gemv_red<<<(2 * HID + 255) / 256, 256>>>(part, tc_b2, h2, 1);
    k_gemv_part2<<<dim3(HID / 256, 32, 2), 256>>>(h2, tc_wa, tc_wc, part);
    k_gemv_red2<<<dim3((2 * HID + 255) / 256, 1, 2), 256>>>(part, tc_ba, tc_bc, av, cv);

    // ---- token attention ----
    k_ln_mod<<<BN, 256>>>(x, x1, n1s, n1b, av, doob_w, doob_b, phi);
    {   // fused: qk = (x1@Wqk)*exp(a_lg) | v = x1@Wv
        GemmF p = {};
        p.A = x1; p.sA = DD; p.B = wqkv; p.sB = DD; p.K = DD;
        p.C = qkb; p.C2 = vb; p.sC = DD;
        p.epi = 5; p.e0 = av + 3072;
        rungemmF(p, 16, 32, 1);
    }
    k_bias<<<BB * HH * NN / 8, 256>>>(qkb, phi, bias);
    k_flash<<<dim3(1, 16, BB * HH), 256>>>(qkb, vb, bias, attnb);
    {   // x_mid = x + (attn @ Wo) * a_gate * gamma1
        GemmF p = {};
        p.A = attnb; p.sA = DD; p.B = wo; p.sB = DD; p.K = DD;
        p.C = xmid; p.sC = DD;
        p.epi = 3; p.e0 = av + 2048; p.e1 = gamma1; p.e2 = x;
        rungemmF(p, 8, 32, 1);
    }

    // ---- channel attention ----
    k_ln_mod<<<BN, 256>>>(xmid, x2, n2s, n2b, cv, nullptr, nullptr, nullptr);
    {   // fused: qkc | vc
        GemmF p = {};
        p.A = x2; p.sA = DD; p.B = wcqv; p.sB = DD; p.K = DD;
        p.C = qkcb; p.C2 = vcb; p.sC = DD;
        p.epi = 5; p.e0 = cv + 3072;
        rungemmF(p, 16, 32, 1);
    }
    k_q2c_part<<<dim3(BB * HCC, 16), 128>>>(qkcb, part);
    k_q2c_red<<<(BB * HCC * 128 + 255) / 256, 256>>>(part, q2c);
    k_chS<<<BB * HCC, 256, CHS_SMEM>>>(qkcb, q2c, tau, Pcp);
    {   // ch[n][c] = sum_d Vc[n][d] * P[c][d]   (batched z = b*8+hc)
        GemmF p = {};
        p.A = vcb; p.sA = DD; p.B = Pcp; p.sB = 128; p.bBz = 128 * 128; p.K = 128;
        p.C = chb; p.sC = DD;
        p.epi = 1; p.zmode = 1;
        rungemmF(p, 1, 16, BB * HCC);
    }
    {   // out = x_mid + (ch @ Wco) * c_gate * gamma2
        GemmF p = {};
        p.A = chb; p.sA = DD; p.B = wco; p.sB = DD; p.K = DD;
        p.C = d_out; p.sC = DD;
        p.epi = 3; p.e0 = cv + 2048; p.e1 = gamma2; p.e2 = xmid;
        rungemmF(p, 8, 32, 1);
    }
}

// round 6
// speedup vs baseline: 3.5343x; 1.0343x over previous
#include <cuda_runtime.h>
#include <cuda_bf16.h>
#include <math.h>
#include <stdint.h>

#define BB 2
#define NN 2048
#define DD 1024
#define HH 16
#define HCC 8
#define HID 4096
#define BN (BB*NN)

// ------------------------- scratch ----------------------------------------------
__device__ float g_emb[BB*HID];
__device__ float g_p1[32*2*HID];
__device__ float g_p2[32*2*HID];
__device__ float g_p3[2*32*2*HID];
__device__ float g_av[BB*HID];
__device__ float g_cv[BB*HID];
__device__ __nv_bfloat16 g_wbf[6u*1048576u];   // transposed bf16 weights [n][k]
__device__ __nv_bfloat16 g_x1[BN*DD];
__device__ __nv_bfloat16 g_qk[BN*DD];
__device__ __nv_bfloat16 g_v[BN*DD];
__device__ float g_bias[BB*HH*NN];
__device__ float g_phi[BB*NN];
__device__ __nv_bfloat16 g_attn[BN*DD];
__device__ float g_xmid[BN*DD];
__device__ __nv_bfloat16 g_x2[BN*DD];
__device__ __nv_bfloat16 g_qkc[BN*DD];
__device__ __nv_bfloat16 g_vc[BN*DD];
__device__ __nv_bfloat16 g_Pc[BB*HCC*128*128];
__device__ __nv_bfloat16 g_ch[BN*DD];

// ------------------------- helpers ---------------------------------------------
__device__ inline float blockRed(float v, int op) {
    __shared__ float sm[32];
    int lane = threadIdx.x & 31, w = threadIdx.x >> 5;
    #pragma unroll
    for (int o = 16; o; o >>= 1) {
        float t = __shfl_xor_sync(0xffffffffu, v, o);
        v = op ? fmaxf(v, t) : v + t;
    }
    if (lane == 0) sm[w] = v;
    __syncthreads();
    int nw = blockDim.x >> 5;
    if (w == 0) {
        v = (lane < nw) ? sm[lane] : (op ? -INFINITY : 0.f);
        #pragma unroll
        for (int o = 16; o; o >>= 1) {
            float t = __shfl_xor_sync(0xffffffffu, v, o);
            v = op ? fmaxf(v, t) : v + t;
        }
        if (lane == 0) sm[0] = v;
    }
    __syncthreads();
    float r = sm[0];
    __syncthreads();
    return r;
}

__device__ inline void mma16816(float* c, const uint32_t* a, const uint32_t* b) {
    asm volatile(
        "mma.sync.aligned.m16n8k16.row.col.f32.bf16.bf16.f32 "
        "{%0,%1,%2,%3}, {%4,%5,%6,%7}, {%8,%9}, {%0,%1,%2,%3};\n"
        : "+f"(c[0]), "+f"(c[1]), "+f"(c[2]), "+f"(c[3])
        : "r"(a[0]), "r"(a[1]), "r"(a[2]), "r"(a[3]), "r"(b[0]), "r"(b[1]));
}

__device__ inline uint32_t packbf(float a, float b) {
    __nv_bfloat162 t = __floats2bfloat162_rn(a, b);
    return *(uint32_t*)&t;
}

__device__ inline uint32_t smem_u32(const void* p) {
    uint32_t a;
    asm("{ .reg .u64 t; cvta.to.shared.u64 t, %1; cvt.u32.u64 %0, t; }" : "=r"(a) : "l"(p));
    return a;
}

__device__ inline void cp_async16(uint32_t saddr, const void* gaddr) {
    asm volatile("cp.async.cg.shared.global [%0], [%1], 16;" :: "r"(saddr), "l"(gaddr));
}

// ------------------------- small kernels ----------------------------------------
__global__ void k_emb(const float* __restrict__ t, float* __restrict__ emb) {
    int i = blockIdx.x * 256 + threadIdx.x;
    if (i >= BB * HID) return;
    int b = i / HID, j = i % HID;
    int jj = j & 2047;
    float f = expf(-9.210340371976184f * (float)jj / 2048.0f);
    float a = t[b] * f;
    emb[i] = (j < 2048) ? cosf(a) : sinf(a);
}

// plain split-K GEMV partials (first layer; input already dense)
__global__ void k_gemv_part(const float* __restrict__ in, const float* __restrict__ W,
                            float* __restrict__ part) {
    int col = blockIdx.x * 256 + threadIdx.x;
    int k0 = blockIdx.y * 128;
    float a0 = 0.f, a1 = 0.f;
    #pragma unroll 8
    for (int k = k0; k < k0 + 128; k++) {
        float w = W[(long)k * HID + col];
        a0 += in[k] * w;
        a1 += in[HID + k] * w;
    }
    part[((long)blockIdx.y * 2 + 0) * HID + col] = a0;
    part[((long)blockIdx.y * 2 + 1) * HID + col] = a1;
}

// fused: reduce prev partials (+bias, silu) for this k-slice, then partial GEMV.
// blockIdx.z selects W0/W1 (output offset z*32*2*HID).
__global__ void k_gemv_step(const float* __restrict__ prevPart,
                            const float* __restrict__ prevBias,
                            const float* __restrict__ W0, const float* __restrict__ W1,
                            float* __restrict__ outPart) {
    __shared__ float in_s[2][128];
    const float* W = blockIdx.z ? W1 : W0;
    float* op = outPart + (long)blockIdx.z * 32 * 2 * HID;
    int tid = threadIdx.x;
    int k0 = blockIdx.y * 128;
    {
        int b = tid >> 7, kk = tid & 127, k = k0 + kk;
        float s = prevBias[k];
        #pragma unroll 8
        for (int p2 = 0; p2 < 32; p2++) s += prevPart[((long)p2 * 2 + b) * HID + k];
        s = s / (1.f + __expf(-s));   // silu
        in_s[b][kk] = s;
    }
    __syncthreads();
    int col = blockIdx.x * 256 + tid;
    float a0 = 0.f, a1 = 0.f;
    #pragma unroll 8
    for (int kk = 0; kk < 128; kk++) {
        float w = W[(long)(k0 + kk) * HID + col];
        a0 += in_s[0][kk] * w;
        a1 += in_s[1][kk] * w;
    }
    op[((long)blockIdx.y * 2 + 0) * HID + col] = a0;
    op[((long)blockIdx.y * 2 + 1) * HID + col] = a1;
}

__global__ void k_gemv_red2(const float* __restrict__ part, const float* __restrict__ b0,
                            const float* __restrict__ b1, float* __restrict__ o0,
                            float* __restrict__ o1) {
    int i = blockIdx.x * 256 + threadIdx.x;
    if (i >= 2 * HID) return;
    const float* pp = part + (long)blockIdx.z * 32 * 2 * HID;
    const float* bias = blockIdx.z ? b1 : b0;
    float* out = blockIdx.z ? o1 : o0;
    int b = i / HID, col = i % HID;
    float s = bias[col];
    #pragma unroll 8
    for (int p = 0; p < 32; p++) s += pp[((long)p * 2 + b) * HID + col];
    out[(long)b * HID + col] = s;
}

// tiled transpose + fp32->bf16
__global__ void k_convt(const float* __restrict__ w0, const float* __restrict__ w1,
                        const float* __restrict__ w2, const float* __restrict__ w3,
                        const float* __restrict__ w4, const float* __restrict__ w5,
                        __nv_bfloat16* __restrict__ out) {
    __shared__ float t[32][33];
    const float* s = w0;
    int z = blockIdx.z;
    if (z == 1) s = w1; else if (z == 2) s = w2; else if (z == 3) s = w3;
    else if (z == 4) s = w4; else if (z == 5) s = w5;
    int x = blockIdx.x * 32 + threadIdx.x;
    int y0 = blockIdx.y * 32;
    #pragma unroll
    for (int j = 0; j < 32; j += 8)
        t[threadIdx.y + j][threadIdx.x] = s[(long)(y0 + threadIdx.y + j) * DD + x];
    __syncthreads();
    __nv_bfloat16* d = out + (long)z * 1048576;
    int n = blockIdx.x * 32 + threadIdx.y;
    int k = y0 + threadIdx.x;
    #pragma unroll
    for (int j = 0; j < 32; j += 8)
        d[(long)(n + j) * DD + k] = __float2bfloat16(t[threadIdx.x][threadIdx.y + j]);
}

// LayerNorm + modulate -> bf16, optional fused phi (doob) reduction
__global__ void k_ln_mod(const float* __restrict__ xin, __nv_bfloat16* __restrict__ xout,
                         const float* __restrict__ sc, const float* __restrict__ bi,
                         const float* __restrict__ mod, const float* __restrict__ dw,
                         const float* __restrict__ db, float* __restrict__ phi) {
    int r = blockIdx.x;
    int b = r >> 11;
    const float* xr = xin + (long)r * DD;
    int tid = threadIdx.x;
    float v[4];
    float s = 0.f;
    #pragma unroll
    for (int i = 0; i < 4; i++) { v[i] = xr[tid + i * 256]; s += v[i]; }
    s = blockRed(s, 0);
    float mu = s * (1.0f / DD);
    float vs = 0.f;
    #pragma unroll
    for (int i = 0; i < 4; i++) { float d = v[i] - mu; vs += d * d; }
    vs = blockRed(vs, 0);
    float rstd = rsqrtf(vs * (1.0f / DD) + 1e-6f);
    float ps = 0.f;
    #pragma unroll
    for (int i = 0; i < 4; i++) {
        int j = tid + i * 256;
        float y = (v[i] - mu) * rstd * sc[j] + bi[j];
        float m = y * (1.f + mod[(long)b * HID + 1024 + j]) + mod[(long)b * HID + j];
        xout[(long)r * DD + j] = __float2bfloat16(m);
        if (dw) ps += m * dw[j];
    }
    if (dw) {
        ps = blockRed(ps, 0);
        if (tid == 0) phi[r] = ps + db[0];
    }
}

// bias[z*NN+n] = phi[b,n] - |q[b,h,n,:]|^2
__global__ void k_bias(const __nv_bfloat16* __restrict__ qk, const float* __restrict__ phi,
                       float* __restrict__ bias) {
    int gid = blockIdx.x * 8 + (threadIdx.x >> 5);
    int lane = threadIdx.x & 31;
    int n = gid & 2047;
    int h = (gid >> 11) & 15;
    int b = gid >> 15;
    const __nv_bfloat16* p = qk + ((long)b * NN + n) * DD + h * 64;
    float f0 = __bfloat162float(p[lane]);
    float f1 = __bfloat162float(p[lane + 32]);
    float s = f0 * f0 + f1 * f1;
    #pragma unroll
    for (int o = 16; o; o >>= 1) s += __shfl_xor_sync(0xffffffffu, s, o);
    if (lane == 0) bias[gid] = phi[b * NN + n] - s;
}

// ------------------------- channel S + softmax (one CTA per (b,hc)) -------------
// q2c comes from diag(S): q2c[d] = S[d][d]
#define CHS_SMEM (128*72*2 + 128*129*4 + 512)
__global__ void __launch_bounds__(256) k_chS(
    const __nv_bfloat16* __restrict__ qkc,
    const float* __restrict__ tau, __nv_bfloat16* __restrict__ Pc)
{
    extern __shared__ __align__(16) char smraw[];
    __nv_bfloat16* sQt = (__nv_bfloat16*)smraw;                 // [128][72]
    float* sS = (float*)(smraw + 128 * 72 * 2);                 // [128][129]
    float* sq2 = (float*)(smraw + 128 * 72 * 2 + 128 * 129 * 4);// [128]
    int z = blockIdx.x;
    int b = z >> 3, hc = z & 7;
    int tid = threadIdx.x, wid = tid >> 5, lane = tid & 31;
    int g = lane >> 2, tg = lane & 3;
    int wm = (wid & 1) * 64, wn = (wid >> 1) * 32;
    const __nv_bfloat16* base = qkc + (long)b * NN * DD + hc * 128;
    float ft = 0.022097086912079608f * tau[hc];

    float acc[4][4][4];
    #pragma unroll
    for (int i = 0; i < 4; i++)
        #pragma unroll
        for (int j = 0; j < 4; j++)
            #pragma unroll
            for (int q = 0; q < 4; q++) acc[i][j][q] = 0.f;

    uint4 rq[4];
    #pragma unroll
    for (int t = 0; t < 4; t++) {
        int idx = tid + t * 256;
        int tok = idx >> 4, dg = (idx & 15) * 8;
        rq[t] = *(const uint4*)(base + (long)tok * DD + dg);
    }

    for (int ch = 0; ch < 32; ch++) {
        #pragma unroll
        for (int t = 0; t < 4; t++) {
            int idx = tid + t * 256;
            int tok = idx >> 4, dg = (idx & 15) * 8;
            union { uint4 u; __nv_bfloat16 hh[8]; } tv;
            tv.u = rq[t];
            #pragma unroll
            for (int j = 0; j < 8; j++) sQt[(dg + j) * 72 + tok] = tv.hh[j];
        }
        __syncthreads();
        if (ch < 31) {
            #pragma unroll
            for (int t = 0; t < 4; t++) {
                int idx = tid + t * 256;
                int tok = idx >> 4, dg = (idx & 15) * 8;
                rq[t] = *(const uint4*)(base + (long)((ch + 1) * 64 + tok) * DD + dg);
            }
        }
        #pragma unroll
        for (int kk = 0; kk < 64; kk += 16) {
            uint32_t ar[4][4], br[4][2];
            #pragma unroll
            for (int mi = 0; mi < 4; mi++) {
                int r = wm + mi * 16;
                ar[mi][0] = *(const uint32_t*)&sQt[(r + g) * 72 + kk + 2 * tg];
                ar[mi][1] = *(const uint32_t*)&sQt[(r + g + 8) * 72 + kk + 2 * tg];
                ar[mi][2] = *(const uint32_t*)&sQt[(r + g) * 72 + kk + 2 * tg + 8];
                ar[mi][3] = *(const uint32_t*)&sQt[(r + g + 8) * 72 + kk + 2 * tg + 8];
            }
            #pragma unroll
            for (int ni = 0; ni < 4; ni++) {
                int c = wn + ni * 8 + g;
                br[ni][0] = *(const uint32_t*)&sQt[c * 72 + kk + 2 * tg];
                br[ni][1] = *(const uint32_t*)&sQt[c * 72 + kk + 2 * tg + 8];
            }
            #pragma unroll
            for (int mi = 0; mi < 4; mi++)
                #pragma unroll
                for (int ni = 0; ni < 4; ni++)
                    mma16816(acc[mi][ni], ar[mi], br[ni]);
        }
        __syncthreads();
    }

    // dump S to smem
    #pragma unroll
    for (int mi = 0; mi < 4; mi++)
        #pragma unroll
        for (int ni = 0; ni < 4; ni++) {
            int r0 = wm + mi * 16 + g, c0 = wn + ni * 8 + 2 * tg;
            sS[r0 * 129 + c0] = acc[mi][ni][0];
            sS[r0 * 129 + c0 + 1] = acc[mi][ni][1];
            sS[(r0 + 8) * 129 + c0] = acc[mi][ni][2];
            sS[(r0 + 8) * 129 + c0 + 1] = acc[mi][ni][3];
        }
    __syncthreads();
    if (tid < 128) sq2[tid] = sS[tid * 129 + tid];   // q2c = diag(S)
    __syncthreads();

    // row softmax: warp per row
    for (int it = 0; it < 16; it++) {
        int r = it * 8 + wid;
        float v[4], mx = -1e30f;
        #pragma unroll
        for (int j = 0; j < 4; j++) {
            int c = lane + 32 * j;
            v[j] = (2.f * sS[r * 129 + c] - sq2[c]) * ft;
            mx = fmaxf(mx, v[j]);
        }
        #pragma unroll
        for (int o = 16; o; o >>= 1) mx = fmaxf(mx, __shfl_xor_sync(0xffffffffu, mx, o));
        float sum = 0.f;
        #pragma unroll
        for (int j = 0; j < 4; j++) { v[j] = __expf(v[j] - mx); sum += v[j]; }
        #pragma unroll
        for (int o = 16; o; o >>= 1) sum += __shfl_xor_sync(0xffffffffu, sum, o);
        float inv = 1.f / sum;
        #pragma unroll
        for (int j = 0; j < 4; j++)
            Pc[(long)z * 16384 + r * 128 + lane + 32 * j] = __float2bfloat16(v[j] * inv);
    }
}

// ------------------------- flash token attention --------------------------------
__global__ void __launch_bounds__(256) k_flash(
    const __nv_bfloat16* __restrict__ qk,
    const __nv_bfloat16* __restrict__ v,
    const float* __restrict__ bias,
    __nv_bfloat16* __restrict__ out)
{
    int z = blockIdx.z;
    int b = z >> 4, h = z & 15;
    const __nv_bfloat16* Qb = qk + ((long)b * NN) * DD + h * 64;
    const __nv_bfloat16* Vb = v  + ((long)b * NN) * DD + h * 64;
    const float* biasb = bias + (long)z * NN;
    int m0 = blockIdx.y * 128;

    __shared__ __nv_bfloat16 sK[128][72];
    __shared__ __nv_bfloat16 sV[64][130];
    __shared__ float sBias[128];

    int tid = threadIdx.x, wid = tid >> 5, lane = tid & 31;
    int g = lane >> 2, tg = lane & 3;
    int mrow = m0 + wid * 16;

    uint32_t qf[4][4];
    #pragma unroll
    for (int kp = 0; kp < 4; kp++) {
        const __nv_bfloat16* q0 = Qb + (long)(mrow + g) * DD + kp * 16 + 2 * tg;
        const __nv_bfloat16* q1 = Qb + (long)(mrow + g + 8) * DD + kp * 16 + 2 * tg;
        qf[kp][0] = *(const uint32_t*)q0;
        qf[kp][1] = *(const uint32_t*)q1;
        qf[kp][2] = *(const uint32_t*)(q0 + 8);
        qf[kp][3] = *(const uint32_t*)(q1 + 8);
    }

    uint4 rk[4], rv[4];
    #pragma unroll
    for (int t = 0; t < 4; t++) {
        int i = tid + t * 256;
        int tok = i >> 3, dv = (i & 7) * 8;
        rk[t] = *(const uint4*)(Qb + (long)tok * DD + dv);
        rv[t] = *(const uint4*)(Vb + (long)tok * DD + dv);
    }

    float m_run[2] = {-1e30f, -1e30f};
    float l_run[2] = {0.f, 0.f};
    float o[8][4];
    #pragma unroll
    for (int i = 0; i < 8; i++)
        #pragma unroll
        for (int j = 0; j < 4; j++) o[i][j] = 0.f;

    for (int n0 = 0; n0 < NN; n0 += 128) {
        #pragma unroll
        for (int t = 0; t < 4; t++) {
            int i = tid + t * 256;
            int tok = i >> 3, dv = (i & 7) * 8;
            *(uint4*)&sK[tok][dv] = rk[t];
            union { uint4 u; __nv_bfloat16 hh[8]; } tv;
            tv.u = rv[t];
            #pragma unroll
            for (int j = 0; j < 8; j++) sV[dv + j][tok] = tv.hh[j];
        }
        if (tid < 128) sBias[tid] = biasb[n0 + tid];
        __syncthreads();

        if (n0 + 128 < NN) {
            #pragma unroll
            for (int t = 0; t < 4; t++) {
                int i = tid + t * 256;
                int tok = i >> 3, dv = (i & 7) * 8;
                rk[t] = *(const uint4*)(Qb + (long)(n0 + 128 + tok) * DD + dv);
                rv[t] = *(const uint4*)(Vb + (long)(n0 + 128 + tok) * DD + dv);
            }
        }

        float s[16][4];
        #pragma unroll
        for (int ni = 0; ni < 16; ni++) {
            s[ni][0] = s[ni][1] = s[ni][2] = s[ni][3] = 0.f;
            #pragma unroll
            for (int kp = 0; kp < 4; kp++) {
                uint32_t bv[2];
                int c = ni * 8 + g;
                bv[0] = *(const uint32_t*)&sK[c][kp * 16 + 2 * tg];
                bv[1] = *(const uint32_t*)&sK[c][kp * 16 + 2 * tg + 8];
                mma16816(s[ni], qf[kp], bv);
            }
        }

        float mx[2] = {-1e30f, -1e30f};
        #pragma unroll
        for (int ni = 0; ni < 16; ni++) {
            #pragma unroll
            for (int j = 0; j < 4; j++) {
                float bval = sBias[ni * 8 + 2 * tg + (j & 1)];
                s[ni][j] = 2.f * s[ni][j] + bval;
                mx[j >> 1] = fmaxf(mx[j >> 1], s[ni][j]);
            }
        }
        #pragma unroll
        for (int r = 0; r < 2; r++) {
            mx[r] = fmaxf(mx[r], __shfl_xor_sync(0xffffffffu, mx[r], 1));
            mx[r] = fmaxf(mx[r], __shfl_xor_sync(0xffffffffu, mx[r], 2));
        }
        float m_new[2], alpha[2], rs[2] = {0.f, 0.f};
        #pragma unroll
        for (int r = 0; r < 2; r++) {
            m_new[r] = fmaxf(m_run[r], mx[r]);
            alpha[r] = __expf(m_run[r] - m_new[r]);
            m_run[r] = m_new[r];
        }
        #pragma unroll
        for (int ni = 0; ni < 16; ni++) {
            #pragma unroll
            for (int j = 0; j < 4; j++) {
                float p = __expf(s[ni][j] - m_new[j >> 1]);
                s[ni][j] = p;
                rs[j >> 1] += p;
            }
        }
        #pragma unroll
        for (int r = 0; r < 2; r++) {
            rs[r] += __shfl_xor_sync(0xffffffffu, rs[r], 1);
            rs[r] += __shfl_xor_sync(0xffffffffu, rs[r], 2);
            l_run[r] = l_run[r] * alpha[r] + rs[r];
        }
        #pragma unroll
        for (int di = 0; di < 8; di++) {
            o[di][0] *= alpha[0]; o[di][1] *= alpha[0];
            o[di][2] *= alpha[1]; o[di][3] *= alpha[1];
        }
        uint32_t pf[8][4];
        #pragma unroll
        for (int kp = 0; kp < 8; kp++) {
            pf[kp][0] = packbf(s[2 * kp][0], s[2 * kp][1]);
            pf[kp][1] = packbf(s[2 * kp][2], s[2 * kp][3]);
            pf[kp][2] = packbf(s[2 * kp + 1][0], s[2 * kp + 1][1]);
            pf[kp][3] = packbf(s[2 * kp + 1][2], s[2 * kp + 1][3]);
        }
        #pragma unroll
        for (int kp = 0; kp < 8; kp++) {
            #pragma unroll
            for (int di = 0; di < 8; di++) {
                uint32_t bv[2];
                int c = di * 8 + g;
                bv[0] = *(const uint32_t*)&sV[c][kp * 16 + 2 * tg];
                bv[1] = *(const uint32_t*)&sV[c][kp * 16 + 2 * tg + 8];
                mma16816(o[di], pf[kp], bv);
            }
        }
        __syncthreads();
    }

    float inv0 = 1.f / l_run[0], inv1 = 1.f / l_run[1];
    long r0 = (long)(b * NN + mrow + g) * DD + h * 64;
    long r1 = (long)(b * NN + mrow + g + 8) * DD + h * 64;
    #pragma unroll
    for (int di = 0; di < 8; di++) {
        int col = di * 8 + 2 * tg;
        __nv_bfloat162 v0 = __floats2bfloat162_rn(o[di][0] * inv0, o[di][1] * inv0);
        __nv_bfloat162 v1 = __floats2bfloat162_rn(o[di][2] * inv1, o[di][3] * inv1);
        *(__nv_bfloat162*)&out[r0 + col] = v0;
        *(__nv_bfloat162*)&out[r1 + col] = v1;
    }
}

// ------------------------- generalized fast GEMM (cp.async, k-contig both) ------
struct GemmF {
    const __nv_bfloat16 *A, *B;
    long sA, sB, sC;
    long bBz;
    int K;
    void *C, *C2;
    int epi;                   // 0 exp bf16, 1 bf16, 3 residual fp32, 5 pair
    int zmode;
    const float *e0, *e1, *e2;
};

#define GF_SMEM (4*128*72*2)

__global__ void __launch_bounds__(256, 2) k_gemmF(GemmF p) {
    extern __shared__ __nv_bfloat16 smdyn[];
    __nv_bfloat16* sA[2] = { smdyn, smdyn + 128 * 72 };
    __nv_bfloat16* sB[2] = { smdyn + 2 * 128 * 72, smdyn + 3 * 128 * 72 };
    int tid = threadIdx.x, wid = tid >> 5, lane = tid & 31;
    int g = lane >> 2, tg = lane & 3;
    int bm = blockIdx.y * 128, bn = blockIdx.x * 128;
    int wm = (wid & 1) * 64, wn = (wid >> 1) * 32;

    long offA = 0, offB = 0, offC = 0;
    if (p.zmode == 1) {
        int z = blockIdx.z, b = z >> 3, hc = z & 7;
        offA = (long)b * NN * DD + hc * 128;
        offB = (long)z * p.bBz;
        offC = offA;
    }
    const __nv_bfloat16* Ag = p.A + offA + (long)bm * p.sA;
    const __nv_bfloat16* Bg = p.B + offB + (long)bn * p.sB;

    float acc[4][4][4];
    #pragma unroll
    for (int i = 0; i < 4; i++)
        #pragma unroll
        for (int j = 0; j < 4; j++)
            #pragma unroll
            for (int q = 0; q < 4; q++) acc[i][j][q] = 0.f;

    #pragma unroll
    for (int t = 0; t < 4; t++) {
        int idx = tid + t * 256;
        int row = idx >> 3, v = (idx & 7) * 8;
        cp_async16(smem_u32(&sA[0][row * 72 + v]), Ag + (long)row * p.sA + v);
        cp_async16(smem_u32(&sB[0][row * 72 + v]), Bg + (long)row * p.sB + v);
    }
    asm volatile("cp.async.commit_group;");

    int nc = p.K >> 6;
    #pragma unroll 1
    for (int c = 0; c < nc; c++) {
        int s = c & 1;
        if (c < nc - 1) {
            int s2 = s ^ 1, k0 = (c + 1) * 64;
            #pragma unroll
            for (int t = 0; t < 4; t++) {
                int idx = tid + t * 256;
                int row = idx >> 3, v = (idx & 7) * 8;
                cp_async16(smem_u32(&sA[s2][row * 72 + v]), Ag + (long)row * p.sA + k0 + v);
                cp_async16(smem_u32(&sB[s2][row * 72 + v]), Bg + (long)row * p.sB + k0 + v);
            }
            asm volatile("cp.async.commit_group;");
            asm volatile("cp.async.wait_group 1;");
        } else {
            asm volatile("cp.async.wait_group 0;");
        }
        __syncthreads();

        const __nv_bfloat16* cA = sA[s];
        const __nv_bfloat16* cB = sB[s];
        #pragma unroll
        for (int kk = 0; kk < 64; kk += 16) {
            uint32_t ar[4][4], br[4][2];
            #pragma unroll
            for (int mi = 0; mi < 4; mi++) {
                int r = wm + mi * 16;
                ar[mi][0] = *(const uint32_t*)&cA[(r + g) * 72 + kk + 2 * tg];
                ar[mi][1] = *(const uint32_t*)&cA[(r + g + 8) * 72 + kk + 2 * tg];
                ar[mi][2] = *(const uint32_t*)&cA[(r + g) * 72 + kk + 2 * tg + 8];
                ar[mi][3] = *(const uint32_t*)&cA[(r + g + 8) * 72 + kk + 2 * tg + 8];
            }
            #pragma unroll
            for (int ni = 0; ni < 4; ni++) {
                int cc = wn + ni * 8 + g;
                br[ni][0] = *(const uint32_t*)&cB[cc * 72 + kk + 2 * tg];
                br[ni][1] = *(const uint32_t*)&cB[cc * 72 + kk + 2 * tg + 8];
            }
            #pragma unroll
            for (int mi = 0; mi < 4; mi++)
                #pragma unroll
                for (int ni = 0; ni < 4; ni++)
                    mma16816(acc[mi][ni], ar[mi], br[ni]);
        }
        __syncthreads();
    }

    #pragma unroll
    for (int mi = 0; mi < 4; mi++)
        #pragma unroll
        for (int ni = 0; ni < 4; ni++) {
            #pragma unroll
            for (int hh = 0; hh < 2; hh++) {
                int r = bm + wm + mi * 16 + g + hh * 8;
                int cc = bn + wn + ni * 8 + 2 * tg;
                float a0 = acc[mi][ni][2 * hh], a1 = acc[mi][ni][2 * hh + 1];
                int bb = r >> 11;
                if (p.epi == 0) {
                    float s0 = expf(p.e0[(long)bb * HID + cc]);
                    float s1 = expf(p.e0[(long)bb * HID + cc + 1]);
                    *(__nv_bfloat162*)&((__nv_bfloat16*)p.C)[offC + (long)r * p.sC + cc] =
                        __floats2bfloat162_rn(a0 * s0, a1 * s1);
                } else if (p.epi == 1) {
                    *(__nv_bfloat162*)&((__nv_bfloat16*)p.C)[offC + (long)r * p.sC + cc] =
                        __floats2bfloat162_rn(a0, a1);
                } else if (p.epi == 3) {
                    float* dst = (float*)p.C + (long)r * p.sC + cc;
                    const float* res = p.e2 + (long)r * DD + cc;
                    dst[0] = res[0] + a0 * p.e0[(long)bb * HID + cc] * p.e1[cc];
                    dst[1] = res[1] + a1 * p.e0[(long)bb * HID + cc + 1] * p.e1[cc + 1];
                } else {   // 5: pair
                    if (cc < 1024) {
                        float s0 = expf(p.e0[(long)bb * HID + cc]);
                        float s1 = expf(p.e0[(long)bb * HID + cc + 1]);
                        *(__nv_bfloat162*)&((__nv_bfloat16*)p.C)[(long)r * DD + cc] =
                            __floats2bfloat162_rn(a0 * s0, a1 * s1);
                    } else {
                        *(__nv_bfloat162*)&((__nv_bfloat16*)p.C2)[(long)r * DD + cc - 1024] =
                            __floats2bfloat162_rn(a0, a1);
                    }
                }
            }
        }
}

static inline void rungemmF(const GemmF& p, int gx, int gy, int gz) {
    static int inited = 0;
    if (!inited) {
        cudaFuncSetAttribute(k_gemmF, cudaFuncAttributeMaxDynamicSharedMemorySize, GF_SMEM);
        cudaFuncSetAttribute(k_chS, cudaFuncAttributeMaxDynamicSharedMemorySize, CHS_SMEM);
        inited = 1;
    }
    k_gemmF<<<dim3(gx, gy, gz), 256, GF_SMEM>>>(p);
}

#define SYMADDR(v, s) do { void* _p = nullptr; cudaGetSymbolAddress(&_p, s); v = (decltype(v))_p; } while (0)

// ------------------------- launch ----------------------------------------------
extern "C" void kernel_launch(void* const* d_in, const int* in_sizes, int n_in,
                              void* d_out, int out_size) {
    const float* x        = (const float*)d_in[0];
    const float* t        = (const float*)d_in[1];
    const float* n1s      = (const float*)d_in[2];
    const float* n1b      = (const float*)d_in[3];
    const float* n2s      = (const float*)d_in[4];
    const float* n2b      = (const float*)d_in[5];
    const float* tc_w1    = (const float*)d_in[6];
    const float* tc_b1    = (const float*)d_in[7];
    const float* tc_w2    = (const float*)d_in[8];
    const float* tc_b2    = (const float*)d_in[9];
    const float* tc_wa    = (const float*)d_in[10];
    const float* tc_ba    = (const float*)d_in[11];
    const float* tc_wc    = (const float*)d_in[12];
    const float* tc_bc    = (const float*)d_in[13];
    const float* attn_qk_w = (const float*)d_in[14];
    const float* attn_v_w  = (const float*)d_in[15];
    const float* attn_out_w= (const float*)d_in[16];
    const float* doob_w   = (const float*)d_in[17];
    const float* doob_b   = (const float*)d_in[18];
    const float* ch_qk_w  = (const float*)d_in[19];
    const float* ch_v_w   = (const float*)d_in[20];
    const float* ch_out_w = (const float*)d_in[21];
    const float* tau      = (const float*)d_in[22];
    const float* gamma1   = (const float*)d_in[23];
    const float* gamma2   = (const float*)d_in[24];

    float *emb, *p1, *p2, *p3, *av, *cv, *bias, *phi, *xmid;
    __nv_bfloat16 *wbf, *x1, *qkb, *vb, *attnb, *x2, *qkcb, *vcb, *Pcp, *chb;
    SYMADDR(emb, g_emb);   SYMADDR(p1, g_p1);     SYMADDR(p2, g_p2);  SYMADDR(p3, g_p3);
    SYMADDR(av, g_av);     SYMADDR(cv, g_cv);     SYMADDR(wbf, g_wbf);
    SYMADDR(x1, g_x1);     SYMADDR(qkb, g_qk);    SYMADDR(vb, g_v);
    SYMADDR(bias, g_bias); SYMADDR(phi, g_phi);
    SYMADDR(attnb, g_attn);SYMADDR(xmid, g_xmid); SYMADDR(x2, g_x2);
    SYMADDR(qkcb, g_qkc);  SYMADDR(vcb, g_vc);
    SYMADDR(Pcp, g_Pc);    SYMADDR(chb, g_ch);

    k_convt<<<dim3(32, 32, 6), dim3(32, 8)>>>(attn_qk_w, attn_v_w, attn_out_w,
                                              ch_qk_w, ch_v_w, ch_out_w, wbf);
    __nv_bfloat16* wqkv = wbf;
    __nv_bfloat16* wo   = wbf + 2 * 1048576;
    __nv_bfloat16* wcqv = wbf + 3 * 1048576;
    __nv_bfloat16* wco  = wbf + 5 * 1048576;

    // ---- conditioning (fused split-K chain) ----
    k_emb<<<(BB * HID + 255) / 256, 256>>>(t, emb);
    k_gemv_part<<<dim3(HID / 256, 32), 256>>>(emb, tc_w1, p1);
    k_gemv_step<<<dim3(HID / 256, 32, 1), 256>>>(p1, tc_b1, tc_w2, tc_w2, p2);
    k_gemv_step<<<dim3(HID / 256, 32, 2), 256>>>(p2, tc_b2, tc_wa, tc_wc, p3);
    k_gemv_red2<<<dim3((2 * HID + 255) / 256, 1, 2), 256>>>(p3, tc_ba, tc_bc, av, cv);

    // ---- token attention ----
    k_ln_mod<<<BN, 256>>>(x, x1, n1s, n1b, av, doob_w, doob_b, phi);
    {   // fused: qk = (x1@Wqk)*exp(a_lg) | v = x1@Wv
        GemmF p = {};
        p.A = x1; p.sA = DD; p.B = wqkv; p.sB = DD; p.K = DD;
        p.C = qkb; p.C2 = vb; p.sC = DD;
        p.epi = 5; p.e0 = av + 3072;
        rungemmF(p, 16, 32, 1);
    }
    k_bias<<<BB * HH * NN / 8, 256>>>(qkb, phi, bias);
    k_flash<<<dim3(1, 16, BB * HH), 256>>>(qkb, vb, bias, attnb);
    {   // x_mid = x + (attn @ Wo) * a_gate * gamma1
        GemmF p = {};
        p.A = attnb; p.sA = DD; p.B = wo; p.sB = DD; p.K = DD;
        p.C = xmid; p.sC = DD;
        p.epi = 3; p.e0 = av + 2048; p.e1 = gamma1; p.e2 = x;
        rungemmF(p, 8, 32, 1);
    }

    // ---- channel attention ----
    k_ln_mod<<<BN, 256>>>(xmid, x2, n2s, n2b, cv, nullptr, nullptr, nullptr);
    {   // fused: qkc | vc
        GemmF p = {};
        p.A = x2; p.sA = DD; p.B = wcqv; p.sB = DD; p.K = DD;
        p.C = qkcb; p.C2 = vcb; p.sC = DD;
        p.epi = 5; p.e0 = cv + 3072;
        rungemmF(p, 16, 32, 1);
    }
    k_chS<<<BB * HCC, 256, CHS_SMEM>>>(qkcb, tau, Pcp);
    {   // ch[n][c] = sum_d Vc[n][d] * P[c][d]   (batched z = b*8+hc)
        GemmF p = {};
        p.A = vcb; p.sA = DD; p.B = Pcp; p.sB = 128; p.bBz = 128 * 128; p.K = 128;
        p.C = chb; p.sC = DD;
        p.epi = 1; p.zmode = 1;
        rungemmF(p, 1, 16, BB * HCC);
    }
    {   // out = x_mid + (ch @ Wco) * c_gate * gamma2
        GemmF p = {};
        p.A = chb; p.sA = DD; p.B = wco; p.sB = DD; p.K = DD;
        p.C = d_out; p.sC = DD;
        p.epi = 3; p.e0 = cv + 2048; p.e1 = gamma2; p.e2 = xmid;
        rungemmF(p, 8, 32, 1);
    }
}

// round 7
// speedup vs baseline: 3.7664x; 1.0657x over previous
#include <cuda_runtime.h>
#include <cuda_bf16.h>
#include <math.h>
#include <stdint.h>

#define BB 2
#define NN 2048
#define DD 1024
#define HH 16
#define HCC 8
#define HID 4096
#define BN (BB*NN)

// ------------------------- scratch ----------------------------------------------
__device__ float g_emb[BB*HID];
__device__ float g_p1[32*2*HID];
__device__ float g_p2[32*2*HID];
__device__ float g_p3[2*32*2*HID];
__device__ float g_av[BB*HID];
__device__ float g_cv[BB*HID];
__device__ __nv_bfloat16 g_wbf[6u*1048576u];   // transposed bf16 weights [n][k]
__device__ __nv_bfloat16 g_x1[BN*DD];
__device__ __nv_bfloat16 g_qk[BN*DD];
__device__ __nv_bfloat16 g_v[BN*DD];
__device__ float g_bias[BB*HH*NN];
__device__ float g_phi[BB*NN];
__device__ __nv_bfloat16 g_attn[BN*DD];
__device__ float g_xmid[BN*DD];
__device__ __nv_bfloat16 g_x2[BN*DD];
__device__ __nv_bfloat16 g_qkc[BN*DD];
__device__ __nv_bfloat16 g_vc[BN*DD];
__device__ __nv_bfloat16 g_Pc[BB*HCC*128*128];
__device__ __nv_bfloat16 g_ch[BN*DD];

// ------------------------- helpers ---------------------------------------------
__device__ inline float blockRed(float v, int op) {
    __shared__ float sm[32];
    int lane = threadIdx.x & 31, w = threadIdx.x >> 5;
    #pragma unroll
    for (int o = 16; o; o >>= 1) {
        float t = __shfl_xor_sync(0xffffffffu, v, o);
        v = op ? fmaxf(v, t) : v + t;
    }
    if (lane == 0) sm[w] = v;
    __syncthreads();
    int nw = blockDim.x >> 5;
    if (w == 0) {
        v = (lane < nw) ? sm[lane] : (op ? -INFINITY : 0.f);
        #pragma unroll
        for (int o = 16; o; o >>= 1) {
            float t = __shfl_xor_sync(0xffffffffu, v, o);
            v = op ? fmaxf(v, t) : v + t;
        }
        if (lane == 0) sm[0] = v;
    }
    __syncthreads();
    float r = sm[0];
    __syncthreads();
    return r;
}

__device__ inline void mma16816(float* c, const uint32_t* a, const uint32_t* b) {
    asm volatile(
        "mma.sync.aligned.m16n8k16.row.col.f32.bf16.bf16.f32 "
        "{%0,%1,%2,%3}, {%4,%5,%6,%7}, {%8,%9}, {%0,%1,%2,%3};\n"
        : "+f"(c[0]), "+f"(c[1]), "+f"(c[2]), "+f"(c[3])
        : "r"(a[0]), "r"(a[1]), "r"(a[2]), "r"(a[3]), "r"(b[0]), "r"(b[1]));
}

__device__ inline void ldsm_x4(uint32_t* r, uint32_t saddr) {
    asm volatile("ldmatrix.sync.aligned.m8n8.x4.shared.b16 {%0,%1,%2,%3}, [%4];"
        : "=r"(r[0]), "=r"(r[1]), "=r"(r[2]), "=r"(r[3]) : "r"(saddr));
}

__device__ inline void ldsm_x4_t(uint32_t* r, uint32_t saddr) {
    asm volatile("ldmatrix.sync.aligned.m8n8.x4.trans.shared.b16 {%0,%1,%2,%3}, [%4];"
        : "=r"(r[0]), "=r"(r[1]), "=r"(r[2]), "=r"(r[3]) : "r"(saddr));
}

__device__ inline uint32_t packbf(float a, float b) {
    __nv_bfloat162 t = __floats2bfloat162_rn(a, b);
    return *(uint32_t*)&t;
}

__device__ inline uint32_t smem_u32(const void* p) {
    uint32_t a;
    asm("{ .reg .u64 t; cvta.to.shared.u64 t, %1; cvt.u32.u64 %0, t; }" : "=r"(a) : "l"(p));
    return a;
}

__device__ inline void cp_async16(uint32_t saddr, const void* gaddr) {
    asm volatile("cp.async.cg.shared.global [%0], [%1], 16;" :: "r"(saddr), "l"(gaddr));
}

// ------------------------- small kernels ----------------------------------------
__global__ void k_emb(const float* __restrict__ t, float* __restrict__ emb) {
    int i = blockIdx.x * 256 + threadIdx.x;
    if (i >= BB * HID) return;
    int b = i / HID, j = i % HID;
    int jj = j & 2047;
    float f = expf(-9.210340371976184f * (float)jj / 2048.0f);
    float a = t[b] * f;
    emb[i] = (j < 2048) ? cosf(a) : sinf(a);
}

// split-K GEMV partials, 4 cols/thread, float4 weight loads
__global__ void k_gemv_part(const float* __restrict__ in, const float* __restrict__ W,
                            float* __restrict__ part) {
    int col = blockIdx.x * 1024 + threadIdx.x * 4;
    int k0 = blockIdx.y * 128;
    float4 a0 = {0,0,0,0}, a1 = {0,0,0,0};
    #pragma unroll 4
    for (int k = k0; k < k0 + 128; k++) {
        float4 w = *(const float4*)&W[(long)k * HID + col];
        float i0 = in[k], i1 = in[HID + k];
        a0.x += i0 * w.x; a0.y += i0 * w.y; a0.z += i0 * w.z; a0.w += i0 * w.w;
        a1.x += i1 * w.x; a1.y += i1 * w.y; a1.z += i1 * w.z; a1.w += i1 * w.w;
    }
    *(float4*)&part[((long)blockIdx.y * 2 + 0) * HID + col] = a0;
    *(float4*)&part[((long)blockIdx.y * 2 + 1) * HID + col] = a1;
}

// fused: reduce prev partials (+bias, silu) for this k-slice, then partial GEMV
__global__ void k_gemv_step(const float* __restrict__ prevPart,
                            const float* __restrict__ prevBias,
                            const float* __restrict__ W0, const float* __restrict__ W1,
                            float* __restrict__ outPart) {
    __shared__ float in_s[2][128];
    const float* W = blockIdx.z ? W1 : W0;
    float* op = outPart + (long)blockIdx.z * 32 * 2 * HID;
    int tid = threadIdx.x;
    int k0 = blockIdx.y * 128;
    {
        int b = tid >> 7, kk = tid & 127, k = k0 + kk;
        float s = prevBias[k];
        #pragma unroll 8
        for (int p2 = 0; p2 < 32; p2++) s += prevPart[((long)p2 * 2 + b) * HID + k];
        in_s[b][kk] = s / (1.f + __expf(-s));
    }
    __syncthreads();
    int col = blockIdx.x * 1024 + tid * 4;
    float4 a0 = {0,0,0,0}, a1 = {0,0,0,0};
    #pragma unroll 4
    for (int kk = 0; kk < 128; kk++) {
        float4 w = *(const float4*)&W[(long)(k0 + kk) * HID + col];
        float i0 = in_s[0][kk], i1 = in_s[1][kk];
        a0.x += i0 * w.x; a0.y += i0 * w.y; a0.z += i0 * w.z; a0.w += i0 * w.w;
        a1.x += i1 * w.x; a1.y += i1 * w.y; a1.z += i1 * w.z; a1.w += i1 * w.w;
    }
    *(float4*)&op[((long)blockIdx.y * 2 + 0) * HID + col] = a0;
    *(float4*)&op[((long)blockIdx.y * 2 + 1) * HID + col] = a1;
}

__global__ void k_gemv_red2(const float* __restrict__ part, const float* __restrict__ b0,
                            const float* __restrict__ b1, float* __restrict__ o0,
                            float* __restrict__ o1) {
    int i = blockIdx.x * 256 + threadIdx.x;
    if (i >= 2 * HID) return;
    const float* pp = part + (long)blockIdx.z * 32 * 2 * HID;
    const float* bias = blockIdx.z ? b1 : b0;
    float* out = blockIdx.z ? o1 : o0;
    int b = i / HID, col = i % HID;
    float s = bias[col];
    #pragma unroll 8
    for (int p = 0; p < 32; p++) s += pp[((long)p * 2 + b) * HID + col];
    out[(long)b * HID + col] = s;
}

// tiled transpose + fp32->bf16
__global__ void k_convt(const float* __restrict__ w0, const float* __restrict__ w1,
                        const float* __restrict__ w2, const float* __restrict__ w3,
                        const float* __restrict__ w4, const float* __restrict__ w5,
                        __nv_bfloat16* __restrict__ out) {
    __shared__ float t[32][33];
    const float* s = w0;
    int z = blockIdx.z;
    if (z == 1) s = w1; else if (z == 2) s = w2; else if (z == 3) s = w3;
    else if (z == 4) s = w4; else if (z == 5) s = w5;
    int x = blockIdx.x * 32 + threadIdx.x;
    int y0 = blockIdx.y * 32;
    #pragma unroll
    for (int j = 0; j < 32; j += 8)
        t[threadIdx.y + j][threadIdx.x] = s[(long)(y0 + threadIdx.y + j) * DD + x];
    __syncthreads();
    __nv_bfloat16* d = out + (long)z * 1048576;
    int n = blockIdx.x * 32 + threadIdx.y;
    int k = y0 + threadIdx.x;
    #pragma unroll
    for (int j = 0; j < 32; j += 8)
        d[(long)(n + j) * DD + k] = __float2bfloat16(t[threadIdx.x][threadIdx.y + j]);
}

// LayerNorm + modulate -> bf16, optional fused phi (doob) reduction
__global__ void k_ln_mod(const float* __restrict__ xin, __nv_bfloat16* __restrict__ xout,
                         const float* __restrict__ sc, const float* __restrict__ bi,
                         const float* __restrict__ mod, const float* __restrict__ dw,
                         const float* __restrict__ db, float* __restrict__ phi) {
    int r = blockIdx.x;
    int b = r >> 11;
    const float* xr = xin + (long)r * DD;
    int tid = threadIdx.x;
    float v[4];
    float s = 0.f;
    #pragma unroll
    for (int i = 0; i < 4; i++) { v[i] = xr[tid + i * 256]; s += v[i]; }
    s = blockRed(s, 0);
    float mu = s * (1.0f / DD);
    float vs = 0.f;
    #pragma unroll
    for (int i = 0; i < 4; i++) { float d = v[i] - mu; vs += d * d; }
    vs = blockRed(vs, 0);
    float rstd = rsqrtf(vs * (1.0f / DD) + 1e-6f);
    float ps = 0.f;
    #pragma unroll
    for (int i = 0; i < 4; i++) {
        int j = tid + i * 256;
        float y = (v[i] - mu) * rstd * sc[j] + bi[j];
        float m = y * (1.f + mod[(long)b * HID + 1024 + j]) + mod[(long)b * HID + j];
        xout[(long)r * DD + j] = __float2bfloat16(m);
        if (dw) ps += m * dw[j];
    }
    if (dw) {
        ps = blockRed(ps, 0);
        if (tid == 0) phi[r] = ps + db[0];
    }
}

// bias[z*NN+n] = phi[b,n] - |q[b,h,n,:]|^2
__global__ void k_bias(const __nv_bfloat16* __restrict__ qk, const float* __restrict__ phi,
                       float* __restrict__ bias) {
    int gid = blockIdx.x * 8 + (threadIdx.x >> 5);
    int lane = threadIdx.x & 31;
    int n = gid & 2047;
    int h = (gid >> 11) & 15;
    int b = gid >> 15;
    const __nv_bfloat16* p = qk + ((long)b * NN + n) * DD + h * 64;
    float f0 = __bfloat162float(p[lane]);
    float f1 = __bfloat162float(p[lane + 32]);
    float s = f0 * f0 + f1 * f1;
    #pragma unroll
    for (int o = 16; o; o >>= 1) s += __shfl_xor_sync(0xffffffffu, s, o);
    if (lane == 0) bias[gid] = phi[b * NN + n] - s;
}

// ------------------------- channel S + softmax (one CTA per (b,hc)) -------------
#define CHS_SMEM (128*72*2 + 128*129*4 + 512)
__global__ void __launch_bounds__(256) k_chS(
    const __nv_bfloat16* __restrict__ qkc,
    const float* __restrict__ tau, __nv_bfloat16* __restrict__ Pc)
{
    extern __shared__ __align__(16) char smraw[];
    __nv_bfloat16* sQt = (__nv_bfloat16*)smraw;                 // [128][72]
    float* sS = (float*)(smraw + 128 * 72 * 2);                 // [128][129]
    float* sq2 = (float*)(smraw + 128 * 72 * 2 + 128 * 129 * 4);// [128]
    int z = blockIdx.x;
    int b = z >> 3, hc = z & 7;
    int tid = threadIdx.x, wid = tid >> 5, lane = tid & 31;
    int g = lane >> 2, tg = lane & 3;
    int wm = (wid & 1) * 64, wn = (wid >> 1) * 32;
    const __nv_bfloat16* base = qkc + (long)b * NN * DD + hc * 128;
    float ft = 0.022097086912079608f * tau[hc];

    int arow = lane & 15, ak = (lane & 16) ? 8 : 0;
    int brow = (lane & 7) + ((lane & 16) ? 8 : 0), bk = (lane & 8) ? 8 : 0;

    float acc[4][4][4];
    #pragma unroll
    for (int i = 0; i < 4; i++)
        #pragma unroll
        for (int j = 0; j < 4; j++)
            #pragma unroll
            for (int q = 0; q < 4; q++) acc[i][j][q] = 0.f;

    uint4 rq[4];
    #pragma unroll
    for (int t = 0; t < 4; t++) {
        int idx = tid + t * 256;
        int tok = idx >> 4, dg = (idx & 15) * 8;
        rq[t] = *(const uint4*)(base + (long)tok * DD + dg);
    }

    for (int ch = 0; ch < 32; ch++) {
        #pragma unroll
        for (int t = 0; t < 4; t++) {
            int idx = tid + t * 256;
            int tok = idx >> 4, dg = (idx & 15) * 8;
            union { uint4 u; __nv_bfloat16 hh[8]; } tv;
            tv.u = rq[t];
            #pragma unroll
            for (int j = 0; j < 8; j++) sQt[(dg + j) * 72 + tok] = tv.hh[j];
        }
        __syncthreads();
        if (ch < 31) {
            #pragma unroll
            for (int t = 0; t < 4; t++) {
                int idx = tid + t * 256;
                int tok = idx >> 4, dg = (idx & 15) * 8;
                rq[t] = *(const uint4*)(base + (long)((ch + 1) * 64 + tok) * DD + dg);
            }
        }
        #pragma unroll
        for (int kk = 0; kk < 64; kk += 16) {
            uint32_t ar[4][4], br[4][2];
            #pragma unroll
            for (int mi = 0; mi < 4; mi++)
                ldsm_x4(ar[mi], smem_u32(&sQt[(wm + mi * 16 + arow) * 72 + kk + ak]));
            #pragma unroll
            for (int np = 0; np < 2; np++) {
                uint32_t rr[4];
                ldsm_x4(rr, smem_u32(&sQt[(wn + np * 16 + brow) * 72 + kk + bk]));
                br[2 * np][0] = rr[0]; br[2 * np][1] = rr[1];
                br[2 * np + 1][0] = rr[2]; br[2 * np + 1][1] = rr[3];
            }
            #pragma unroll
            for (int mi = 0; mi < 4; mi++)
                #pragma unroll
                for (int ni = 0; ni < 4; ni++)
                    mma16816(acc[mi][ni], ar[mi], br[ni]);
        }
        __syncthreads();
    }

    #pragma unroll
    for (int mi = 0; mi < 4; mi++)
        #pragma unroll
        for (int ni = 0; ni < 4; ni++) {
            int r0 = wm + mi * 16 + g, c0 = wn + ni * 8 + 2 * tg;
            sS[r0 * 129 + c0] = acc[mi][ni][0];
            sS[r0 * 129 + c0 + 1] = acc[mi][ni][1];
            sS[(r0 + 8) * 129 + c0] = acc[mi][ni][2];
            sS[(r0 + 8) * 129 + c0 + 1] = acc[mi][ni][3];
        }
    __syncthreads();
    if (tid < 128) sq2[tid] = sS[tid * 129 + tid];
    __syncthreads();

    for (int it = 0; it < 16; it++) {
        int r = it * 8 + wid;
        float v[4], mx = -1e30f;
        #pragma unroll
        for (int j = 0; j < 4; j++) {
            int c = lane + 32 * j;
            v[j] = (2.f * sS[r * 129 + c] - sq2[c]) * ft;
            mx = fmaxf(mx, v[j]);
        }
        #pragma unroll
        for (int o = 16; o; o >>= 1) mx = fmaxf(mx, __shfl_xor_sync(0xffffffffu, mx, o));
        float sum = 0.f;
        #pragma unroll
        for (int j = 0; j < 4; j++) { v[j] = __expf(v[j] - mx); sum += v[j]; }
        #pragma unroll
        for (int o = 16; o; o >>= 1) sum += __shfl_xor_sync(0xffffffffu, sum, o);
        float inv = 1.f / sum;
        #pragma unroll
        for (int j = 0; j < 4; j++)
            Pc[(long)z * 16384 + r * 128 + lane + 32 * j] = __float2bfloat16(v[j] * inv);
    }
}

// ------------------------- flash token attention --------------------------------
__global__ void __launch_bounds__(256) k_flash(
    const __nv_bfloat16* __restrict__ qk,
    const __nv_bfloat16* __restrict__ v,
    const float* __restrict__ bias,
    __nv_bfloat16* __restrict__ out)
{
    int z = blockIdx.z;
    int b = z >> 4, h = z & 15;
    const __nv_bfloat16* Qb = qk + ((long)b * NN) * DD + h * 64;
    const __nv_bfloat16* Vb = v  + ((long)b * NN) * DD + h * 64;
    const float* biasb = bias + (long)z * NN;
    int m0 = blockIdx.y * 128;

    __shared__ __nv_bfloat16 sK[128][72];    // [token][d]
    __shared__ __nv_bfloat16 sVn[128][72];   // [token][d] (natural; PV uses ldsm.trans)
    __shared__ float sBias[128];

    int tid = threadIdx.x, wid = tid >> 5, lane = tid & 31;
    int g = lane >> 2, tg = lane & 3;
    int mrow = m0 + wid * 16;

    int brow = (lane & 7) + ((lane & 16) ? 8 : 0), bk = (lane & 8) ? 8 : 0;
    int vrow = (lane & 7) + ((lane & 8) ? 8 : 0), vcol = (lane & 16) ? 8 : 0;

    uint32_t qf[4][4];
    #pragma unroll
    for (int kp = 0; kp < 4; kp++) {
        const __nv_bfloat16* q0 = Qb + (long)(mrow + g) * DD + kp * 16 + 2 * tg;
        const __nv_bfloat16* q1 = Qb + (long)(mrow + g + 8) * DD + kp * 16 + 2 * tg;
        qf[kp][0] = *(const uint32_t*)q0;
        qf[kp][1] = *(const uint32_t*)q1;
        qf[kp][2] = *(const uint32_t*)(q0 + 8);
        qf[kp][3] = *(const uint32_t*)(q1 + 8);
    }

    uint4 rk[4], rv[4];
    #pragma unroll
    for (int t = 0; t < 4; t++) {
        int i = tid + t * 256;
        int tok = i >> 3, dv = (i & 7) * 8;
        rk[t] = *(const uint4*)(Qb + (long)tok * DD + dv);
        rv[t] = *(const uint4*)(Vb + (long)tok * DD + dv);
    }

    float m_run[2] = {-1e30f, -1e30f};
    float l_run[2] = {0.f, 0.f};
    float o[8][4];
    #pragma unroll
    for (int i = 0; i < 8; i++)
        #pragma unroll
        for (int j = 0; j < 4; j++) o[i][j] = 0.f;

    for (int n0 = 0; n0 < NN; n0 += 128) {
        #pragma unroll
        for (int t = 0; t < 4; t++) {
            int i = tid + t * 256;
            int tok = i >> 3, dv = (i & 7) * 8;
            *(uint4*)&sK[tok][dv] = rk[t];
            *(uint4*)&sVn[tok][dv] = rv[t];
        }
        if (tid < 128) sBias[tid] = biasb[n0 + tid];
        __syncthreads();

        if (n0 + 128 < NN) {
            #pragma unroll
            for (int t = 0; t < 4; t++) {
                int i = tid + t * 256;
                int tok = i >> 3, dv = (i & 7) * 8;
                rk[t] = *(const uint4*)(Qb + (long)(n0 + 128 + tok) * DD + dv);
                rv[t] = *(const uint4*)(Vb + (long)(n0 + 128 + tok) * DD + dv);
            }
        }

        // S = Q @ K^T via ldmatrix (2 n-tiles per LDSM.x4)
        float s[16][4];
        #pragma unroll
        for (int ni = 0; ni < 16; ni++)
            s[ni][0] = s[ni][1] = s[ni][2] = s[ni][3] = 0.f;
        #pragma unroll
        for (int kp = 0; kp < 4; kp++) {
            #pragma unroll
            for (int np = 0; np < 8; np++) {
                uint32_t rr[4];
                ldsm_x4(rr, smem_u32(&sK[np * 16 + brow][kp * 16 + bk]));
                uint32_t b0[2] = { rr[0], rr[1] }, b1[2] = { rr[2], rr[3] };
                mma16816(s[2 * np], qf[kp], b0);
                mma16816(s[2 * np + 1], qf[kp], b1);
            }
        }

        float mx[2] = {-1e30f, -1e30f};
        #pragma unroll
        for (int ni = 0; ni < 16; ni++) {
            #pragma unroll
            for (int j = 0; j < 4; j++) {
                float bval = sBias[ni * 8 + 2 * tg + (j & 1)];
                s[ni][j] = 2.f * s[ni][j] + bval;
                mx[j >> 1] = fmaxf(mx[j >> 1], s[ni][j]);
            }
        }
        #pragma unroll
        for (int r = 0; r < 2; r++) {
            mx[r] = fmaxf(mx[r], __shfl_xor_sync(0xffffffffu, mx[r], 1));
            mx[r] = fmaxf(mx[r], __shfl_xor_sync(0xffffffffu, mx[r], 2));
        }
        float m_new[2], alpha[2], rs[2] = {0.f, 0.f};
        #pragma unroll
        for (int r = 0; r < 2; r++) {
            m_new[r] = fmaxf(m_run[r], mx[r]);
            alpha[r] = __expf(m_run[r] - m_new[r]);
            m_run[r] = m_new[r];
        }
        #pragma unroll
        for (int ni = 0; ni < 16; ni++) {
            #pragma unroll
            for (int j = 0; j < 4; j++) {
                float p = __expf(s[ni][j] - m_new[j >> 1]);
                s[ni][j] = p;
                rs[j >> 1] += p;
            }
        }
        #pragma unroll
        for (int r = 0; r < 2; r++) {
            rs[r] += __shfl_xor_sync(0xffffffffu, rs[r], 1);
            rs[r] += __shfl_xor_sync(0xffffffffu, rs[r], 2);
            l_run[r] = l_run[r] * alpha[r] + rs[r];
        }
        #pragma unroll
        for (int di = 0; di < 8; di++) {
            o[di][0] *= alpha[0]; o[di][1] *= alpha[0];
            o[di][2] *= alpha[1]; o[di][3] *= alpha[1];
        }
        uint32_t pf[8][4];
        #pragma unroll
        for (int kp = 0; kp < 8; kp++) {
            pf[kp][0] = packbf(s[2 * kp][0], s[2 * kp][1]);
            pf[kp][1] = packbf(s[2 * kp][2], s[2 * kp][3]);
            pf[kp][2] = packbf(s[2 * kp + 1][0], s[2 * kp + 1][1]);
            pf[kp][3] = packbf(s[2 * kp + 1][2], s[2 * kp + 1][3]);
        }
        // O += P @ V via ldmatrix.trans on natural-layout V
        #pragma unroll
        for (int kp = 0; kp < 8; kp++) {
            #pragma unroll
            for (int dp = 0; dp < 4; dp++) {
                uint32_t rr[4];
                ldsm_x4_t(rr, smem_u32(&sVn[kp * 16 + vrow][dp * 16 + vcol]));
                uint32_t b0[2] = { rr[0], rr[1] }, b1[2] = { rr[2], rr[3] };
                mma16816(o[2 * dp], pf[kp], b0);
                mma16816(o[2 * dp + 1], pf[kp], b1);
            }
        }
        __syncthreads();
    }

    float inv0 = 1.f / l_run[0], inv1 = 1.f / l_run[1];
    long r0 = (long)(b * NN + mrow + g) * DD + h * 64;
    long r1 = (long)(b * NN + mrow + g + 8) * DD + h * 64;
    #pragma unroll
    for (int di = 0; di < 8; di++) {
        int col = di * 8 + 2 * tg;
        __nv_bfloat162 v0 = __floats2bfloat162_rn(o[di][0] * inv0, o[di][1] * inv0);
        __nv_bfloat162 v1 = __floats2bfloat162_rn(o[di][2] * inv1, o[di][3] * inv1);
        *(__nv_bfloat162*)&out[r0 + col] = v0;
        *(__nv_bfloat162*)&out[r1 + col] = v1;
    }
}

// ------------------------- generalized fast GEMM (cp.async + ldmatrix) ----------
struct GemmF {
    const __nv_bfloat16 *A, *B;
    long sA, sB, sC;
    long bBz;
    int K;
    void *C, *C2;
    int epi;                   // 0 exp bf16, 1 bf16, 3 residual fp32, 5 pair
    int zmode;
    const float *e0, *e1, *e2;
};

#define GF_SMEM (4*128*72*2)

__global__ void __launch_bounds__(256, 2) k_gemmF(GemmF p) {
    extern __shared__ __nv_bfloat16 smdyn[];
    __nv_bfloat16* sA[2] = { smdyn, smdyn + 128 * 72 };
    __nv_bfloat16* sB[2] = { smdyn + 2 * 128 * 72, smdyn + 3 * 128 * 72 };
    int tid = threadIdx.x, wid = tid >> 5, lane = tid & 31;
    int g = lane >> 2, tg = lane & 3;
    int bm = blockIdx.y * 128, bn = blockIdx.x * 128;
    int wm = (wid & 1) * 64, wn = (wid >> 1) * 32;

    int arow = lane & 15, ak = (lane & 16) ? 8 : 0;
    int brow = (lane & 7) + ((lane & 16) ? 8 : 0), bk = (lane & 8) ? 8 : 0;

    long offA = 0, offB = 0, offC = 0;
    if (p.zmode == 1) {
        int z = blockIdx.z, b = z >> 3, hc = z & 7;
        offA = (long)b * NN * DD + hc * 128;
        offB = (long)z * p.bBz;
        offC = offA;
    }
    const __nv_bfloat16* Ag = p.A + offA + (long)bm * p.sA;
    const __nv_bfloat16* Bg = p.B + offB + (long)bn * p.sB;

    float acc[4][4][4];
    #pragma unroll
    for (int i = 0; i < 4; i++)
        #pragma unroll
        for (int j = 0; j < 4; j++)
            #pragma unroll
            for (int q = 0; q < 4; q++) acc[i][j][q] = 0.f;

    #pragma unroll
    for (int t = 0; t < 4; t++) {
        int idx = tid + t * 256;
        int row = idx >> 3, v = (idx & 7) * 8;
        cp_async16(smem_u32(&sA[0][row * 72 + v]), Ag + (long)row * p.sA + v);
        cp_async16(smem_u32(&sB[0][row * 72 + v]), Bg + (long)row * p.sB + v);
    }
    asm volatile("cp.async.commit_group;");

    int nc = p.K >> 6;
    #pragma unroll 1
    for (int c = 0; c < nc; c++) {
        int s = c & 1;
        if (c < nc - 1) {
            int s2 = s ^ 1, k0 = (c + 1) * 64;
            #pragma unroll
            for (int t = 0; t < 4; t++) {
                int idx = tid + t * 256;
                int row = idx >> 3, v = (idx & 7) * 8;
                cp_async16(smem_u32(&sA[s2][row * 72 + v]), Ag + (long)row * p.sA + k0 + v);
                cp_async16(smem_u32(&sB[s2][row * 72 + v]), Bg + (long)row * p.sB + k0 + v);
            }
            asm volatile("cp.async.commit_group;");
            asm volatile("cp.async.wait_group 1;");
        } else {
            asm volatile("cp.async.wait_group 0;");
        }
        __syncthreads();

        const __nv_bfloat16* cA = sA[s];
        const __nv_bfloat16* cB = sB[s];
        #pragma unroll
        for (int kk = 0; kk < 64; kk += 16) {
            uint32_t ar[4][4], br[4][2];
            #pragma unroll
            for (int mi = 0; mi < 4; mi++)
                ldsm_x4(ar[mi], smem_u32(&cA[(wm + mi * 16 + arow) * 72 + kk + ak]));
            #pragma unroll
            for (int np = 0; np < 2; np++) {
                uint32_t rr[4];
                ldsm_x4(rr, smem_u32(&cB[(wn + np * 16 + brow) * 72 + kk + bk]));
                br[2 * np][0] = rr[0]; br[2 * np][1] = rr[1];
                br[2 * np + 1][0] = rr[2]; br[2 * np + 1][1] = rr[3];
            }
            #pragma unroll
            for (int mi = 0; mi < 4; mi++)
                #pragma unroll
                for (int ni = 0; ni < 4; ni++)
                    mma16816(acc[mi][ni], ar[mi], br[ni]);
        }
        __syncthreads();
    }

    #pragma unroll
    for (int mi = 0; mi < 4; mi++)
        #pragma unroll
        for (int ni = 0; ni < 4; ni++) {
            #pragma unroll
            for (int hh = 0; hh < 2; hh++) {
                int r = bm + wm + mi * 16 + g + hh * 8;
                int cc = bn + wn + ni * 8 + 2 * tg;
                float a0 = acc[mi][ni][2 * hh], a1 = acc[mi][ni][2 * hh + 1];
                int bb = r >> 11;
                if (p.epi == 0) {
                    float s0 = expf(p.e0[(long)bb * HID + cc]);
                    float s1 = expf(p.e0[(long)bb * HID + cc + 1]);
                    *(__nv_bfloat162*)&((__nv_bfloat16*)p.C)[offC + (long)r * p.sC + cc] =
                        __floats2bfloat162_rn(a0 * s0, a1 * s1);
                } else if (p.epi == 1) {
                    *(__nv_bfloat162*)&((__nv_bfloat16*)p.C)[offC + (long)r * p.sC + cc] =
                        __floats2bfloat162_rn(a0, a1);
                } else if (p.epi == 3) {
                    float* dst = (float*)p.C + (long)r * p.sC + cc;
                    const float* res = p.e2 + (long)r * DD + cc;
                    dst[0] = res[0] + a0 * p.e0[(long)bb * HID + cc] * p.e1[cc];
                    dst[1] = res[1] + a1 * p.e0[(long)bb * HID + cc + 1] * p.e1[cc + 1];
                } else {   // 5: pair
                    if (cc < 1024) {
                        float s0 = expf(p.e0[(long)bb * HID + cc]);
                        float s1 = expf(p.e0[(long)bb * HID + cc + 1]);
                        *(__nv_bfloat162*)&((__nv_bfloat16*)p.C)[(long)r * DD + cc] =
                            __floats2bfloat162_rn(a0 * s0, a1 * s1);
                    } else {
                        *(__nv_bfloat162*)&((__nv_bfloat16*)p.C2)[(long)r * DD + cc - 1024] =
                            __floats2bfloat162_rn(a0, a1);
                    }
                }
            }
        }
}

static inline void rungemmF(const GemmF& p, int gx, int gy, int gz) {
    static int inited = 0;
    if (!inited) {
        cudaFuncSetAttribute(k_gemmF, cudaFuncAttributeMaxDynamicSharedMemorySize, GF_SMEM);
        cudaFuncSetAttribute(k_chS, cudaFuncAttributeMaxDynamicSharedMemorySize, CHS_SMEM);
        inited = 1;
    }
    k_gemmF<<<dim3(gx, gy, gz), 256, GF_SMEM>>>(p);
}

#define SYMADDR(v, s) do { void* _p = nullptr; cudaGetSymbolAddress(&_p, s); v = (decltype(v))_p; } while (0)

// ------------------------- launch ----------------------------------------------
extern "C" void kernel_launch(void* const* d_in, const int* in_sizes, int n_in,
                              void* d_out, int out_size) {
    const float* x        = (const float*)d_in[0];
    const float* t        = (const float*)d_in[1];
    const float* n1s      = (const float*)d_in[2];
    const float* n1b      = (const float*)d_in[3];
    const float* n2s      = (const float*)d_in[4];
    const float* n2b      = (const float*)d_in[5];
    const float* tc_w1    = (const float*)d_in[6];
    const float* tc_b1    = (const float*)d_in[7];
    const float* tc_w2    = (const float*)d_in[8];
    const float* tc_b2    = (const float*)d_in[9];
    const float* tc_wa    = (const float*)d_in[10];
    const float* tc_ba    = (const float*)d_in[11];
    const float* tc_wc    = (const float*)d_in[12];
    const float* tc_bc    = (const float*)d_in[13];
    const float* attn_qk_w = (const float*)d_in[14];
    const float* attn_v_w  = (const float*)d_in[15];
    const float* attn_out_w= (const float*)d_in[16];
    const float* doob_w   = (const float*)d_in[17];
    const float* doob_b   = (const float*)d_in[18];
    const float* ch_qk_w  = (const float*)d_in[19];
    const float* ch_v_w   = (const float*)d_in[20];
    const float* ch_out_w = (const float*)d_in[21];
    const float* tau      = (const float*)d_in[22];
    const float* gamma1   = (const float*)d_in[23];
    const float* gamma2   = (const float*)d_in[24];

    float *emb, *p1, *p2, *p3, *av, *cv, *bias, *phi, *xmid;
    __nv_bfloat16 *wbf, *x1, *qkb, *vb, *attnb, *x2, *qkcb, *vcb, *Pcp, *chb;
    SYMADDR(emb, g_emb);   SYMADDR(p1, g_p1);     SYMADDR(p2, g_p2);  SYMADDR(p3, g_p3);
    SYMADDR(av, g_av);     SYMADDR(cv, g_cv);     SYMADDR(wbf, g_wbf);
    SYMADDR(x1, g_x1);     SYMADDR(qkb, g_qk);    SYMADDR(vb, g_v);
    SYMADDR(bias, g_bias); SYMADDR(phi, g_phi);
    SYMADDR(attnb, g_attn);SYMADDR(xmid, g_xmid); SYMADDR(x2, g_x2);
    SYMADDR(qkcb, g_qkc);  SYMADDR(vcb, g_vc);
    SYMADDR(Pcp, g_Pc);    SYMADDR(chb, g_ch);

    k_convt<<<dim3(32, 32, 6), dim3(32, 8)>>>(attn_qk_w, attn_v_w, attn_out_w,
                                              ch_qk_w, ch_v_w, ch_out_w, wbf);
    __nv_bfloat16* wqkv = wbf;
    __nv_bfloat16* wo   = wbf + 2 * 1048576;
    __nv_bfloat16* wcqv = wbf + 3 * 1048576;
    __nv_bfloat16* wco  = wbf + 5 * 1048576;

    // ---- conditioning (fused split-K chain) ----
    k_emb<<<(BB * HID + 255) / 256, 256>>>(t, emb);
    k_gemv_part<<<dim3(HID / 1024, 32), 256>>>(emb, tc_w1, p1);
    k_gemv_step<<<dim3(HID / 1024, 32, 1), 256>>>(p1, tc_b1, tc_w2, tc_w2, p2);
    k_gemv_step<<<dim3(HID / 1024, 32, 2), 256>>>(p2, tc_b2, tc_wa, tc_wc, p3);
    k_gemv_red2<<<dim3((2 * HID + 255) / 256, 1, 2), 256>>>(p3, tc_ba, tc_bc, av, cv);

    // ---- token attention ----
    k_ln_mod<<<BN, 256>>>(x, x1, n1s, n1b, av, doob_w, doob_b, phi);
    {   // fused: qk = (x1@Wqk)*exp(a_lg) | v = x1@Wv
        GemmF p = {};
        p.A = x1; p.sA = DD; p.B = wqkv; p.sB = DD; p.K = DD;
        p.C = qkb; p.C2 = vb; p.sC = DD;
        p.epi = 5; p.e0 = av + 3072;
        rungemmF(p, 16, 32, 1);
    }
    k_bias<<<BB * HH * NN / 8, 256>>>(qkb, phi, bias);
    k_flash<<<dim3(1, 16, BB * HH), 256>>>(qkb, vb, bias, attnb);
    {   // x_mid = x + (attn @ Wo) * a_gate * gamma1
        GemmF p = {};
        p.A = attnb; p.sA = DD; p.B = wo; p.sB = DD; p.K = DD;
        p.C = xmid; p.sC = DD;
        p.epi = 3; p.e0 = av + 2048; p.e1 = gamma1; p.e2 = x;
        rungemmF(p, 8, 32, 1);
    }

    // ---- channel attention ----
    k_ln_mod<<<BN, 256>>>(xmid, x2, n2s, n2b, cv, nullptr, nullptr, nullptr);
    {   // fused: qkc | vc
        GemmF p = {};
        p.A = x2; p.sA = DD; p.B = wcqv; p.sB = DD; p.K = DD;
        p.C = qkcb; p.C2 = vcb; p.sC = DD;
        p.epi = 5; p.e0 = cv + 3072;
        rungemmF(p, 16, 32, 1);
    }
    k_chS<<<BB * HCC, 256, CHS_SMEM>>>(qkcb, tau, Pcp);
    {   // ch[n][c] = sum_d Vc[n][d] * P[c][d]   (batched z = b*8+hc)
        GemmF p = {};
        p.A = vcb; p.sA = DD; p.B = Pcp; p.sB = 128; p.bBz = 128 * 128; p.K = 128;
        p.C = chb; p.sC = DD;
        p.epi = 1; p.zmode = 1;
        rungemmF(p, 1, 16, BB * HCC);
    }
    {   // out = x_mid + (ch @ Wco) * c_gate * gamma2
        GemmF p = {};
        p.A = chb; p.sA = DD; p.B = wco; p.sB = DD; p.K = DD;
        p.C = d_out; p.sC = DD;
        p.epi = 3; p.e0 = cv + 2048; p.e1 = gamma2; p.e2 = xmid;
        rungemmF(p, 8, 32, 1);
    }
}

// round 8
// speedup vs baseline: 4.1069x; 1.0904x over previous
#include <cuda_runtime.h>
#include <cuda_bf16.h>
#include <math.h>
#include <stdint.h>

#define BB 2
#define NN 2048
#define DD 1024
#define HH 16
#define HCC 8
#define HID 4096
#define BN (BB*NN)

// ------------------------- scratch ----------------------------------------------
__device__ float g_emb[BB*HID];
__device__ float g_p1[64*2*HID];
__device__ float g_p2[64*2*HID];
__device__ float g_p3[2*64*2*HID];
__device__ float g_av[BB*HID];
__device__ float g_cv[BB*HID];
__device__ __nv_bfloat16 g_wbf[6u*1048576u];   // transposed bf16 weights [n][k]
__device__ __nv_bfloat16 g_x1[BN*DD];
__device__ __nv_bfloat16 g_qk[BN*DD];
__device__ __nv_bfloat16 g_v[BN*DD];
__device__ float g_bias[BB*HH*NN];
__device__ float g_phi[BB*NN];
__device__ __nv_bfloat16 g_attn[BN*DD];
__device__ float g_xmid[BN*DD];
__device__ __nv_bfloat16 g_x2[BN*DD];
__device__ __nv_bfloat16 g_qkc[BN*DD];
__device__ __nv_bfloat16 g_vc[BN*DD];
__device__ __nv_bfloat16 g_Pc[BB*HCC*128*128];
__device__ __nv_bfloat16 g_ch[BN*DD];

// ------------------------- helpers ---------------------------------------------
__device__ inline float blockRed(float v, int op) {
    __shared__ float sm[32];
    int lane = threadIdx.x & 31, w = threadIdx.x >> 5;
    #pragma unroll
    for (int o = 16; o; o >>= 1) {
        float t = __shfl_xor_sync(0xffffffffu, v, o);
        v = op ? fmaxf(v, t) : v + t;
    }
    if (lane == 0) sm[w] = v;
    __syncthreads();
    int nw = blockDim.x >> 5;
    if (w == 0) {
        v = (lane < nw) ? sm[lane] : (op ? -INFINITY : 0.f);
        #pragma unroll
        for (int o = 16; o; o >>= 1) {
            float t = __shfl_xor_sync(0xffffffffu, v, o);
            v = op ? fmaxf(v, t) : v + t;
        }
        if (lane == 0) sm[0] = v;
    }
    __syncthreads();
    float r = sm[0];
    __syncthreads();
    return r;
}

__device__ inline void mma16816(float* c, const uint32_t* a, const uint32_t* b) {
    asm volatile(
        "mma.sync.aligned.m16n8k16.row.col.f32.bf16.bf16.f32 "
        "{%0,%1,%2,%3}, {%4,%5,%6,%7}, {%8,%9}, {%0,%1,%2,%3};\n"
        : "+f"(c[0]), "+f"(c[1]), "+f"(c[2]), "+f"(c[3])
        : "r"(a[0]), "r"(a[1]), "r"(a[2]), "r"(a[3]), "r"(b[0]), "r"(b[1]));
}

__device__ inline void ldsm_x4(uint32_t* r, uint32_t saddr) {
    asm volatile("ldmatrix.sync.aligned.m8n8.x4.shared.b16 {%0,%1,%2,%3}, [%4];"
        : "=r"(r[0]), "=r"(r[1]), "=r"(r[2]), "=r"(r[3]) : "r"(saddr));
}

__device__ inline void ldsm_x4_t(uint32_t* r, uint32_t saddr) {
    asm volatile("ldmatrix.sync.aligned.m8n8.x4.trans.shared.b16 {%0,%1,%2,%3}, [%4];"
        : "=r"(r[0]), "=r"(r[1]), "=r"(r[2]), "=r"(r[3]) : "r"(saddr));
}

__device__ inline uint32_t packbf(float a, float b) {
    __nv_bfloat162 t = __floats2bfloat162_rn(a, b);
    return *(uint32_t*)&t;
}

__device__ inline uint32_t smem_u32(const void* p) {
    uint32_t a;
    asm("{ .reg .u64 t; cvta.to.shared.u64 t, %1; cvt.u32.u64 %0, t; }" : "=r"(a) : "l"(p));
    return a;
}

__device__ inline void cp_async16(uint32_t saddr, const void* gaddr) {
    asm volatile("cp.async.cg.shared.global [%0], [%1], 16;" :: "r"(saddr), "l"(gaddr));
}

// ------------------------- small kernels ----------------------------------------
__global__ void k_emb(const float* __restrict__ t, float* __restrict__ emb) {
    int i = blockIdx.x * 256 + threadIdx.x;
    if (i >= BB * HID) return;
    int b = i / HID, j = i % HID;
    int jj = j & 2047;
    float f = expf(-9.210340371976184f * (float)jj / 2048.0f);
    float a = t[b] * f;
    emb[i] = (j < 2048) ? cosf(a) : sinf(a);
}

// split-K GEMV partials: 64 k-slices of 64, scalar coalesced loads, 1024 CTAs
__global__ void k_gemv_part(const float* __restrict__ in, const float* __restrict__ W,
                            float* __restrict__ part) {
    int col = blockIdx.x * 256 + threadIdx.x;
    int k0 = blockIdx.y * 64;
    float a0 = 0.f, a1 = 0.f;
    #pragma unroll 8
    for (int k = k0; k < k0 + 64; k++) {
        float w = W[(long)k * HID + col];
        a0 += in[k] * w;
        a1 += in[HID + k] * w;
    }
    part[((long)blockIdx.y * 2 + 0) * HID + col] = a0;
    part[((long)blockIdx.y * 2 + 1) * HID + col] = a1;
}

// fused: reduce prev partials (+bias, silu) for this 64-k-slice, then partial GEMV
__global__ void k_gemv_step(const float* __restrict__ prevPart,
                            const float* __restrict__ prevBias,
                            const float* __restrict__ W0, const float* __restrict__ W1,
                            float* __restrict__ outPart) {
    __shared__ float in_s[2][64];
    const float* W = blockIdx.z ? W1 : W0;
    float* op = outPart + (long)blockIdx.z * 64 * 2 * HID;
    int tid = threadIdx.x;
    int k0 = blockIdx.y * 64;
    if (tid < 128) {
        int b = tid >> 6, kk = tid & 63, k = k0 + kk;
        float s = prevBias[k];
        #pragma unroll 8
        for (int p2 = 0; p2 < 64; p2++) s += prevPart[((long)p2 * 2 + b) * HID + k];
        in_s[b][kk] = s / (1.f + __expf(-s));
    }
    __syncthreads();
    int col = blockIdx.x * 256 + tid;
    float a0 = 0.f, a1 = 0.f;
    #pragma unroll 8
    for (int kk = 0; kk < 64; kk++) {
        float w = W[(long)(k0 + kk) * HID + col];
        a0 += in_s[0][kk] * w;
        a1 += in_s[1][kk] * w;
    }
    op[((long)blockIdx.y * 2 + 0) * HID + col] = a0;
    op[((long)blockIdx.y * 2 + 1) * HID + col] = a1;
}

__global__ void k_gemv_red2(const float* __restrict__ part, const float* __restrict__ b0,
                            const float* __restrict__ b1, float* __restrict__ o0,
                            float* __restrict__ o1) {
    int i = blockIdx.x * 256 + threadIdx.x;
    if (i >= 2 * HID) return;
    const float* pp = part + (long)blockIdx.z * 64 * 2 * HID;
    const float* bias = blockIdx.z ? b1 : b0;
    float* out = blockIdx.z ? o1 : o0;
    int b = i / HID, col = i % HID;
    float s = bias[col];
    #pragma unroll 8
    for (int p = 0; p < 64; p++) s += pp[((long)p * 2 + b) * HID + col];
    out[(long)b * HID + col] = s;
}

// tiled transpose + fp32->bf16
__global__ void k_convt(const float* __restrict__ w0, const float* __restrict__ w1,
                        const float* __restrict__ w2, const float* __restrict__ w3,
                        const float* __restrict__ w4, const float* __restrict__ w5,
                        __nv_bfloat16* __restrict__ out) {
    __shared__ float t[32][33];
    const float* s = w0;
    int z = blockIdx.z;
    if (z == 1) s = w1; else if (z == 2) s = w2; else if (z == 3) s = w3;
    else if (z == 4) s = w4; else if (z == 5) s = w5;
    int x = blockIdx.x * 32 + threadIdx.x;
    int y0 = blockIdx.y * 32;
    #pragma unroll
    for (int j = 0; j < 32; j += 8)
        t[threadIdx.y + j][threadIdx.x] = s[(long)(y0 + threadIdx.y + j) * DD + x];
    __syncthreads();
    __nv_bfloat16* d = out + (long)z * 1048576;
    int n = blockIdx.x * 32 + threadIdx.y;
    int k = y0 + threadIdx.x;
    #pragma unroll
    for (int j = 0; j < 32; j += 8)
        d[(long)(n + j) * DD + k] = __float2bfloat16(t[threadIdx.x][threadIdx.y + j]);
}

// LayerNorm + modulate -> bf16, optional fused phi (doob) reduction
__global__ void k_ln_mod(const float* __restrict__ xin, __nv_bfloat16* __restrict__ xout,
                         const float* __restrict__ sc, const float* __restrict__ bi,
                         const float* __restrict__ mod, const float* __restrict__ dw,
                         const float* __restrict__ db, float* __restrict__ phi) {
    int r = blockIdx.x;
    int b = r >> 11;
    const float* xr = xin + (long)r * DD;
    int tid = threadIdx.x;
    float v[4];
    float s = 0.f;
    #pragma unroll
    for (int i = 0; i < 4; i++) { v[i] = xr[tid + i * 256]; s += v[i]; }
    s = blockRed(s, 0);
    float mu = s * (1.0f / DD);
    float vs = 0.f;
    #pragma unroll
    for (int i = 0; i < 4; i++) { float d = v[i] - mu; vs += d * d; }
    vs = blockRed(vs, 0);
    float rstd = rsqrtf(vs * (1.0f / DD) + 1e-6f);
    float ps = 0.f;
    #pragma unroll
    for (int i = 0; i < 4; i++) {
        int j = tid + i * 256;
        float y = (v[i] - mu) * rstd * sc[j] + bi[j];
        float m = y * (1.f + mod[(long)b * HID + 1024 + j]) + mod[(long)b * HID + j];
        xout[(long)r * DD + j] = __float2bfloat16(m);
        if (dw) ps += m * dw[j];
    }
    if (dw) {
        ps = blockRed(ps, 0);
        if (tid == 0) phi[r] = ps + db[0];
    }
}

// bias[z*NN+n] = phi[b,n] - |q[b,h,n,:]|^2
__global__ void k_bias(const __nv_bfloat16* __restrict__ qk, const float* __restrict__ phi,
                       float* __restrict__ bias) {
    int gid = blockIdx.x * 8 + (threadIdx.x >> 5);
    int lane = threadIdx.x & 31;
    int n = gid & 2047;
    int h = (gid >> 11) & 15;
    int b = gid >> 15;
    const __nv_bfloat16* p = qk + ((long)b * NN + n) * DD + h * 64;
    float f0 = __bfloat162float(p[lane]);
    float f1 = __bfloat162float(p[lane + 32]);
    float s = f0 * f0 + f1 * f1;
    #pragma unroll
    for (int o = 16; o; o >>= 1) s += __shfl_xor_sync(0xffffffffu, s, o);
    if (lane == 0) bias[gid] = phi[b * NN + n] - s;
}

// ------------------------- channel S + softmax (one CTA per (b,hc)) -------------
#define CHS_SMEM (128*72*2 + 128*129*4 + 512)
__global__ void __launch_bounds__(256) k_chS(
    const __nv_bfloat16* __restrict__ qkc,
    const float* __restrict__ tau, __nv_bfloat16* __restrict__ Pc)
{
    extern __shared__ __align__(16) char smraw[];
    __nv_bfloat16* sQt = (__nv_bfloat16*)smraw;                 // [128][72]
    float* sS = (float*)(smraw + 128 * 72 * 2);                 // [128][129]
    float* sq2 = (float*)(smraw + 128 * 72 * 2 + 128 * 129 * 4);// [128]
    int z = blockIdx.x;
    int b = z >> 3, hc = z & 7;
    int tid = threadIdx.x, wid = tid >> 5, lane = tid & 31;
    int g = lane >> 2, tg = lane & 3;
    int wm = (wid & 1) * 64, wn = (wid >> 1) * 32;
    const __nv_bfloat16* base = qkc + (long)b * NN * DD + hc * 128;
    float ft = 0.022097086912079608f * tau[hc];

    int arow = lane & 15, ak = (lane & 16) ? 8 : 0;
    int brow = (lane & 7) + ((lane & 16) ? 8 : 0), bk = (lane & 8) ? 8 : 0;

    float acc[4][4][4];
    #pragma unroll
    for (int i = 0; i < 4; i++)
        #pragma unroll
        for (int j = 0; j < 4; j++)
            #pragma unroll
            for (int q = 0; q < 4; q++) acc[i][j][q] = 0.f;

    uint4 rq[4];
    #pragma unroll
    for (int t = 0; t < 4; t++) {
        int idx = tid + t * 256;
        int tok = idx >> 4, dg = (idx & 15) * 8;
        rq[t] = *(const uint4*)(base + (long)tok * DD + dg);
    }

    for (int ch = 0; ch < 32; ch++) {
        #pragma unroll
        for (int t = 0; t < 4; t++) {
            int idx = tid + t * 256;
            int tok = idx >> 4, dg = (idx & 15) * 8;
            union { uint4 u; __nv_bfloat16 hh[8]; } tv;
            tv.u = rq[t];
            #pragma unroll
            for (int j = 0; j < 8; j++) sQt[(dg + j) * 72 + tok] = tv.hh[j];
        }
        __syncthreads();
        if (ch < 31) {
            #pragma unroll
            for (int t = 0; t < 4; t++) {
                int idx = tid + t * 256;
                int tok = idx >> 4, dg = (idx & 15) * 8;
                rq[t] = *(const uint4*)(base + (long)((ch + 1) * 64 + tok) * DD + dg);
            }
        }
        #pragma unroll
        for (int kk = 0; kk < 64; kk += 16) {
            uint32_t ar[4][4], br[4][2];
            #pragma unroll
            for (int mi = 0; mi < 4; mi++)
                ldsm_x4(ar[mi], smem_u32(&sQt[(wm + mi * 16 + arow) * 72 + kk + ak]));
            #pragma unroll
            for (int np = 0; np < 2; np++) {
                uint32_t rr[4];
                ldsm_x4(rr, smem_u32(&sQt[(wn + np * 16 + brow) * 72 + kk + bk]));
                br[2 * np][0] = rr[0]; br[2 * np][1] = rr[1];
                br[2 * np + 1][0] = rr[2]; br[2 * np + 1][1] = rr[3];
            }
            #pragma unroll
            for (int mi = 0; mi < 4; mi++)
                #pragma unroll
                for (int ni = 0; ni < 4; ni++)
                    mma16816(acc[mi][ni], ar[mi], br[ni]);
        }
        __syncthreads();
    }

    #pragma unroll
    for (int mi = 0; mi < 4; mi++)
        #pragma unroll
        for (int ni = 0; ni < 4; ni++) {
            int r0 = wm + mi * 16 + g, c0 = wn + ni * 8 + 2 * tg;
            sS[r0 * 129 + c0] = acc[mi][ni][0];
            sS[r0 * 129 + c0 + 1] = acc[mi][ni][1];
            sS[(r0 + 8) * 129 + c0] = acc[mi][ni][2];
            sS[(r0 + 8) * 129 + c0 + 1] = acc[mi][ni][3];
        }
    __syncthreads();
    if (tid < 128) sq2[tid] = sS[tid * 129 + tid];
    __syncthreads();

    for (int it = 0; it < 16; it++) {
        int r = it * 8 + wid;
        float v[4], mx = -1e30f;
        #pragma unroll
        for (int j = 0; j < 4; j++) {
            int c = lane + 32 * j;
            v[j] = (2.f * sS[r * 129 + c] - sq2[c]) * ft;
            mx = fmaxf(mx, v[j]);
        }
        #pragma unroll
        for (int o = 16; o; o >>= 1) mx = fmaxf(mx, __shfl_xor_sync(0xffffffffu, mx, o));
        float sum = 0.f;
        #pragma unroll
        for (int j = 0; j < 4; j++) { v[j] = __expf(v[j] - mx); sum += v[j]; }
        #pragma unroll
        for (int o = 16; o; o >>= 1) sum += __shfl_xor_sync(0xffffffffu, sum, o);
        float inv = 1.f / sum;
        #pragma unroll
        for (int j = 0; j < 4; j++)
            Pc[(long)z * 16384 + r * 128 + lane + 32 * j] = __float2bfloat16(v[j] * inv);
    }
}

// ------------------------- flash token attention --------------------------------
__global__ void __launch_bounds__(256) k_flash(
    const __nv_bfloat16* __restrict__ qk,
    const __nv_bfloat16* __restrict__ v,
    const float* __restrict__ bias,
    __nv_bfloat16* __restrict__ out)
{
    int z = blockIdx.z;
    int b = z >> 4, h = z & 15;
    const __nv_bfloat16* Qb = qk + ((long)b * NN) * DD + h * 64;
    const __nv_bfloat16* Vb = v  + ((long)b * NN) * DD + h * 64;
    const float* biasb = bias + (long)z * NN;
    int m0 = blockIdx.y * 128;

    __shared__ __nv_bfloat16 sK[128][72];    // [token][d]
    __shared__ __nv_bfloat16 sVn[128][72];   // [token][d] (natural; PV via ldsm.trans)
    __shared__ float sBias[128];

    int tid = threadIdx.x, wid = tid >> 5, lane = tid & 31;
    int g = lane >> 2, tg = lane & 3;
    int mrow = m0 + wid * 16;

    int brow = (lane & 7) + ((lane & 16) ? 8 : 0), bk = (lane & 8) ? 8 : 0;
    int vrow = (lane & 7) + ((lane & 8) ? 8 : 0), vcol = (lane & 16) ? 8 : 0;

    uint32_t qf[4][4];
    #pragma unroll
    for (int kp = 0; kp < 4; kp++) {
        const __nv_bfloat16* q0 = Qb + (long)(mrow + g) * DD + kp * 16 + 2 * tg;
        const __nv_bfloat16* q1 = Qb + (long)(mrow + g + 8) * DD + kp * 16 + 2 * tg;
        qf[kp][0] = *(const uint32_t*)q0;
        qf[kp][1] = *(const uint32_t*)q1;
        qf[kp][2] = *(const uint32_t*)(q0 + 8);
        qf[kp][3] = *(const uint32_t*)(q1 + 8);
    }

    uint4 rk[4], rv[4];
    #pragma unroll
    for (int t = 0; t < 4; t++) {
        int i = tid + t * 256;
        int tok = i >> 3, dv = (i & 7) * 8;
        rk[t] = *(const uint4*)(Qb + (long)tok * DD + dv);
        rv[t] = *(const uint4*)(Vb + (long)tok * DD + dv);
    }

    float m_run[2] = {-1e30f, -1e30f};
    float l_run[2] = {0.f, 0.f};
    float o[8][4];
    #pragma unroll
    for (int i = 0; i < 8; i++)
        #pragma unroll
        for (int j = 0; j < 4; j++) o[i][j] = 0.f;

    for (int n0 = 0; n0 < NN; n0 += 128) {
        #pragma unroll
        for (int t = 0; t < 4; t++) {
            int i = tid + t * 256;
            int tok = i >> 3, dv = (i & 7) * 8;
            *(uint4*)&sK[tok][dv] = rk[t];
            *(uint4*)&sVn[tok][dv] = rv[t];
        }
        if (tid < 128) sBias[tid] = biasb[n0 + tid];
        __syncthreads();

        if (n0 + 128 < NN) {
            #pragma unroll
            for (int t = 0; t < 4; t++) {
                int i = tid + t * 256;
                int tok = i >> 3, dv = (i & 7) * 8;
                rk[t] = *(const uint4*)(Qb + (long)(n0 + 128 + tok) * DD + dv);
                rv[t] = *(const uint4*)(Vb + (long)(n0 + 128 + tok) * DD + dv);
            }
        }

        float s[16][4];
        #pragma unroll
        for (int ni = 0; ni < 16; ni++)
            s[ni][0] = s[ni][1] = s[ni][2] = s[ni][3] = 0.f;
        #pragma unroll
        for (int kp = 0; kp < 4; kp++) {
            #pragma unroll
            for (int np = 0; np < 8; np++) {
                uint32_t rr[4];
                ldsm_x4(rr, smem_u32(&sK[np * 16 + brow][kp * 16 + bk]));
                uint32_t b0[2] = { rr[0], rr[1] }, b1[2] = { rr[2], rr[3] };
                mma16816(s[2 * np], qf[kp], b0);
                mma16816(s[2 * np + 1], qf[kp], b1);
            }
        }

        float mx[2] = {-1e30f, -1e30f};
        #pragma unroll
        for (int ni = 0; ni < 16; ni++) {
            #pragma unroll
            for (int j = 0; j < 4; j++) {
                float bval = sBias[ni * 8 + 2 * tg + (j & 1)];
                s[ni][j] = 2.f * s[ni][j] + bval;
                mx[j >> 1] = fmaxf(mx[j >> 1], s[ni][j]);
            }
        }
        #pragma unroll
        for (int r = 0; r < 2; r++) {
            mx[r] = fmaxf(mx[r], __shfl_xor_sync(0xffffffffu, mx[r], 1));
            mx[r] = fmaxf(mx[r], __shfl_xor_sync(0xffffffffu, mx[r], 2));
        }
        float m_new[2], alpha[2], rs[2] = {0.f, 0.f};
        #pragma unroll
        for (int r = 0; r < 2; r++) {
            m_new[r] = fmaxf(m_run[r], mx[r]);
            alpha[r] = __expf(m_run[r] - m_new[r]);
            m_run[r] = m_new[r];
        }
        #pragma unroll
        for (int ni = 0; ni < 16; ni++) {
            #pragma unroll
            for (int j = 0; j < 4; j++) {
                float p = __expf(s[ni][j] - m_new[j >> 1]);
                s[ni][j] = p;
                rs[j >> 1] += p;
            }
        }
        #pragma unroll
        for (int r = 0; r < 2; r++) {
            rs[r] += __shfl_xor_sync(0xffffffffu, rs[r], 1);
            rs[r] += __shfl_xor_sync(0xffffffffu, rs[r], 2);
            l_run[r] = l_run[r] * alpha[r] + rs[r];
        }
        #pragma unroll
        for (int di = 0; di < 8; di++) {
            o[di][0] *= alpha[0]; o[di][1] *= alpha[0];
            o[di][2] *= alpha[1]; o[di][3] *= alpha[1];
        }
        uint32_t pf[8][4];
        #pragma unroll
        for (int kp = 0; kp < 8; kp++) {
            pf[kp][0] = packbf(s[2 * kp][0], s[2 * kp][1]);
            pf[kp][1] = packbf(s[2 * kp][2], s[2 * kp][3]);
            pf[kp][2] = packbf(s[2 * kp + 1][0], s[2 * kp + 1][1]);
            pf[kp][3] = packbf(s[2 * kp + 1][2], s[2 * kp + 1][3]);
        }
        #pragma unroll
        for (int kp = 0; kp < 8; kp++) {
            #pragma unroll
            for (int dp = 0; dp < 4; dp++) {
                uint32_t rr[4];
                ldsm_x4_t(rr, smem_u32(&sVn[kp * 16 + vrow][dp * 16 + vcol]));
                uint32_t b0[2] = { rr[0], rr[1] }, b1[2] = { rr[2], rr[3] };
                mma16816(o[2 * dp], pf[kp], b0);
                mma16816(o[2 * dp + 1], pf[kp], b1);
            }
        }
        __syncthreads();
    }

    float inv0 = 1.f / l_run[0], inv1 = 1.f / l_run[1];
    long r0 = (long)(b * NN + mrow + g) * DD + h * 64;
    long r1 = (long)(b * NN + mrow + g + 8) * DD + h * 64;
    #pragma unroll
    for (int di = 0; di < 8; di++) {
        int col = di * 8 + 2 * tg;
        __nv_bfloat162 v0 = __floats2bfloat162_rn(o[di][0] * inv0, o[di][1] * inv0);
        __nv_bfloat162 v1 = __floats2bfloat162_rn(o[di][2] * inv1, o[di][3] * inv1);
        *(__nv_bfloat162*)&out[r0 + col] = v0;
        *(__nv_bfloat162*)&out[r1 + col] = v1;
    }
}

// ------------------------- generalized fast GEMM (cp.async + ldmatrix) ----------
struct GemmF {
    const __nv_bfloat16 *A, *B;
    long sA, sB, sC;
    long bBz;
    int K;
    void *C, *C2;
    int epi;                   // 0 exp bf16, 1 bf16, 3 residual fp32, 5 pair
    int zmode;
    const float *e0, *e1, *e2;
};

#define GF_SMEM (4*128*72*2)

__global__ void __launch_bounds__(256, 2) k_gemmF(GemmF p) {
    extern __shared__ __nv_bfloat16 smdyn[];
    __nv_bfloat16* sA[2] = { smdyn, smdyn + 128 * 72 };
    __nv_bfloat16* sB[2] = { smdyn + 2 * 128 * 72, smdyn + 3 * 128 * 72 };
    int tid = threadIdx.x, wid = tid >> 5, lane = tid & 31;
    int g = lane >> 2, tg = lane & 3;
    int bm = blockIdx.y * 128, bn = blockIdx.x * 128;
    int wm = (wid & 1) * 64, wn = (wid >> 1) * 32;

    int arow = lane & 15, ak = (lane & 16) ? 8 : 0;
    int brow = (lane & 7) + ((lane & 16) ? 8 : 0), bk = (lane & 8) ? 8 : 0;

    long offA = 0, offB = 0, offC = 0;
    if (p.zmode == 1) {
        int z = blockIdx.z, b = z >> 3, hc = z & 7;
        offA = (long)b * NN * DD + hc * 128;
        offB = (long)z * p.bBz;
        offC = offA;
    }
    const __nv_bfloat16* Ag = p.A + offA + (long)bm * p.sA;
    const __nv_bfloat16* Bg = p.B + offB + (long)bn * p.sB;

    float acc[4][4][4];
    #pragma unroll
    for (int i = 0; i < 4; i++)
        #pragma unroll
        for (int j = 0; j < 4; j++)
            #pragma unroll
            for (int q = 0; q < 4; q++) acc[i][j][q] = 0.f;

    #pragma unroll
    for (int t = 0; t < 4; t++) {
        int idx = tid + t * 256;
        int row = idx >> 3, v = (idx & 7) * 8;
        cp_async16(smem_u32(&sA[0][row * 72 + v]), Ag + (long)row * p.sA + v);
        cp_async16(smem_u32(&sB[0][row * 72 + v]), Bg + (long)row * p.sB + v);
    }
    asm volatile("cp.async.commit_group;");

    int nc = p.K >> 6;
    #pragma unroll 1
    for (int c = 0; c < nc; c++) {
        int s = c & 1;
        if (c < nc - 1) {
            int s2 = s ^ 1, k0 = (c + 1) * 64;
            #pragma unroll
            for (int t = 0; t < 4; t++) {
                int idx = tid + t * 256;
                int row = idx >> 3, v = (idx & 7) * 8;
                cp_async16(smem_u32(&sA[s2][row * 72 + v]), Ag + (long)row * p.sA + k0 + v);
                cp_async16(smem_u32(&sB[s2][row * 72 + v]), Bg + (long)row * p.sB + k0 + v);
            }
            asm volatile("cp.async.commit_group;");
            asm volatile("cp.async.wait_group 1;");
        } else {
            asm volatile("cp.async.wait_group 0;");
        }
        __syncthreads();

        const __nv_bfloat16* cA = sA[s];
        const __nv_bfloat16* cB = sB[s];
        #pragma unroll
        for (int kk = 0; kk < 64; kk += 16) {
            uint32_t ar[4][4], br[4][2];
            #pragma unroll
            for (int mi = 0; mi < 4; mi++)
                ldsm_x4(ar[mi], smem_u32(&cA[(wm + mi * 16 + arow) * 72 + kk + ak]));
            #pragma unroll
            for (int np = 0; np < 2; np++) {
                uint32_t rr[4];
                ldsm_x4(rr, smem_u32(&cB[(wn + np * 16 + brow) * 72 + kk + bk]));
                br[2 * np][0] = rr[0]; br[2 * np][1] = rr[1];
                br[2 * np + 1][0] = rr[2]; br[2 * np + 1][1] = rr[3];
            }
            #pragma unroll
            for (int mi = 0; mi < 4; mi++)
                #pragma unroll
                for (int ni = 0; ni < 4; ni++)
                    mma16816(acc[mi][ni], ar[mi], br[ni]);
        }
        __syncthreads();
    }

    #pragma unroll
    for (int mi = 0; mi < 4; mi++)
        #pragma unroll
        for (int ni = 0; ni < 4; ni++) {
            #pragma unroll
            for (int hh = 0; hh < 2; hh++) {
                int r = bm + wm + mi * 16 + g + hh * 8;
                int cc = bn + wn + ni * 8 + 2 * tg;
                float a0 = acc[mi][ni][2 * hh], a1 = acc[mi][ni][2 * hh + 1];
                int bb = r >> 11;
                if (p.epi == 0) {
                    float s0 = expf(p.e0[(long)bb * HID + cc]);
                    float s1 = expf(p.e0[(long)bb * HID + cc + 1]);
                    *(__nv_bfloat162*)&((__nv_bfloat16*)p.C)[offC + (long)r * p.sC + cc] =
                        __floats2bfloat162_rn(a0 * s0, a1 * s1);
                } else if (p.epi == 1) {
                    *(__nv_bfloat162*)&((__nv_bfloat16*)p.C)[offC + (long)r * p.sC + cc] =
                        __floats2bfloat162_rn(a0, a1);
                } else if (p.epi == 3) {
                    float* dst = (float*)p.C + (long)r * p.sC + cc;
                    const float* res = p.e2 + (long)r * DD + cc;
                    dst[0] = res[0] + a0 * p.e0[(long)bb * HID + cc] * p.e1[cc];
                    dst[1] = res[1] + a1 * p.e0[(long)bb * HID + cc + 1] * p.e1[cc + 1];
                } else {   // 5: pair
                    if (cc < 1024) {
                        float s0 = expf(p.e0[(long)bb * HID + cc]);
                        float s1 = expf(p.e0[(long)bb * HID + cc + 1]);
                        *(__nv_bfloat162*)&((__nv_bfloat16*)p.C)[(long)r * DD + cc] =
                            __floats2bfloat162_rn(a0 * s0, a1 * s1);
                    } else {
                        *(__nv_bfloat162*)&((__nv_bfloat16*)p.C2)[(long)r * DD + cc - 1024] =
                            __floats2bfloat162_rn(a0, a1);
                    }
                }
            }
        }
}

static inline void rungemmF(const GemmF& p, int gx, int gy, int gz) {
    static int inited = 0;
    if (!inited) {
        cudaFuncSetAttribute(k_gemmF, cudaFuncAttributeMaxDynamicSharedMemorySize, GF_SMEM);
        cudaFuncSetAttribute(k_chS, cudaFuncAttributeMaxDynamicSharedMemorySize, CHS_SMEM);
        inited = 1;
    }
    k_gemmF<<<dim3(gx, gy, gz), 256, GF_SMEM>>>(p);
}

#define SYMADDR(v, s) do { void* _p = nullptr; cudaGetSymbolAddress(&_p, s); v = (decltype(v))_p; } while (0)

// ------------------------- launch ----------------------------------------------
extern "C" void kernel_launch(void* const* d_in, const int* in_sizes, int n_in,
                              void* d_out, int out_size) {
    const float* x        = (const float*)d_in[0];
    const float* t        = (const float*)d_in[1];
    const float* n1s      = (const float*)d_in[2];
    const float* n1b      = (const float*)d_in[3];
    const float* n2s      = (const float*)d_in[4];
    const float* n2b      = (const float*)d_in[5];
    const float* tc_w1    = (const float*)d_in[6];
    const float* tc_b1    = (const float*)d_in[7];
    const float* tc_w2    = (const float*)d_in[8];
    const float* tc_b2    = (const float*)d_in[9];
    const float* tc_wa    = (const float*)d_in[10];
    const float* tc_ba    = (const float*)d_in[11];
    const float* tc_wc    = (const float*)d_in[12];
    const float* tc_bc    = (const float*)d_in[13];
    const float* attn_qk_w = (const float*)d_in[14];
    const float* attn_v_w  = (const float*)d_in[15];
    const float* attn_out_w= (const float*)d_in[16];
    const float* doob_w   = (const float*)d_in[17];
    const float* doob_b   = (const float*)d_in[18];
    const float* ch_qk_w  = (const float*)d_in[19];
    const float* ch_v_w   = (const float*)d_in[20];
    const float* ch_out_w = (const float*)d_in[21];
    const float* tau      = (const float*)d_in[22];
    const float* gamma1   = (const float*)d_in[23];
    const float* gamma2   = (const float*)d_in[24];

    float *emb, *p1, *p2, *p3, *av, *cv, *bias, *phi, *xmid;
    __nv_bfloat16 *wbf, *x1, *qkb, *vb, *attnb, *x2, *qkcb, *vcb, *Pcp, *chb;
    SYMADDR(emb, g_emb);   SYMADDR(p1, g_p1);     SYMADDR(p2, g_p2);  SYMADDR(p3, g_p3);
    SYMADDR(av, g_av);     SYMADDR(cv, g_cv);     SYMADDR(wbf, g_wbf);
    SYMADDR(x1, g_x1);     SYMADDR(qkb, g_qk);    SYMADDR(vb, g_v);
    SYMADDR(bias, g_bias); SYMADDR(phi, g_phi);
    SYMADDR(attnb, g_attn);SYMADDR(xmid, g_xmid); SYMADDR(x2, g_x2);
    SYMADDR(qkcb, g_qkc);  SYMADDR(vcb, g_vc);
    SYMADDR(Pcp, g_Pc);    SYMADDR(chb, g_ch);

    k_convt<<<dim3(32, 32, 6), dim3(32, 8)>>>(attn_qk_w, attn_v_w, attn_out_w,
                                              ch_qk_w, ch_v_w, ch_out_w, wbf);
    __nv_bfloat16* wqkv = wbf;
    __nv_bfloat16* wo   = wbf + 2 * 1048576;
    __nv_bfloat16* wcqv = wbf + 3 * 1048576;
    __nv_bfloat16* wco  = wbf + 5 * 1048576;

    // ---- conditioning (fused split-K chain, 64-way split, 1024 CTAs/layer) ----
    k_emb<<<(BB * HID + 255) / 256, 256>>>(t, emb);
    k_gemv_part<<<dim3(HID / 256, 64), 256>>>(emb, tc_w1, p1);
    k_gemv_step<<<dim3(HID / 256, 64, 1), 256>>>(p1, tc_b1, tc_w2, tc_w2, p2);
    k_gemv_step<<<dim3(HID / 256, 64, 2), 256>>>(p2, tc_b2, tc_wa, tc_wc, p3);
    k_gemv_red2<<<dim3((2 * HID + 255) / 256, 1, 2), 256>>>(p3, tc_ba, tc_bc, av, cv);

    // ---- token attention ----
    k_ln_mod<<<BN, 256>>>(x, x1, n1s, n1b, av, doob_w, doob_b, phi);
    {   // fused: qk = (x1@Wqk)*exp(a_lg) | v = x1@Wv
        GemmF p = {};
        p.A = x1; p.sA = DD; p.B = wqkv; p.sB = DD; p.K = DD;
        p.C = qkb; p.C2 = vb; p.sC = DD;
        p.epi = 5; p.e0 = av + 3072;
        rungemmF(p, 16, 32, 1);
    }
    k_bias<<<BB * HH * NN / 8, 256>>>(qkb, phi, bias);
    k_flash<<<dim3(1, 16, BB * HH), 256>>>(qkb, vb, bias, attnb);
    {   // x_mid = x + (attn @ Wo) * a_gate * gamma1
        GemmF p = {};
        p.A = attnb; p.sA = DD; p.B = wo; p.sB = DD; p.K = DD;
        p.C = xmid; p.sC = DD;
        p.epi = 3; p.e0 = av + 2048; p.e1 = gamma1; p.e2 = x;
        rungemmF(p, 8, 32, 1);
    }

    // ---- channel attention ----
    k_ln_mod<<<BN, 256>>>(xmid, x2, n2s, n2b, cv, nullptr, nullptr, nullptr);
    {   // fused: qkc | vc
        GemmF p = {};
        p.A = x2; p.sA = DD; p.B = wcqv; p.sB = DD; p.K = DD;
        p.C = qkcb; p.C2 = vcb; p.sC = DD;
        p.epi = 5; p.e0 = cv + 3072;
        rungemmF(p, 16, 32, 1);
    }
    k_chS<<<BB * HCC, 256, CHS_SMEM>>>(qkcb, tau, Pcp);
    {   // ch[n][c] = sum_d Vc[n][d] * P[c][d]   (batched z = b*8+hc)
        GemmF p = {};
        p.A = vcb; p.sA = DD; p.B = Pcp; p.sB = 128; p.bBz = 128 * 128; p.K = 128;
        p.C = chb; p.sC = DD;
        p.epi = 1; p.zmode = 1;
        rungemmF(p, 1, 16, BB * HCC);
    }
    {   // out = x_mid + (ch @ Wco) * c_gate * gamma2
        GemmF p = {};
        p.A = chb; p.sA = DD; p.B = wco; p.sB = DD; p.K = DD;
        p.C = d_out; p.sC = DD;
        p.epi = 3; p.e0 = cv + 2048; p.e1 = gamma2; p.e2 = xmid;
        rungemmF(p, 8, 32, 1);
    }
}